// round 12
// baseline (speedup 1.0000x reference)
#include <cuda_runtime.h>
#include <cuda_bf16.h>
#include <cstdint>
#include <cstddef>

// ---------------------------------------------------------------------------
// Combined-graph layout: lig nodes [0, NL), pad [NL, NPL), rec [NPL, NPL+NR),
// tail pad to NT_pad (mult of 128). Fixed 64-slot edge buckets per node.
// Softmax is precomputed: alpha records [n][slot] = {alpha[10], src, pad}.
// ---------------------------------------------------------------------------
#define MAXNP 40192
#define MAXDEG 64

__device__ __align__(256) __nv_bfloat16 g_agg_hi[MAXNP * 640];
__device__ __align__(256) __nv_bfloat16 g_agg_lo[MAXNP * 640];
__device__ float g_hsum[MAXNP * 64];
__device__ float g_agg2[MAXNP * 64];
__device__ float g_el[MAXNP * 10];
__device__ float g_er[MAXNP * 10];
__device__ float g_el2[MAXNP];
__device__ float g_er2[MAXNP];
__device__ int   g_cnt[MAXNP];
__device__ int   g_csrsrc[MAXNP * MAXDEG];
__device__ __align__(256) float g_alpha[MAXNP * MAXDEG * 12];  // 12 floats/record
__device__ float g_wl1[2 * 640];
__device__ float g_wr1[2 * 640];
__device__ float g_wl2[2 * 64];
__device__ float g_wr2[2 * 64];
__device__ __align__(256) __nv_bfloat16 g_w1t_hi[2 * 40960];  // [br][h][c][k]
__device__ __align__(256) __nv_bfloat16 g_w1t_lo[2 * 40960];
__device__ float g_read[32 * 256];

__device__ __forceinline__ float lrelu02(float e) { return fmaxf(e, 0.2f * e); }

__device__ __forceinline__ uint32_t smem_to_u32(const void* p) {
    uint32_t a;
    asm("{ .reg .u64 t; cvta.to.shared.u64 t, %1; cvt.u32.u64 %0, t; }" : "=r"(a) : "l"(p));
    return a;
}
__device__ __forceinline__ void cp_async16(void* smem_ptr, const void* gptr) {
    unsigned sa = (unsigned)__cvta_generic_to_shared(smem_ptr);
    asm volatile("cp.async.cg.shared.global [%0], [%1], 16;\n" :: "r"(sa), "l"(gptr));
}
#define CP_COMMIT() asm volatile("cp.async.commit_group;\n" ::: "memory")
#define CP_WAIT1()  asm volatile("cp.async.wait_group 1;\n" ::: "memory")
#define CP_WAIT0()  asm volatile("cp.async.wait_group 0;\n" ::: "memory")

#define SW128(o) ((o) ^ (((o) >> 3) & 0x70))

#define LDSM_X4(r0, r1, r2, r3, a) \
    asm volatile("ldmatrix.sync.aligned.m8n8.x4.shared.b16 {%0,%1,%2,%3}, [%4];" \
                 : "=r"(r0), "=r"(r1), "=r"(r2), "=r"(r3) : "r"(a))
#define LDSM_X2(r0, r1, a) \
    asm volatile("ldmatrix.sync.aligned.m8n8.x2.shared.b16 {%0,%1}, [%2];" \
                 : "=r"(r0), "=r"(r1) : "r"(a))
#define MMA_BF16(d, a0, a1, a2, a3, b0, b1) \
    asm volatile("mma.sync.aligned.m16n8k16.row.col.f32.bf16.bf16.f32 " \
                 "{%0,%1,%2,%3}, {%4,%5,%6,%7}, {%8,%9}, {%0,%1,%2,%3};" \
                 : "+f"((d)[0]), "+f"((d)[1]), "+f"((d)[2]), "+f"((d)[3]) \
                 : "r"(a0), "r"(a1), "r"(a2), "r"(a3), "r"(b0), "r"(b1))

// ---------------------------------------------------------------------------
// One-pass bucket scatter. cnt starts zero (zero-init + reset by gather2).
// ---------------------------------------------------------------------------
__global__ void scatter_kernel(const int* __restrict__ src_l, const int* __restrict__ dst_l,
                               const int* __restrict__ src_r, const int* __restrict__ dst_r,
                               int* __restrict__ cnt, int* __restrict__ csrsrc,
                               int EL, int ET, int NPL) {
    int i = blockIdx.x * blockDim.x + threadIdx.x;
    if (i >= ET) return;
    int s, d;
    if (i < EL) { s = src_l[i];            d = dst_l[i]; }
    else        { s = NPL + src_r[i - EL]; d = NPL + dst_r[i - EL]; }
    int p = atomicAdd(&cnt[d], 1);
    if (p < MAXDEG) csrsrc[d * MAXDEG + p] = s;
}

// ---------------------------------------------------------------------------
// Merged weight precompute + read-buffer zeroing.
// Blocks [0,88): al/ar projections. [88,408): W1^T split-bf16. [408,440): read=0.
// ---------------------------------------------------------------------------
__global__ void prep_all(const float* __restrict__ W1l, const float* __restrict__ al1l,
                         const float* __restrict__ ar1l, const float* __restrict__ W2l,
                         const float* __restrict__ al2l, const float* __restrict__ ar2l,
                         const float* __restrict__ W1r, const float* __restrict__ al1r,
                         const float* __restrict__ ar1r, const float* __restrict__ W2r,
                         const float* __restrict__ al2r, const float* __restrict__ ar2r,
                         float* __restrict__ wl1, float* __restrict__ wr1,
                         float* __restrict__ wl2, float* __restrict__ wr2,
                         __nv_bfloat16* __restrict__ hi, __nv_bfloat16* __restrict__ lo,
                         float* __restrict__ read) {
    if (blockIdx.x < 88) {
        int w    = (blockIdx.x * blockDim.x + threadIdx.x) >> 5;
        int lane = threadIdx.x & 31;
        if (w >= 2816) return;
        int combo = w / 704;
        int r     = w - combo * 704;
        int br = combo >> 1, side = combo & 1;
        const float* W1 = br ? W1r : W1l;
        const float* W2 = br ? W2r : W2l;
        const float* a1 = br ? (side ? ar1r : al1r) : (side ? ar1l : al1l);
        const float* a2 = br ? (side ? ar2r : al2r) : (side ? ar2l : al2l);
        float s;
        if (r < 640) {
            int h = r >> 6, k = r & 63;
            s = W1[(size_t)k * 640 + h * 64 + lane]      * a1[h * 64 + lane]
              + W1[(size_t)k * 640 + h * 64 + lane + 32] * a1[h * 64 + lane + 32];
        } else {
            int k = r - 640;
            s = 0.f;
#pragma unroll
            for (int j = 0; j < 4; j++)
                s += W2[(size_t)k * 128 + lane + 32 * j] * a2[lane + 32 * j];
        }
#pragma unroll
        for (int o = 16; o; o >>= 1) s += __shfl_xor_sync(0xffffffffu, s, o);
        if (lane == 0) {
            if (r < 640) (side ? wr1 : wl1)[br * 640 + r]        = s;
            else         (side ? wr2 : wl2)[br * 64 + (r - 640)] = s;
        }
    } else if (blockIdx.x < 408) {
        int idx = (blockIdx.x - 88) * 256 + threadIdx.x;
        if (idx >= 81920) return;
        int br  = idx / 40960;
        int rem = idx - br * 40960;
        int h = rem >> 12;
        int c = (rem >> 6) & 63;
        int k = rem & 63;
        const float* W1 = br ? W1r : W1l;
        float v = W1[(size_t)k * 640 + h * 64 + c];
        __nv_bfloat16 hb = __float2bfloat16(v);
        hi[idx] = hb;
        lo[idx] = __float2bfloat16(v - __bfloat162float(hb));
    } else {
        int idx = (blockIdx.x - 408) * 256 + threadIdx.x;
        if (idx < 8192) read[idx] = 0.f;
    }
}

// ---------------------------------------------------------------------------
// Layer-1 logits over combined nodes. Warp per node.
// ---------------------------------------------------------------------------
__global__ void elr1_kernel(const float* __restrict__ xl, const float* __restrict__ xr,
                            const float* __restrict__ wl1, const float* __restrict__ wr1,
                            float* __restrict__ el, float* __restrict__ er,
                            int NL, int NPL, int NT) {
    int n    = (blockIdx.x * blockDim.x + threadIdx.x) >> 5;
    int lane = threadIdx.x & 31;
    if (n >= NT) return;
    if (n >= NL && n < NPL) return;
    int br = (n >= NPL);
    const float4* xv = reinterpret_cast<const float4*>(
        br ? xr + (size_t)(n - NPL) * 64 : xl + (size_t)n * 64);
    bool isl = lane < 10;
    bool isr = lane >= 16 && lane < 26;
    if (!(isl || isr)) return;
    int h = isl ? lane : lane - 16;
    const float4* wv = reinterpret_cast<const float4*>(
        (isl ? wl1 : wr1) + br * 640 + h * 64);
    float s = 0.f;
#pragma unroll
    for (int q = 0; q < 16; q++) {
        float4 a = xv[q];
        float4 b = wv[q];
        s += a.x * b.x + a.y * b.y + a.z * b.z + a.w * b.w;
    }
    if (isl) el[(size_t)n * 10 + h] = s;
    else     er[(size_t)n * 10 + h] = s;
}

// ---------------------------------------------------------------------------
// alpha_kernel: warp per node, lane = edge slot (2 passes over 64 slots).
// Computes NORMALIZED softmax weights for all 10 heads with full-lane MUFU
// and writes records alpha[n][slot] = {a0..a9, src_bits, pad} (12 floats).
// ---------------------------------------------------------------------------
__global__ void alpha_kernel(const int* __restrict__ cnt, const int* __restrict__ csrsrc,
                             const float* __restrict__ el, const float* __restrict__ er,
                             float* __restrict__ alpha, int NT) {
    int n    = (blockIdx.x * blockDim.x + threadIdx.x) >> 5;
    int lane = threadIdx.x & 31;
    if (n >= NT) return;
    int deg = min(cnt[n], MAXDEG);
    if (deg == 0) return;

    float ern[10];
#pragma unroll
    for (int q = 0; q < 5; q++) {
        float2 t = *reinterpret_cast<const float2*>(er + (size_t)n * 10 + q * 2);
        ern[q * 2] = t.x; ern[q * 2 + 1] = t.y;
    }
    const bool vA = lane < deg, vB = lane + 32 < deg;
    const int sA = vA ? csrsrc[n * MAXDEG + lane] : 0;
    const int sB = vB ? csrsrc[n * MAXDEG + lane + 32] : 0;

    float wA[10], wB[10];
#pragma unroll
    for (int q = 0; q < 5; q++) {
        float2 a = *reinterpret_cast<const float2*>(el + (size_t)sA * 10 + q * 2);
        float2 b = *reinterpret_cast<const float2*>(el + (size_t)sB * 10 + q * 2);
        wA[q * 2]     = vA ? __expf(fminf(lrelu02(a.x + ern[q * 2]),     60.f)) : 0.f;
        wA[q * 2 + 1] = vA ? __expf(fminf(lrelu02(a.y + ern[q * 2 + 1]), 60.f)) : 0.f;
        wB[q * 2]     = vB ? __expf(fminf(lrelu02(b.x + ern[q * 2]),     60.f)) : 0.f;
        wB[q * 2 + 1] = vB ? __expf(fminf(lrelu02(b.y + ern[q * 2 + 1]), 60.f)) : 0.f;
    }
#pragma unroll
    for (int h = 0; h < 10; h++) {
        float d = wA[h] + wB[h];
#pragma unroll
        for (int o = 16; o; o >>= 1) d += __shfl_xor_sync(0xffffffffu, d, o);
        float inv = 1.f / d;
        wA[h] *= inv; wB[h] *= inv;
    }
    if (vA) {
        float* rec = alpha + ((size_t)n * MAXDEG + lane) * 12;
        *reinterpret_cast<float4*>(rec)     = make_float4(wA[0], wA[1], wA[2], wA[3]);
        *reinterpret_cast<float4*>(rec + 4) = make_float4(wA[4], wA[5], wA[6], wA[7]);
        *reinterpret_cast<float4*>(rec + 8) = make_float4(wA[8], wA[9], __int_as_float(sA), 0.f);
    }
    if (vB) {
        float* rec = alpha + ((size_t)n * MAXDEG + lane + 32) * 12;
        *reinterpret_cast<float4*>(rec)     = make_float4(wB[0], wB[1], wB[2], wB[3]);
        *reinterpret_cast<float4*>(rec + 4) = make_float4(wB[4], wB[5], wB[6], wB[7]);
        *reinterpret_cast<float4*>(rec + 8) = make_float4(wB[8], wB[9], __int_as_float(sB), 0.f);
    }
}

// ---------------------------------------------------------------------------
// Layer-1 gather: 2 warps per node (5 heads each); per edge only ONE record
// LDG (alpha + src share a record), 6 shfl, 1 x LDG.128, 20 FMA. No exp/div.
// ---------------------------------------------------------------------------
__global__ void gather1_kernel(const float* __restrict__ xl, const float* __restrict__ xr,
                               const int* __restrict__ cnt, const float* __restrict__ alpha,
                               __nv_bfloat16* __restrict__ agg_hi,
                               __nv_bfloat16* __restrict__ agg_lo,
                               int NPL, int NW) {
    const int gw   = (blockIdx.x * blockDim.x + threadIdx.x) >> 5;
    const int lane = threadIdx.x & 31;
    if (gw >= NW) return;
    const int n    = gw >> 1;
    const int hg   = (gw & 1) * 5;         // head-group base (0 or 5)
    const int half = lane & 16;
    const int hb   = half >> 4;
    const int hl   = lane & 15;
    const int db   = hl * 4;
    const int deg = min(cnt[n], MAXDEG);
    const float* xb = (n < NPL) ? xl : (xr - (ptrdiff_t)NPL * 64);
    const int off = (hl < 5) ? (hg + hl) : 10;   // alpha slot / src slot

    float4 acc[5];
#pragma unroll
    for (int h = 0; h < 5; h++) acc[h] = make_float4(0.f, 0.f, 0.f, 0.f);

    if (deg > 0) {
        const float* base = alpha + (size_t)n * (MAXDEG * 12);
        int slot = hb;
        float nval = 0.f;
        if (hl <= 5 && slot < deg) nval = base[slot * 12 + off];

        for (int i = 0; i < deg; i += 2) {
            float val = nval;
            int j = i + 2 + hb;
            nval = 0.f;
            if (i + 2 < deg) {
                if (hl <= 5 && j < deg) nval = base[j * 12 + off];
            }
            int src = __float_as_int(__shfl_sync(0xffffffffu, val, 5 + half));
            float4 v = *reinterpret_cast<const float4*>(xb + (size_t)src * 64 + db);
#pragma unroll
            for (int h = 0; h < 5; h++) {
                float wh = __shfl_sync(0xffffffffu, val, h + half);
                acc[h].x += wh * v.x;
                acc[h].y += wh * v.y;
                acc[h].z += wh * v.z;
                acc[h].w += wh * v.w;
            }
        }
    }

#pragma unroll
    for (int h = 0; h < 5; h++) {
        acc[h].x += __shfl_xor_sync(0xffffffffu, acc[h].x, 16);
        acc[h].y += __shfl_xor_sync(0xffffffffu, acc[h].y, 16);
        acc[h].z += __shfl_xor_sync(0xffffffffu, acc[h].z, 16);
        acc[h].w += __shfl_xor_sync(0xffffffffu, acc[h].w, 16);
    }

    if (lane < 16) {
        size_t base = (size_t)n * 640 + (size_t)hg * 64 + db;
#pragma unroll
        for (int h = 0; h < 5; h++) {
            float ax = acc[h].x, ay = acc[h].y, az = acc[h].z, aw = acc[h].w;
            __nv_bfloat162 h0 = __floats2bfloat162_rn(ax, ay);
            __nv_bfloat162 h1 = __floats2bfloat162_rn(az, aw);
            float2 f0 = __bfloat1622float2(h0);
            float2 f1 = __bfloat1622float2(h1);
            __nv_bfloat162 l0 = __floats2bfloat162_rn(ax - f0.x, ay - f0.y);
            __nv_bfloat162 l1 = __floats2bfloat162_rn(az - f1.x, aw - f1.y);
            uint2 uh, ul;
            uh.x = *reinterpret_cast<unsigned*>(&h0);
            uh.y = *reinterpret_cast<unsigned*>(&h1);
            ul.x = *reinterpret_cast<unsigned*>(&l0);
            ul.y = *reinterpret_cast<unsigned*>(&l1);
            *reinterpret_cast<uint2*>(agg_hi + base + h * 64) = uh;
            *reinterpret_cast<uint2*>(agg_lo + base + h * 64) = ul;
        }
    }
}

// ---------------------------------------------------------------------------
// headgemm via mma.sync (HMMA): 64-row tile, 256 threads (4 M x 2 N warps),
// split-bf16 (hi*hi + hi*lo + lo*hi), fp32 register accum, cp.async double
// buffering, per-head bias+relu+head-sum, fused elr2 epilogue.
// ---------------------------------------------------------------------------
__global__ void __launch_bounds__(256) headgemm_mma(
    const __nv_bfloat16* __restrict__ agg_hi, const __nv_bfloat16* __restrict__ agg_lo,
    const __nv_bfloat16* __restrict__ w1t_hi, const __nv_bfloat16* __restrict__ w1t_lo,
    const float* __restrict__ b1l, const float* __restrict__ b1r,
    const float* __restrict__ wl2, const float* __restrict__ wr2,
    float* __restrict__ hsum, float* __restrict__ el2, float* __restrict__ er2,
    int NPL) {
    extern __shared__ char sm[];
    const int tid  = threadIdx.x;          // 256 threads, 8 warps
    const int w    = tid >> 5;
    const int lane = tid & 31;
    const int wm   = w & 3;                // M group (16 rows)
    const int wn   = w >> 2;               // N group (32 cols)
    const int gid  = lane >> 2, tid4 = lane & 3;
    const int bm = blockIdx.x * 64;
    const int br = (bm >= NPL);
    const float* b1 = br ? b1r : b1l;
    const uint32_t smb = smem_to_u32(sm);
    float* b1s  = reinterpret_cast<float*>(sm + 65536);
    float* wl2s = reinterpret_cast<float*>(sm + 68096);
    float* wr2s = reinterpret_cast<float*>(sm + 68352);
    float* hs   = reinterpret_cast<float*>(sm);   // epilogue reuse, stride 66

    for (int i = tid; i < 640; i += 256) b1s[i] = b1[i];
    if (tid < 64) { wl2s[tid] = wl2[br * 64 + tid]; wr2s[tid] = wr2[br * 64 + tid]; }

    auto loads = [&](int h) {
        int st = h & 1;
        const char* Ah = (const char*)agg_hi + ((size_t)bm * 640 + h * 64) * 2;
        const char* Al = (const char*)agg_lo + ((size_t)bm * 640 + h * 64) * 2;
        char* Ahd = sm + st * 16384;
        char* Ald = Ahd + 8192;
#pragma unroll
        for (int i = 0; i < 2; i++) {
            int f = tid + i * 256;
            int row = f >> 3, c = f & 7;
            int so = SW128(row * 128 + c * 16);
            size_t go = (size_t)row * 1280 + c * 16;
            cp_async16(Ahd + so, Ah + go);
            cp_async16(Ald + so, Al + go);
        }
        const char* Wh = (const char*)w1t_hi + ((size_t)br * 40960 + h * 4096) * 2;
        const char* Wl = (const char*)w1t_lo + ((size_t)br * 40960 + h * 4096) * 2;
        char* Whd = sm + 32768 + st * 16384;
        char* Wld = Whd + 8192;
#pragma unroll
        for (int i = 0; i < 2; i++) {
            int f = tid + i * 256;
            int row = f >> 3, c = f & 7;
            int so = SW128(row * 128 + c * 16);
            size_t go = (size_t)row * 128 + c * 16;
            cp_async16(Whd + so, Wh + go);
            cp_async16(Wld + so, Wl + go);
        }
        CP_COMMIT();
    };

    loads(0);
    loads(1);

    float out[4][4];
#pragma unroll
    for (int nf = 0; nf < 4; nf++)
#pragma unroll
        for (int j = 0; j < 4; j++) out[nf][j] = 0.f;

    const int arow  = wm * 16 + (lane & 15);
    const int acolb = (lane >> 4) * 16;
    const int brow  = lane & 7;
    const int bcolb = ((lane >> 3) & 1) * 16;

    for (int h = 0; h < 10; h++) {
        if (h < 9) { CP_WAIT1(); } else { CP_WAIT0(); }
        __syncthreads();

        const int st = h & 1;
        const uint32_t Ah = smb + st * 16384;
        const uint32_t Al = Ah + 8192;
        const uint32_t Wh = smb + 32768 + st * 16384;
        const uint32_t Wl = Wh + 8192;

        float d[4][4];
#pragma unroll
        for (int nf = 0; nf < 4; nf++)
#pragma unroll
            for (int j = 0; j < 4; j++) d[nf][j] = 0.f;

#pragma unroll
        for (int kc = 0; kc < 4; kc++) {
            uint32_t aoff = SW128(arow * 128 + kc * 32 + acolb);
            uint32_t ah0, ah1, ah2, ah3, al0, al1, al2, al3;
            LDSM_X4(ah0, ah1, ah2, ah3, Ah + aoff);
            LDSM_X4(al0, al1, al2, al3, Al + aoff);
#pragma unroll
            for (int nf = 0; nf < 4; nf++) {
                uint32_t boff = SW128((wn * 32 + nf * 8 + brow) * 128 + kc * 32 + bcolb);
                uint32_t bh0, bh1, bl0, bl1;
                LDSM_X2(bh0, bh1, Wh + boff);
                LDSM_X2(bl0, bl1, Wl + boff);
                MMA_BF16(d[nf], ah0, ah1, ah2, ah3, bh0, bh1);
                MMA_BF16(d[nf], ah0, ah1, ah2, ah3, bl0, bl1);
                MMA_BF16(d[nf], al0, al1, al2, al3, bh0, bh1);
            }
        }
        __syncthreads();
        if (h + 2 < 10) loads(h + 2);

#pragma unroll
        for (int nf = 0; nf < 4; nf++) {
            int col = wn * 32 + nf * 8 + tid4 * 2;
            float2 bb = *reinterpret_cast<const float2*>(&b1s[h * 64 + col]);
            out[nf][0] += fmaxf(d[nf][0] + bb.x, 0.f);
            out[nf][1] += fmaxf(d[nf][1] + bb.y, 0.f);
            out[nf][2] += fmaxf(d[nf][2] + bb.x, 0.f);
            out[nf][3] += fmaxf(d[nf][3] + bb.y, 0.f);
        }
    }

    __syncthreads();
    const int row0 = wm * 16 + gid;
#pragma unroll
    for (int nf = 0; nf < 4; nf++) {
        int colb = wn * 32 + nf * 8 + tid4 * 2;
        *reinterpret_cast<float2*>(&hs[row0 * 66 + colb])       = make_float2(out[nf][0], out[nf][1]);
        *reinterpret_cast<float2*>(&hs[(row0 + 8) * 66 + colb]) = make_float2(out[nf][2], out[nf][3]);
    }
    __syncthreads();
    if (tid < 64) {
        int row = tid;
        float pl = 0.f, pr = 0.f;
        float4* hp = reinterpret_cast<float4*>(hsum + (size_t)(bm + row) * 64);
#pragma unroll
        for (int c4 = 0; c4 < 16; c4++) {
            float v0 = hs[row * 66 + c4 * 4 + 0];
            float v1 = hs[row * 66 + c4 * 4 + 1];
            float v2 = hs[row * 66 + c4 * 4 + 2];
            float v3 = hs[row * 66 + c4 * 4 + 3];
            pl += v0 * wl2s[c4 * 4] + v1 * wl2s[c4 * 4 + 1] + v2 * wl2s[c4 * 4 + 2] + v3 * wl2s[c4 * 4 + 3];
            pr += v0 * wr2s[c4 * 4] + v1 * wr2s[c4 * 4 + 1] + v2 * wr2s[c4 * 4 + 2] + v3 * wr2s[c4 * 4 + 3];
            hp[c4] = make_float4(v0, v1, v2, v3);
        }
        el2[bm + row] = pl;
        er2[bm + row] = pr;
    }
}

// ---------------------------------------------------------------------------
// Layer-2 gather on hsum: warp per dst node, float2 per lane, distance-1
// prefetch. Also RESETS cnt[n]=0 (last reader) so the graph is replayable
// without a separate memset launch.
// ---------------------------------------------------------------------------
__global__ void gather2_kernel(const float* __restrict__ hsum, int* __restrict__ cnt,
                               const int* __restrict__ csrsrc, const float* __restrict__ el,
                               const float* __restrict__ er, float* __restrict__ agg2, int NT) {
    int n    = (blockIdx.x * blockDim.x + threadIdx.x) >> 5;
    int lane = threadIdx.x & 31;
    if (n >= NT) return;
    int beg = n * MAXDEG;
    int deg = min(cnt[n], MAXDEG);
    if (lane == 0) cnt[n] = 0;
    int end = beg + deg;
    float2 acc = make_float2(0.f, 0.f);
    float den = 1.f;
    if (deg > 0) {
        den = 0.f;
        const float ern = er[n];
        int s0 = csrsrc[beg];
        bool has1 = beg + 1 < end;
        int s1 = has1 ? csrsrc[beg + 1] : s0;
        float e0 = el[s0], e1 = el[s1];
        float2 v0 = *reinterpret_cast<const float2*>(hsum + (size_t)s0 * 64 + lane * 2);
        float2 v1 = *reinterpret_cast<const float2*>(hsum + (size_t)s1 * 64 + lane * 2);
        for (int i = beg; i < end; i += 2) {
            float ce0 = e0, ce1 = e1;
            float2 cv0 = v0, cv1 = v1;
            bool chas1 = has1;
            int j = i + 2;
            if (j < end) {
                s0 = csrsrc[j];
                has1 = j + 1 < end;
                s1 = has1 ? csrsrc[j + 1] : s0;
                e0 = el[s0]; e1 = el[s1];
                v0 = *reinterpret_cast<const float2*>(hsum + (size_t)s0 * 64 + lane * 2);
                v1 = *reinterpret_cast<const float2*>(hsum + (size_t)s1 * 64 + lane * 2);
            }
            float w0 = __expf(fminf(lrelu02(ce0 + ern), 60.f));
            float w1 = chas1 ? __expf(fminf(lrelu02(ce1 + ern), 60.f)) : 0.f;
            den += w0 + w1;
            acc.x += w0 * cv0.x + w1 * cv1.x;
            acc.y += w0 * cv0.y + w1 * cv1.y;
        }
    }
    const float inv = 1.f / den;
    *reinterpret_cast<float2*>(agg2 + (size_t)n * 64 + lane * 2) =
        make_float2(acc.x * inv, acc.y * inv);
}

// ---------------------------------------------------------------------------
// Fused layer-2 GEMM + bias + relu + graph-max readout (combined rows).
// ---------------------------------------------------------------------------
__global__ void gemm2ro_kernel(const float* __restrict__ X,
                               const float* __restrict__ W2l, const float* __restrict__ b2l,
                               const float* __restrict__ W2r, const float* __restrict__ b2r,
                               const int* __restrict__ gid_l, const int* __restrict__ gid_r,
                               float* __restrict__ read, int NL, int NPL, int NR) {
    __shared__ float XsT[64][68];
    __shared__ float Ws[64][64];
    const int bm  = blockIdx.y * 64;
    const int bn  = blockIdx.x * 64;
    const int br  = (bm >= NPL);
    const float* W  = br ? W2r : W2l;
    const float* b2 = br ? b2r : b2l;
    const int tid = threadIdx.x;

#pragma unroll
    for (int i = 0; i < 16; i++) {
        int e = tid + i * 256;
        int r = e >> 6, k = e & 63;
        XsT[k][r] = X[(size_t)(bm + r) * 64 + k];
    }
#pragma unroll
    for (int i = 0; i < 16; i++) {
        int e = tid + i * 256;
        int k = e >> 6, c = e & 63;
        Ws[k][c] = W[(size_t)k * 128 + bn + c];
    }
    __syncthreads();

    const int tx = tid & 15, ty = tid >> 4;
    const int r0 = ty * 4, c0 = tx * 4;
    float acc[4][4] = {};
#pragma unroll
    for (int k = 0; k < 64; k++) {
        float4 a = *reinterpret_cast<const float4*>(&XsT[k][r0]);
        float4 b = *reinterpret_cast<const float4*>(&Ws[k][c0]);
        acc[0][0] += a.x * b.x; acc[0][1] += a.x * b.y; acc[0][2] += a.x * b.z; acc[0][3] += a.x * b.w;
        acc[1][0] += a.y * b.x; acc[1][1] += a.y * b.y; acc[1][2] += a.y * b.z; acc[1][3] += a.y * b.w;
        acc[2][0] += a.z * b.x; acc[2][1] += a.z * b.y; acc[2][2] += a.z * b.z; acc[2][3] += a.z * b.w;
        acc[3][0] += a.w * b.x; acc[3][1] += a.w * b.y; acc[3][2] += a.w * b.z; acc[3][3] += a.w * b.w;
    }

    float4 bb = *reinterpret_cast<const float4*>(&b2[bn + c0]);
#pragma unroll
    for (int i = 0; i < 4; i++) {
        int r = bm + r0 + i;
        bool vlig = (r < NL);
        bool vrec = (r >= NPL) && (r < NPL + NR);
        if (vlig || vrec) {
            int g   = vlig ? gid_l[r] : gid_r[r - NPL];
            int off = vlig ? 0 : 128;
            int* rp = reinterpret_cast<int*>(read) + (size_t)g * 256 + off + bn + c0;
            atomicMax(rp + 0, __float_as_int(fmaxf(acc[i][0] + bb.x, 0.f)));
            atomicMax(rp + 1, __float_as_int(fmaxf(acc[i][1] + bb.y, 0.f)));
            atomicMax(rp + 2, __float_as_int(fmaxf(acc[i][2] + bb.z, 0.f)));
            atomicMax(rp + 3, __float_as_int(fmaxf(acc[i][3] + bb.w, 0.f)));
        }
    }
}

// ---------------------------------------------------------------------------
// Final MLP head: [32,256] -> relu(@W1+b1) -> relu(@W2+b2) -> [32]
// ---------------------------------------------------------------------------
__global__ void mlp_kernel(const float* __restrict__ read, const float* __restrict__ W1,
                           const float* __restrict__ bb1, const float* __restrict__ W2,
                           const float* __restrict__ bb2, float* __restrict__ out) {
    __shared__ float sin[256];
    __shared__ float red[128];
    int t = threadIdx.x;
    for (int b = 0; b < 32; b++) {
        sin[t]       = read[b * 256 + t];
        sin[t + 128] = read[b * 256 + 128 + t];
        __syncthreads();
        float acc = bb1[t];
#pragma unroll 4
        for (int k = 0; k < 256; k++) acc += sin[k] * W1[(size_t)k * 128 + t];
        acc = fmaxf(acc, 0.f);
        red[t] = acc * W2[t];
        __syncthreads();
        for (int o = 64; o; o >>= 1) {
            if (t < o) red[t] += red[t + o];
            __syncthreads();
        }
        if (t == 0) out[b] = fmaxf(red[0] + bb2[0], 0.f);
        __syncthreads();
    }
}

// ---------------------------------------------------------------------------
// Host-side orchestration
// ---------------------------------------------------------------------------
static inline int div_up(int a, int b) { return (a + b - 1) / b; }

extern "C" void kernel_launch(void* const* d_in, const int* in_sizes, int n_in,
                              void* d_out, int out_size) {
    (void)n_in; (void)out_size;
    const float* x_lig   = (const float*)d_in[0];
    const int*   src_lig = (const int*)  d_in[1];
    const int*   dst_lig = (const int*)  d_in[2];
    const int*   gid_lig = (const int*)  d_in[3];
    const float* x_rec   = (const float*)d_in[4];
    const int*   src_rec = (const int*)  d_in[5];
    const int*   dst_rec = (const int*)  d_in[6];
    const int*   gid_rec = (const int*)  d_in[7];
    const float* W1l  = (const float*)d_in[8];
    const float* al1l = (const float*)d_in[9];
    const float* ar1l = (const float*)d_in[10];
    const float* b1l  = (const float*)d_in[11];
    const float* W2l  = (const float*)d_in[12];
    const float* al2l = (const float*)d_in[13];
    const float* ar2l = (const float*)d_in[14];
    const float* b2l  = (const float*)d_in[15];
    const float* W1r  = (const float*)d_in[16];
    const float* al1r = (const float*)d_in[17];
    const float* ar1r = (const float*)d_in[18];
    const float* b1r  = (const float*)d_in[19];
    const float* W2r  = (const float*)d_in[20];
    const float* al2r = (const float*)d_in[21];
    const float* ar2r = (const float*)d_in[22];
    const float* b2r  = (const float*)d_in[23];
    const float* W_lin1 = (const float*)d_in[24];
    const float* b_lin1 = (const float*)d_in[25];
    const float* W_lin2 = (const float*)d_in[26];
    const float* b_lin2 = (const float*)d_in[27];

    const int NL = in_sizes[0] / 64;
    const int EL = in_sizes[1];
    const int NR = in_sizes[4] / 64;
    const int ER = in_sizes[5];
    const int NPL    = (NL + 127) & ~127;       // rec offset, 128-aligned
    const int NT     = NPL + NR;
    const int NT_pad = (NT + 127) & ~127;
    const int ET     = EL + ER;

    __nv_bfloat16 *agg_hi, *agg_lo, *w1t_hi, *w1t_lo;
    float *hsum, *agg2, *el, *er, *el2, *er2, *read, *alpha;
    float *wl1, *wr1, *wl2, *wr2;
    int *cnt, *csrsrc;
    cudaGetSymbolAddress((void**)&agg_hi, g_agg_hi);
    cudaGetSymbolAddress((void**)&agg_lo, g_agg_lo);
    cudaGetSymbolAddress((void**)&w1t_hi, g_w1t_hi);
    cudaGetSymbolAddress((void**)&w1t_lo, g_w1t_lo);
    cudaGetSymbolAddress((void**)&hsum,   g_hsum);
    cudaGetSymbolAddress((void**)&agg2,   g_agg2);
    cudaGetSymbolAddress((void**)&el,     g_el);
    cudaGetSymbolAddress((void**)&er,     g_er);
    cudaGetSymbolAddress((void**)&el2,    g_el2);
    cudaGetSymbolAddress((void**)&er2,    g_er2);
    cudaGetSymbolAddress((void**)&cnt,    g_cnt);
    cudaGetSymbolAddress((void**)&csrsrc, g_csrsrc);
    cudaGetSymbolAddress((void**)&alpha,  g_alpha);
    cudaGetSymbolAddress((void**)&wl1,    g_wl1);
    cudaGetSymbolAddress((void**)&wr1,    g_wr1);
    cudaGetSymbolAddress((void**)&wl2,    g_wl2);
    cudaGetSymbolAddress((void**)&wr2,    g_wr2);
    cudaGetSymbolAddress((void**)&read,   g_read);

    cudaFuncSetAttribute(headgemm_mma,
                         cudaFuncAttributeMaxDynamicSharedMemorySize, 68608);

    // ---- one-pass bucket CSR (cnt is zero from init / gather2's reset) ----
    scatter_kernel<<<div_up(ET, 256), 256>>>(src_lig, dst_lig, src_rec, dst_rec,
                                             cnt, csrsrc, EL, ET, NPL);

    // ---- weights precompute + layer-1 logits + softmax precompute ----
    prep_all<<<440, 256>>>(W1l, al1l, ar1l, W2l, al2l, ar2l,
                           W1r, al1r, ar1r, W2r, al2r, ar2r,
                           wl1, wr1, wl2, wr2, w1t_hi, w1t_lo, read);
    elr1_kernel<<<div_up(NT * 32, 256), 256>>>(x_lig, x_rec, wl1, wr1, el, er, NL, NPL, NT);
    alpha_kernel<<<div_up(NT * 32, 256), 256>>>(cnt, csrsrc, el, er, alpha, NT);

    // ---- layer 1: record-based gather (bf16 split), HMMA GEMM ----
    gather1_kernel<<<div_up(NT_pad * 64, 256), 256>>>(x_lig, x_rec, cnt, alpha,
                                                      agg_hi, agg_lo, NPL, NT_pad * 2);
    headgemm_mma<<<NT_pad / 64, 256, 68608>>>(agg_hi, agg_lo, w1t_hi, w1t_lo,
                                              b1l, b1r, wl2, wr2,
                                              hsum, el2, er2, NPL);

    // ---- layer 2: prefetched gather (+cnt reset), fused GEMM + readout ----
    gather2_kernel<<<div_up(NT * 32, 256), 256>>>(hsum, cnt, csrsrc, el2, er2, agg2, NT);
    gemm2ro_kernel<<<dim3(2, NT_pad / 64), 256>>>(agg2, W2l, b2l, W2r, b2r,
                                                  gid_lig, gid_rec, read, NL, NPL, NR);

    mlp_kernel<<<1, 128>>>(read, W_lin1, b_lin1, W_lin2, b_lin2, (float*)d_out);
}

// round 13
// speedup vs baseline: 1.0872x; 1.0872x over previous
#include <cuda_runtime.h>
#include <cuda_bf16.h>
#include <cstdint>
#include <cstddef>

// ---------------------------------------------------------------------------
// Combined-graph layout: lig nodes [0, NL), pad [NL, NPL), rec [NPL, NPL+NR),
// tail pad to NT_pad (mult of 128). Fixed 64-slot edge buckets per node.
// ---------------------------------------------------------------------------
#define MAXNP 40192
#define MAXDEG 64

__device__ __align__(256) __nv_bfloat16 g_agg_hi[MAXNP * 640];
__device__ __align__(256) __nv_bfloat16 g_agg_lo[MAXNP * 640];
__device__ float g_hsum[MAXNP * 64];
__device__ float g_agg2[MAXNP * 64];
__device__ float g_el[MAXNP * 10];
__device__ float g_er[MAXNP * 10];
__device__ float g_el2[MAXNP];
__device__ float g_er2[MAXNP];
__device__ int   g_cnt[MAXNP];
__device__ int   g_csrsrc[MAXNP * MAXDEG];
__device__ float g_wl1[2 * 640];
__device__ float g_wr1[2 * 640];
__device__ float g_wl2[2 * 64];
__device__ float g_wr2[2 * 64];
__device__ __align__(256) __nv_bfloat16 g_w1t_hi[2 * 40960];  // [br][h][c][k]
__device__ __align__(256) __nv_bfloat16 g_w1t_lo[2 * 40960];
__device__ float g_read[32 * 256];

__device__ __forceinline__ float lrelu02(float e) { return fmaxf(e, 0.2f * e); }

__device__ __forceinline__ uint32_t smem_to_u32(const void* p) {
    uint32_t a;
    asm("{ .reg .u64 t; cvta.to.shared.u64 t, %1; cvt.u32.u64 %0, t; }" : "=r"(a) : "l"(p));
    return a;
}
__device__ __forceinline__ void cp_async16(void* smem_ptr, const void* gptr) {
    unsigned sa = (unsigned)__cvta_generic_to_shared(smem_ptr);
    asm volatile("cp.async.cg.shared.global [%0], [%1], 16;\n" :: "r"(sa), "l"(gptr));
}
#define CP_COMMIT() asm volatile("cp.async.commit_group;\n" ::: "memory")
#define CP_WAIT1()  asm volatile("cp.async.wait_group 1;\n" ::: "memory")
#define CP_WAIT0()  asm volatile("cp.async.wait_group 0;\n" ::: "memory")

#define SW128(o) ((o) ^ (((o) >> 3) & 0x70))

#define LDSM_X4(r0, r1, r2, r3, a) \
    asm volatile("ldmatrix.sync.aligned.m8n8.x4.shared.b16 {%0,%1,%2,%3}, [%4];" \
                 : "=r"(r0), "=r"(r1), "=r"(r2), "=r"(r3) : "r"(a))
#define LDSM_X2(r0, r1, a) \
    asm volatile("ldmatrix.sync.aligned.m8n8.x2.shared.b16 {%0,%1}, [%2];" \
                 : "=r"(r0), "=r"(r1) : "r"(a))
#define MMA_BF16(d, a0, a1, a2, a3, b0, b1) \
    asm volatile("mma.sync.aligned.m16n8k16.row.col.f32.bf16.bf16.f32 " \
                 "{%0,%1,%2,%3}, {%4,%5,%6,%7}, {%8,%9}, {%0,%1,%2,%3};" \
                 : "+f"((d)[0]), "+f"((d)[1]), "+f"((d)[2]), "+f"((d)[3]) \
                 : "r"(a0), "r"(a1), "r"(a2), "r"(a3), "r"(b0), "r"(b1))

// ---------------------------------------------------------------------------
// FRONT kernel: three independent tasks in one launch (block-range dispatch).
//   [0, SB)            : bucket scatter of combined edge list
//   [SB, SB+440)       : weight precompute (al/ar proj, W1^T split, read=0)
//   [SB+440, SB+440+EB): layer-1 logits el/er (warp per node)
// ---------------------------------------------------------------------------
__global__ void front_kernel(
    const int* __restrict__ src_l, const int* __restrict__ dst_l,
    const int* __restrict__ src_r, const int* __restrict__ dst_r,
    int* __restrict__ cnt, int* __restrict__ csrsrc,
    const float* __restrict__ W1l, const float* __restrict__ al1l,
    const float* __restrict__ ar1l, const float* __restrict__ W2l,
    const float* __restrict__ al2l, const float* __restrict__ ar2l,
    const float* __restrict__ W1r, const float* __restrict__ al1r,
    const float* __restrict__ ar1r, const float* __restrict__ W2r,
    const float* __restrict__ al2r, const float* __restrict__ ar2r,
    float* __restrict__ wl1, float* __restrict__ wr1,
    float* __restrict__ wl2, float* __restrict__ wr2,
    __nv_bfloat16* __restrict__ hi, __nv_bfloat16* __restrict__ lo,
    float* __restrict__ read,
    const float* __restrict__ xl, const float* __restrict__ xr,
    float* __restrict__ el, float* __restrict__ er,
    int EL, int ET, int NL, int NPL, int NT, int SB) {
    int b = blockIdx.x;
    if (b < SB) {
        // ---- scatter ----
        int i = b * 256 + threadIdx.x;
        if (i >= ET) return;
        int s, d;
        if (i < EL) { s = src_l[i];            d = dst_l[i]; }
        else        { s = NPL + src_r[i - EL]; d = NPL + dst_r[i - EL]; }
        int p = atomicAdd(&cnt[d], 1);
        if (p < MAXDEG) csrsrc[d * MAXDEG + p] = s;
        return;
    }
    b -= SB;
    if (b < 440) {
        if (b < 88) {
            int w    = (b * 256 + threadIdx.x) >> 5;
            int lane = threadIdx.x & 31;
            if (w >= 2816) return;
            int combo = w / 704;
            int r     = w - combo * 704;
            int br = combo >> 1, side = combo & 1;
            const float* W1 = br ? W1r : W1l;
            const float* W2 = br ? W2r : W2l;
            const float* a1 = br ? (side ? ar1r : al1r) : (side ? ar1l : al1l);
            const float* a2 = br ? (side ? ar2r : al2r) : (side ? ar2l : al2l);
            float s;
            if (r < 640) {
                int h = r >> 6, k = r & 63;
                s = W1[(size_t)k * 640 + h * 64 + lane]      * a1[h * 64 + lane]
                  + W1[(size_t)k * 640 + h * 64 + lane + 32] * a1[h * 64 + lane + 32];
            } else {
                int k = r - 640;
                s = 0.f;
#pragma unroll
                for (int j = 0; j < 4; j++)
                    s += W2[(size_t)k * 128 + lane + 32 * j] * a2[lane + 32 * j];
            }
#pragma unroll
            for (int o = 16; o; o >>= 1) s += __shfl_xor_sync(0xffffffffu, s, o);
            if (lane == 0) {
                if (r < 640) (side ? wr1 : wl1)[br * 640 + r]        = s;
                else         (side ? wr2 : wl2)[br * 64 + (r - 640)] = s;
            }
        } else if (b < 408) {
            int idx = (b - 88) * 256 + threadIdx.x;
            if (idx >= 81920) return;
            int br  = idx / 40960;
            int rem = idx - br * 40960;
            int h = rem >> 12;
            int c = (rem >> 6) & 63;
            int k = rem & 63;
            const float* W1 = br ? W1r : W1l;
            float v = W1[(size_t)k * 640 + h * 64 + c];
            __nv_bfloat16 hb = __float2bfloat16(v);
            hi[idx] = hb;
            lo[idx] = __float2bfloat16(v - __bfloat162float(hb));
        } else {
            int idx = (b - 408) * 256 + threadIdx.x;
            if (idx < 8192) read[idx] = 0.f;
        }
        return;
    }
    b -= 440;
    {
        // ---- elr1: warp per node ----
        int n    = (b * 256 + threadIdx.x) >> 5;
        int lane = threadIdx.x & 31;
        if (n >= NT) return;
        if (n >= NL && n < NPL) return;
        int br = (n >= NPL);
        const float4* xv = reinterpret_cast<const float4*>(
            br ? xr + (size_t)(n - NPL) * 64 : xl + (size_t)n * 64);
        bool isl = lane < 10;
        bool isr = lane >= 16 && lane < 26;
        if (!(isl || isr)) return;
        int h = isl ? lane : lane - 16;
        const float4* wv = reinterpret_cast<const float4*>(
            (isl ? wl1 : wr1) + br * 640 + h * 64);
        float s = 0.f;
#pragma unroll
        for (int q = 0; q < 16; q++) {
            float4 a = xv[q];
            float4 bq = wv[q];
            s += a.x * bq.x + a.y * bq.y + a.z * bq.z + a.w * bq.w;
        }
        if (isl) el[(size_t)n * 10 + h] = s;
        else     er[(size_t)n * 10 + h] = s;
    }
}

// ---------------------------------------------------------------------------
// Layer-1 gather on RAW x: 2 warps per node (5 heads each), 4 edges per
// iteration (two pairs; each 16-lane half handles 2 of them). Per-edge exp in
// lanes hl<5; 32-bit x addressing; emits split bf16.
// ---------------------------------------------------------------------------
__global__ void gather1_kernel(const float* __restrict__ xl, const float* __restrict__ xr,
                               const int* __restrict__ cnt, const int* __restrict__ csrsrc,
                               const float* __restrict__ el, const float* __restrict__ er,
                               __nv_bfloat16* __restrict__ agg_hi,
                               __nv_bfloat16* __restrict__ agg_lo,
                               int NPL, int NW) {
    const int gw   = (blockIdx.x * blockDim.x + threadIdx.x) >> 5;
    const int lane = threadIdx.x & 31;
    if (gw >= NW) return;
    const int n    = gw >> 1;
    const int hg   = (gw & 1) * 5;         // head-group base (0 or 5)
    const int half = lane & 16;
    const int hb   = half >> 4;
    const int hl   = lane & 15;
    const int db   = hl * 4;
    const int deg  = min(cnt[n], MAXDEG);
    const float* xb = (n < NPL) ? xl : (xr - (ptrdiff_t)NPL * 64);
    const int* srcp = csrsrc + n * MAXDEG;
    const bool ishd = (hl < 5);

    float ern = ishd ? er[(size_t)n * 10 + hg + hl] : 0.f;

    float4 acc[5];
#pragma unroll
    for (int h = 0; h < 5; h++) acc[h] = make_float4(0.f, 0.f, 0.f, 0.f);
    float den = 0.f;

    for (int i = 0; i < deg; i += 4) {
        int m0 = i + hb, m1 = i + 2 + hb;
        bool v0 = m0 < deg, v1 = m1 < deg;
        int s0 = srcp[v0 ? m0 : 0];
        int s1 = srcp[v1 ? m1 : 0];
        float w0 = 0.f, w1 = 0.f;
        if (ishd) {
            if (v0) w0 = __expf(fminf(lrelu02(el[(unsigned)s0 * 10 + hg + hl] + ern), 60.f));
            if (v1) w1 = __expf(fminf(lrelu02(el[(unsigned)s1 * 10 + hg + hl] + ern), 60.f));
            den += w0 + w1;
        }
        float4 x0 = *reinterpret_cast<const float4*>(xb + ((unsigned)s0 << 6) + db);
        float4 x1 = *reinterpret_cast<const float4*>(xb + ((unsigned)s1 << 6) + db);
#pragma unroll
        for (int h = 0; h < 5; h++) {
            float a0 = __shfl_sync(0xffffffffu, w0, h + half);
            float a1 = __shfl_sync(0xffffffffu, w1, h + half);
            acc[h].x += a0 * x0.x + a1 * x1.x;
            acc[h].y += a0 * x0.y + a1 * x1.y;
            acc[h].z += a0 * x0.z + a1 * x1.z;
            acc[h].w += a0 * x0.w + a1 * x1.w;
        }
    }

    den += __shfl_xor_sync(0xffffffffu, den, 16);
#pragma unroll
    for (int h = 0; h < 5; h++) {
        acc[h].x += __shfl_xor_sync(0xffffffffu, acc[h].x, 16);
        acc[h].y += __shfl_xor_sync(0xffffffffu, acc[h].y, 16);
        acc[h].z += __shfl_xor_sync(0xffffffffu, acc[h].z, 16);
        acc[h].w += __shfl_xor_sync(0xffffffffu, acc[h].w, 16);
    }
    float inv = (deg > 0 && ishd) ? (1.f / den) : 0.f;

    if (lane < 16) {
        size_t base = (size_t)n * 640 + (size_t)hg * 64 + db;
#pragma unroll
        for (int h = 0; h < 5; h++) {
            float ih = __shfl_sync(0x0000ffffu, inv, h);
            float ax = acc[h].x * ih, ay = acc[h].y * ih;
            float az = acc[h].z * ih, aw = acc[h].w * ih;
            __nv_bfloat162 h0 = __floats2bfloat162_rn(ax, ay);
            __nv_bfloat162 h1 = __floats2bfloat162_rn(az, aw);
            float2 f0 = __bfloat1622float2(h0);
            float2 f1 = __bfloat1622float2(h1);
            __nv_bfloat162 l0 = __floats2bfloat162_rn(ax - f0.x, ay - f0.y);
            __nv_bfloat162 l1 = __floats2bfloat162_rn(az - f1.x, aw - f1.y);
            uint2 uh, ul;
            uh.x = *reinterpret_cast<unsigned*>(&h0);
            uh.y = *reinterpret_cast<unsigned*>(&h1);
            ul.x = *reinterpret_cast<unsigned*>(&l0);
            ul.y = *reinterpret_cast<unsigned*>(&l1);
            *reinterpret_cast<uint2*>(agg_hi + base + h * 64) = uh;
            *reinterpret_cast<uint2*>(agg_lo + base + h * 64) = ul;
        }
    }
}

// ---------------------------------------------------------------------------
// headgemm via mma.sync (HMMA): 64-row tile, 256 threads (4 M x 2 N warps),
// split-bf16 (hi*hi + hi*lo + lo*hi), fp32 register accum, cp.async double
// buffering, per-head bias+relu+head-sum, fused elr2 epilogue.
// ---------------------------------------------------------------------------
__global__ void __launch_bounds__(256) headgemm_mma(
    const __nv_bfloat16* __restrict__ agg_hi, const __nv_bfloat16* __restrict__ agg_lo,
    const __nv_bfloat16* __restrict__ w1t_hi, const __nv_bfloat16* __restrict__ w1t_lo,
    const float* __restrict__ b1l, const float* __restrict__ b1r,
    const float* __restrict__ wl2, const float* __restrict__ wr2,
    float* __restrict__ hsum, float* __restrict__ el2, float* __restrict__ er2,
    int NPL) {
    extern __shared__ char sm[];
    const int tid  = threadIdx.x;          // 256 threads, 8 warps
    const int w    = tid >> 5;
    const int lane = tid & 31;
    const int wm   = w & 3;                // M group (16 rows)
    const int wn   = w >> 2;               // N group (32 cols)
    const int gid  = lane >> 2, tid4 = lane & 3;
    const int bm = blockIdx.x * 64;
    const int br = (bm >= NPL);
    const float* b1 = br ? b1r : b1l;
    const uint32_t smb = smem_to_u32(sm);
    float* b1s  = reinterpret_cast<float*>(sm + 65536);
    float* wl2s = reinterpret_cast<float*>(sm + 68096);
    float* wr2s = reinterpret_cast<float*>(sm + 68352);
    float* hs   = reinterpret_cast<float*>(sm);   // epilogue reuse, stride 66

    for (int i = tid; i < 640; i += 256) b1s[i] = b1[i];
    if (tid < 64) { wl2s[tid] = wl2[br * 64 + tid]; wr2s[tid] = wr2[br * 64 + tid]; }

    auto loads = [&](int h) {
        int st = h & 1;
        const char* Ah = (const char*)agg_hi + ((size_t)bm * 640 + h * 64) * 2;
        const char* Al = (const char*)agg_lo + ((size_t)bm * 640 + h * 64) * 2;
        char* Ahd = sm + st * 16384;
        char* Ald = Ahd + 8192;
#pragma unroll
        for (int i = 0; i < 2; i++) {
            int f = tid + i * 256;
            int row = f >> 3, c = f & 7;
            int so = SW128(row * 128 + c * 16);
            size_t go = (size_t)row * 1280 + c * 16;
            cp_async16(Ahd + so, Ah + go);
            cp_async16(Ald + so, Al + go);
        }
        const char* Wh = (const char*)w1t_hi + ((size_t)br * 40960 + h * 4096) * 2;
        const char* Wl = (const char*)w1t_lo + ((size_t)br * 40960 + h * 4096) * 2;
        char* Whd = sm + 32768 + st * 16384;
        char* Wld = Whd + 8192;
#pragma unroll
        for (int i = 0; i < 2; i++) {
            int f = tid + i * 256;
            int row = f >> 3, c = f & 7;
            int so = SW128(row * 128 + c * 16);
            size_t go = (size_t)row * 128 + c * 16;
            cp_async16(Whd + so, Wh + go);
            cp_async16(Wld + so, Wl + go);
        }
        CP_COMMIT();
    };

    loads(0);
    loads(1);

    float out[4][4];
#pragma unroll
    for (int nf = 0; nf < 4; nf++)
#pragma unroll
        for (int j = 0; j < 4; j++) out[nf][j] = 0.f;

    const int arow  = wm * 16 + (lane & 15);
    const int acolb = (lane >> 4) * 16;
    const int brow  = lane & 7;
    const int bcolb = ((lane >> 3) & 1) * 16;

    for (int h = 0; h < 10; h++) {
        if (h < 9) { CP_WAIT1(); } else { CP_WAIT0(); }
        __syncthreads();

        const int st = h & 1;
        const uint32_t Ah = smb + st * 16384;
        const uint32_t Al = Ah + 8192;
        const uint32_t Wh = smb + 32768 + st * 16384;
        const uint32_t Wl = Wh + 8192;

        float d[4][4];
#pragma unroll
        for (int nf = 0; nf < 4; nf++)
#pragma unroll
            for (int j = 0; j < 4; j++) d[nf][j] = 0.f;

#pragma unroll
        for (int kc = 0; kc < 4; kc++) {
            uint32_t aoff = SW128(arow * 128 + kc * 32 + acolb);
            uint32_t ah0, ah1, ah2, ah3, al0, al1, al2, al3;
            LDSM_X4(ah0, ah1, ah2, ah3, Ah + aoff);
            LDSM_X4(al0, al1, al2, al3, Al + aoff);
#pragma unroll
            for (int nf = 0; nf < 4; nf++) {
                uint32_t boff = SW128((wn * 32 + nf * 8 + brow) * 128 + kc * 32 + bcolb);
                uint32_t bh0, bh1, bl0, bl1;
                LDSM_X2(bh0, bh1, Wh + boff);
                LDSM_X2(bl0, bl1, Wl + boff);
                MMA_BF16(d[nf], ah0, ah1, ah2, ah3, bh0, bh1);
                MMA_BF16(d[nf], ah0, ah1, ah2, ah3, bl0, bl1);
                MMA_BF16(d[nf], al0, al1, al2, al3, bh0, bh1);
            }
        }
        __syncthreads();
        if (h + 2 < 10) loads(h + 2);

#pragma unroll
        for (int nf = 0; nf < 4; nf++) {
            int col = wn * 32 + nf * 8 + tid4 * 2;
            float2 bb = *reinterpret_cast<const float2*>(&b1s[h * 64 + col]);
            out[nf][0] += fmaxf(d[nf][0] + bb.x, 0.f);
            out[nf][1] += fmaxf(d[nf][1] + bb.y, 0.f);
            out[nf][2] += fmaxf(d[nf][2] + bb.x, 0.f);
            out[nf][3] += fmaxf(d[nf][3] + bb.y, 0.f);
        }
    }

    __syncthreads();
    const int row0 = wm * 16 + gid;
#pragma unroll
    for (int nf = 0; nf < 4; nf++) {
        int colb = wn * 32 + nf * 8 + tid4 * 2;
        *reinterpret_cast<float2*>(&hs[row0 * 66 + colb])       = make_float2(out[nf][0], out[nf][1]);
        *reinterpret_cast<float2*>(&hs[(row0 + 8) * 66 + colb]) = make_float2(out[nf][2], out[nf][3]);
    }
    __syncthreads();
    if (tid < 64) {
        int row = tid;
        float pl = 0.f, pr = 0.f;
        float4* hp = reinterpret_cast<float4*>(hsum + (size_t)(bm + row) * 64);
#pragma unroll
        for (int c4 = 0; c4 < 16; c4++) {
            float v0 = hs[row * 66 + c4 * 4 + 0];
            float v1 = hs[row * 66 + c4 * 4 + 1];
            float v2 = hs[row * 66 + c4 * 4 + 2];
            float v3 = hs[row * 66 + c4 * 4 + 3];
            pl += v0 * wl2s[c4 * 4] + v1 * wl2s[c4 * 4 + 1] + v2 * wl2s[c4 * 4 + 2] + v3 * wl2s[c4 * 4 + 3];
            pr += v0 * wr2s[c4 * 4] + v1 * wr2s[c4 * 4 + 1] + v2 * wr2s[c4 * 4 + 2] + v3 * wr2s[c4 * 4 + 3];
            hp[c4] = make_float4(v0, v1, v2, v3);
        }
        el2[bm + row] = pl;
        er2[bm + row] = pr;
    }
}

// ---------------------------------------------------------------------------
// Layer-2 gather on hsum: warp per dst node, float2 per lane, distance-1
// prefetch. RESETS cnt[n]=0 (last reader) so no memset launch is needed.
// ---------------------------------------------------------------------------
__global__ void gather2_kernel(const float* __restrict__ hsum, int* __restrict__ cnt,
                               const int* __restrict__ csrsrc, const float* __restrict__ el,
                               const float* __restrict__ er, float* __restrict__ agg2, int NT) {
    int n    = (blockIdx.x * blockDim.x + threadIdx.x) >> 5;
    int lane = threadIdx.x & 31;
    if (n >= NT) return;
    int beg = n * MAXDEG;
    int deg = min(cnt[n], MAXDEG);
    if (lane == 0) cnt[n] = 0;
    int end = beg + deg;
    float2 acc = make_float2(0.f, 0.f);
    float den = 1.f;
    if (deg > 0) {
        den = 0.f;
        const float ern = er[n];
        int s0 = csrsrc[beg];
        bool has1 = beg + 1 < end;
        int s1 = has1 ? csrsrc[beg + 1] : s0;
        float e0 = el[s0], e1 = el[s1];
        float2 v0 = *reinterpret_cast<const float2*>(hsum + (size_t)s0 * 64 + lane * 2);
        float2 v1 = *reinterpret_cast<const float2*>(hsum + (size_t)s1 * 64 + lane * 2);
        for (int i = beg; i < end; i += 2) {
            float ce0 = e0, ce1 = e1;
            float2 cv0 = v0, cv1 = v1;
            bool chas1 = has1;
            int j = i + 2;
            if (j < end) {
                s0 = csrsrc[j];
                has1 = j + 1 < end;
                s1 = has1 ? csrsrc[j + 1] : s0;
                e0 = el[s0]; e1 = el[s1];
                v0 = *reinterpret_cast<const float2*>(hsum + (size_t)s0 * 64 + lane * 2);
                v1 = *reinterpret_cast<const float2*>(hsum + (size_t)s1 * 64 + lane * 2);
            }
            float w0 = __expf(fminf(lrelu02(ce0 + ern), 60.f));
            float w1 = chas1 ? __expf(fminf(lrelu02(ce1 + ern), 60.f)) : 0.f;
            den += w0 + w1;
            acc.x += w0 * cv0.x + w1 * cv1.x;
            acc.y += w0 * cv0.y + w1 * cv1.y;
        }
    }
    const float inv = 1.f / den;
    *reinterpret_cast<float2*>(agg2 + (size_t)n * 64 + lane * 2) =
        make_float2(acc.x * inv, acc.y * inv);
}

// ---------------------------------------------------------------------------
// Fused layer-2 GEMM + bias + relu + graph-max readout (combined rows).
// ---------------------------------------------------------------------------
__global__ void gemm2ro_kernel(const float* __restrict__ X,
                               const float* __restrict__ W2l, const float* __restrict__ b2l,
                               const float* __restrict__ W2r, const float* __restrict__ b2r,
                               const int* __restrict__ gid_l, const int* __restrict__ gid_r,
                               float* __restrict__ read, int NL, int NPL, int NR) {
    __shared__ float XsT[64][68];
    __shared__ float Ws[64][64];
    const int bm  = blockIdx.y * 64;
    const int bn  = blockIdx.x * 64;
    const int br  = (bm >= NPL);
    const float* W  = br ? W2r : W2l;
    const float* b2 = br ? b2r : b2l;
    const int tid = threadIdx.x;

#pragma unroll
    for (int i = 0; i < 16; i++) {
        int e = tid + i * 256;
        int r = e >> 6, k = e & 63;
        XsT[k][r] = X[(size_t)(bm + r) * 64 + k];
    }
#pragma unroll
    for (int i = 0; i < 16; i++) {
        int e = tid + i * 256;
        int k = e >> 6, c = e & 63;
        Ws[k][c] = W[(size_t)k * 128 + bn + c];
    }
    __syncthreads();

    const int tx = tid & 15, ty = tid >> 4;
    const int r0 = ty * 4, c0 = tx * 4;
    float acc[4][4] = {};
#pragma unroll
    for (int k = 0; k < 64; k++) {
        float4 a = *reinterpret_cast<const float4*>(&XsT[k][r0]);
        float4 b = *reinterpret_cast<const float4*>(&Ws[k][c0]);
        acc[0][0] += a.x * b.x; acc[0][1] += a.x * b.y; acc[0][2] += a.x * b.z; acc[0][3] += a.x * b.w;
        acc[1][0] += a.y * b.x; acc[1][1] += a.y * b.y; acc[1][2] += a.y * b.z; acc[1][3] += a.y * b.w;
        acc[2][0] += a.z * b.x; acc[2][1] += a.z * b.y; acc[2][2] += a.z * b.z; acc[2][3] += a.z * b.w;
        acc[3][0] += a.w * b.x; acc[3][1] += a.w * b.y; acc[3][2] += a.w * b.z; acc[3][3] += a.w * b.w;
    }

    float4 bb = *reinterpret_cast<const float4*>(&b2[bn + c0]);
#pragma unroll
    for (int i = 0; i < 4; i++) {
        int r = bm + r0 + i;
        bool vlig = (r < NL);
        bool vrec = (r >= NPL) && (r < NPL + NR);
        if (vlig || vrec) {
            int g   = vlig ? gid_l[r] : gid_r[r - NPL];
            int off = vlig ? 0 : 128;
            int* rp = reinterpret_cast<int*>(read) + (size_t)g * 256 + off + bn + c0;
            atomicMax(rp + 0, __float_as_int(fmaxf(acc[i][0] + bb.x, 0.f)));
            atomicMax(rp + 1, __float_as_int(fmaxf(acc[i][1] + bb.y, 0.f)));
            atomicMax(rp + 2, __float_as_int(fmaxf(acc[i][2] + bb.z, 0.f)));
            atomicMax(rp + 3, __float_as_int(fmaxf(acc[i][3] + bb.w, 0.f)));
        }
    }
}

// ---------------------------------------------------------------------------
// Final MLP head: [32,256] -> relu(@W1+b1) -> relu(@W2+b2) -> [32]
// ---------------------------------------------------------------------------
__global__ void mlp_kernel(const float* __restrict__ read, const float* __restrict__ W1,
                           const float* __restrict__ bb1, const float* __restrict__ W2,
                           const float* __restrict__ bb2, float* __restrict__ out) {
    __shared__ float sin[256];
    __shared__ float red[128];
    int t = threadIdx.x;
    for (int b = 0; b < 32; b++) {
        sin[t]       = read[b * 256 + t];
        sin[t + 128] = read[b * 256 + 128 + t];
        __syncthreads();
        float acc = bb1[t];
#pragma unroll 4
        for (int k = 0; k < 256; k++) acc += sin[k] * W1[(size_t)k * 128 + t];
        acc = fmaxf(acc, 0.f);
        red[t] = acc * W2[t];
        __syncthreads();
        for (int o = 64; o; o >>= 1) {
            if (t < o) red[t] += red[t + o];
            __syncthreads();
        }
        if (t == 0) out[b] = fmaxf(red[0] + bb2[0], 0.f);
        __syncthreads();
    }
}

// ---------------------------------------------------------------------------
// Host-side orchestration
// ---------------------------------------------------------------------------
static inline int div_up(int a, int b) { return (a + b - 1) / b; }

extern "C" void kernel_launch(void* const* d_in, const int* in_sizes, int n_in,
                              void* d_out, int out_size) {
    (void)n_in; (void)out_size;
    const float* x_lig   = (const float*)d_in[0];
    const int*   src_lig = (const int*)  d_in[1];
    const int*   dst_lig = (const int*)  d_in[2];
    const int*   gid_lig = (const int*)  d_in[3];
    const float* x_rec   = (const float*)d_in[4];
    const int*   src_rec = (const int*)  d_in[5];
    const int*   dst_rec = (const int*)  d_in[6];
    const int*   gid_rec = (const int*)  d_in[7];
    const float* W1l  = (const float*)d_in[8];
    const float* al1l = (const float*)d_in[9];
    const float* ar1l = (const float*)d_in[10];
    const float* b1l  = (const float*)d_in[11];
    const float* W2l  = (const float*)d_in[12];
    const float* al2l = (const float*)d_in[13];
    const float* ar2l = (const float*)d_in[14];
    const float* b2l  = (const float*)d_in[15];
    const float* W1r  = (const float*)d_in[16];
    const float* al1r = (const float*)d_in[17];
    const float* ar1r = (const float*)d_in[18];
    const float* b1r  = (const float*)d_in[19];
    const float* W2r  = (const float*)d_in[20];
    const float* al2r = (const float*)d_in[21];
    const float* ar2r = (const float*)d_in[22];
    const float* b2r  = (const float*)d_in[23];
    const float* W_lin1 = (const float*)d_in[24];
    const float* b_lin1 = (const float*)d_in[25];
    const float* W_lin2 = (const float*)d_in[26];
    const float* b_lin2 = (const float*)d_in[27];

    const int NL = in_sizes[0] / 64;
    const int EL = in_sizes[1];
    const int NR = in_sizes[4] / 64;
    const int ER = in_sizes[5];
    const int NPL    = (NL + 127) & ~127;       // rec offset, 128-aligned
    const int NT     = NPL + NR;
    const int NT_pad = (NT + 127) & ~127;
    const int ET     = EL + ER;
    const int SB     = div_up(ET, 256);
    const int EB     = div_up(NT * 32, 256);

    __nv_bfloat16 *agg_hi, *agg_lo, *w1t_hi, *w1t_lo;
    float *hsum, *agg2, *el, *er, *el2, *er2, *read;
    float *wl1, *wr1, *wl2, *wr2;
    int *cnt, *csrsrc;
    cudaGetSymbolAddress((void**)&agg_hi, g_agg_hi);
    cudaGetSymbolAddress((void**)&agg_lo, g_agg_lo);
    cudaGetSymbolAddress((void**)&w1t_hi, g_w1t_hi);
    cudaGetSymbolAddress((void**)&w1t_lo, g_w1t_lo);
    cudaGetSymbolAddress((void**)&hsum,   g_hsum);
    cudaGetSymbolAddress((void**)&agg2,   g_agg2);
    cudaGetSymbolAddress((void**)&el,     g_el);
    cudaGetSymbolAddress((void**)&er,     g_er);
    cudaGetSymbolAddress((void**)&el2,    g_el2);
    cudaGetSymbolAddress((void**)&er2,    g_er2);
    cudaGetSymbolAddress((void**)&cnt,    g_cnt);
    cudaGetSymbolAddress((void**)&csrsrc, g_csrsrc);
    cudaGetSymbolAddress((void**)&wl1,    g_wl1);
    cudaGetSymbolAddress((void**)&wr1,    g_wr1);
    cudaGetSymbolAddress((void**)&wl2,    g_wl2);
    cudaGetSymbolAddress((void**)&wr2,    g_wr2);
    cudaGetSymbolAddress((void**)&read,   g_read);

    cudaFuncSetAttribute(headgemm_mma,
                         cudaFuncAttributeMaxDynamicSharedMemorySize, 68608);

    // ---- FRONT: scatter + weight precompute + elr1 in one launch ----
    front_kernel<<<SB + 440 + EB, 256>>>(
        src_lig, dst_lig, src_rec, dst_rec, cnt, csrsrc,
        W1l, al1l, ar1l, W2l, al2l, ar2l,
        W1r, al1r, ar1r, W2r, al2r, ar2r,
        wl1, wr1, wl2, wr2, w1t_hi, w1t_lo, read,
        x_lig, x_rec, el, er,
        EL, ET, NL, NPL, NT, SB);

    // ---- layer 1: 2-warp-per-node gather (4 edges/iter), HMMA GEMM ----
    gather1_kernel<<<div_up(NT_pad * 64, 256), 256>>>(x_lig, x_rec, cnt, csrsrc,
                                                      el, er, agg_hi, agg_lo,
                                                      NPL, NT_pad * 2);
    headgemm_mma<<<NT_pad / 64, 256, 68608>>>(agg_hi, agg_lo, w1t_hi, w1t_lo,
                                              b1l, b1r, wl2, wr2,
                                              hsum, el2, er2, NPL);

    // ---- layer 2: prefetched gather (+cnt reset), fused GEMM + readout ----
    gather2_kernel<<<div_up(NT * 32, 256), 256>>>(hsum, cnt, csrsrc, el2, er2, agg2, NT);
    gemm2ro_kernel<<<dim3(2, NT_pad / 64), 256>>>(agg2, W2l, b2l, W2r, b2r,
                                                  gid_lig, gid_rec, read, NL, NPL, NR);

    mlp_kernel<<<1, 128>>>(read, W_lin1, b_lin1, W_lin2, b_lin2, (float*)d_out);
}

// round 14
// speedup vs baseline: 1.0963x; 1.0083x over previous
#include <cuda_runtime.h>
#include <cuda_bf16.h>
#include <cstdint>
#include <cstddef>

// ---------------------------------------------------------------------------
// Combined-graph layout: lig nodes [0, NL), pad [NL, NPL), rec [NPL, NPL+NR),
// tail pad to NT_pad (mult of 128). Fixed 64-slot edge buckets per node.
// ---------------------------------------------------------------------------
#define MAXNP 40192
#define MAXDEG 64

__device__ __align__(256) __nv_bfloat16 g_agg_hi[MAXNP * 640];
__device__ __align__(256) __nv_bfloat16 g_agg_lo[MAXNP * 640];
__device__ float g_hsum[MAXNP * 64];
__device__ float g_agg2[MAXNP * 64];
__device__ float g_el[MAXNP * 10];
__device__ float g_er[MAXNP * 10];
__device__ float g_el2[MAXNP];
__device__ float g_er2[MAXNP];
__device__ int   g_cnt[MAXNP];
__device__ int   g_csrsrc[MAXNP * MAXDEG];
__device__ float g_wl1[2 * 640];
__device__ float g_wr1[2 * 640];
__device__ float g_wl2[2 * 64];
__device__ float g_wr2[2 * 64];
__device__ __align__(256) __nv_bfloat16 g_w1t_hi[2 * 40960];  // [br][h][c][k]
__device__ __align__(256) __nv_bfloat16 g_w1t_lo[2 * 40960];
__device__ float g_read[32 * 256];

__device__ __forceinline__ float lrelu02(float e) { return fmaxf(e, 0.2f * e); }

__device__ __forceinline__ uint32_t smem_to_u32(const void* p) {
    uint32_t a;
    asm("{ .reg .u64 t; cvta.to.shared.u64 t, %1; cvt.u32.u64 %0, t; }" : "=r"(a) : "l"(p));
    return a;
}
__device__ __forceinline__ void cp_async16(void* smem_ptr, const void* gptr) {
    unsigned sa = (unsigned)__cvta_generic_to_shared(smem_ptr);
    asm volatile("cp.async.cg.shared.global [%0], [%1], 16;\n" :: "r"(sa), "l"(gptr));
}
#define CP_COMMIT() asm volatile("cp.async.commit_group;\n" ::: "memory")
#define CP_WAIT1()  asm volatile("cp.async.wait_group 1;\n" ::: "memory")
#define CP_WAIT0()  asm volatile("cp.async.wait_group 0;\n" ::: "memory")

#define SW128(o) ((o) ^ (((o) >> 3) & 0x70))

#define LDSM_X4(r0, r1, r2, r3, a) \
    asm volatile("ldmatrix.sync.aligned.m8n8.x4.shared.b16 {%0,%1,%2,%3}, [%4];" \
                 : "=r"(r0), "=r"(r1), "=r"(r2), "=r"(r3) : "r"(a))
#define LDSM_X2(r0, r1, a) \
    asm volatile("ldmatrix.sync.aligned.m8n8.x2.shared.b16 {%0,%1}, [%2];" \
                 : "=r"(r0), "=r"(r1) : "r"(a))
#define MMA_BF16(d, a0, a1, a2, a3, b0, b1) \
    asm volatile("mma.sync.aligned.m16n8k16.row.col.f32.bf16.bf16.f32 " \
                 "{%0,%1,%2,%3}, {%4,%5,%6,%7}, {%8,%9}, {%0,%1,%2,%3};" \
                 : "+f"((d)[0]), "+f"((d)[1]), "+f"((d)[2]), "+f"((d)[3]) \
                 : "r"(a0), "r"(a1), "r"(a2), "r"(a3), "r"(b0), "r"(b1))

// ---------------------------------------------------------------------------
// One-pass bucket scatter. cnt starts zero (zero-init; reset by gather2).
// ---------------------------------------------------------------------------
__global__ void scatter_kernel(const int* __restrict__ src_l, const int* __restrict__ dst_l,
                               const int* __restrict__ src_r, const int* __restrict__ dst_r,
                               int* __restrict__ cnt, int* __restrict__ csrsrc,
                               int EL, int ET, int NPL) {
    int i = blockIdx.x * blockDim.x + threadIdx.x;
    if (i >= ET) return;
    int s, d;
    if (i < EL) { s = src_l[i];            d = dst_l[i]; }
    else        { s = NPL + src_r[i - EL]; d = NPL + dst_r[i - EL]; }
    int p = atomicAdd(&cnt[d], 1);
    if (p < MAXDEG) csrsrc[d * MAXDEG + p] = s;
}

// ---------------------------------------------------------------------------
// Merged weight precompute + read-buffer zeroing.
// Blocks [0,88): al/ar projections. [88,408): W1^T split-bf16. [408,440): read=0.
// ---------------------------------------------------------------------------
__global__ void prep_all(const float* __restrict__ W1l, const float* __restrict__ al1l,
                         const float* __restrict__ ar1l, const float* __restrict__ W2l,
                         const float* __restrict__ al2l, const float* __restrict__ ar2l,
                         const float* __restrict__ W1r, const float* __restrict__ al1r,
                         const float* __restrict__ ar1r, const float* __restrict__ W2r,
                         const float* __restrict__ al2r, const float* __restrict__ ar2r,
                         float* __restrict__ wl1, float* __restrict__ wr1,
                         float* __restrict__ wl2, float* __restrict__ wr2,
                         __nv_bfloat16* __restrict__ hi, __nv_bfloat16* __restrict__ lo,
                         float* __restrict__ read) {
    if (blockIdx.x < 88) {
        int w    = (blockIdx.x * blockDim.x + threadIdx.x) >> 5;
        int lane = threadIdx.x & 31;
        if (w >= 2816) return;
        int combo = w / 704;
        int r     = w - combo * 704;
        int br = combo >> 1, side = combo & 1;
        const float* W1 = br ? W1r : W1l;
        const float* W2 = br ? W2r : W2l;
        const float* a1 = br ? (side ? ar1r : al1r) : (side ? ar1l : al1l);
        const float* a2 = br ? (side ? ar2r : al2r) : (side ? ar2l : al2l);
        float s;
        if (r < 640) {
            int h = r >> 6, k = r & 63;
            s = W1[(size_t)k * 640 + h * 64 + lane]      * a1[h * 64 + lane]
              + W1[(size_t)k * 640 + h * 64 + lane + 32] * a1[h * 64 + lane + 32];
        } else {
            int k = r - 640;
            s = 0.f;
#pragma unroll
            for (int j = 0; j < 4; j++)
                s += W2[(size_t)k * 128 + lane + 32 * j] * a2[lane + 32 * j];
        }
#pragma unroll
        for (int o = 16; o; o >>= 1) s += __shfl_xor_sync(0xffffffffu, s, o);
        if (lane == 0) {
            if (r < 640) (side ? wr1 : wl1)[br * 640 + r]        = s;
            else         (side ? wr2 : wl2)[br * 64 + (r - 640)] = s;
        }
    } else if (blockIdx.x < 408) {
        int idx = (blockIdx.x - 88) * 256 + threadIdx.x;
        if (idx >= 81920) return;
        int br  = idx / 40960;
        int rem = idx - br * 40960;
        int h = rem >> 12;
        int c = (rem >> 6) & 63;
        int k = rem & 63;
        const float* W1 = br ? W1r : W1l;
        float v = W1[(size_t)k * 640 + h * 64 + c];
        __nv_bfloat16 hb = __float2bfloat16(v);
        hi[idx] = hb;
        lo[idx] = __float2bfloat16(v - __bfloat162float(hb));
    } else {
        int idx = (blockIdx.x - 408) * 256 + threadIdx.x;
        if (idx < 8192) read[idx] = 0.f;
    }
}

// ---------------------------------------------------------------------------
// Layer-1 logits over combined nodes. Warp per node.
// ---------------------------------------------------------------------------
__global__ void elr1_kernel(const float* __restrict__ xl, const float* __restrict__ xr,
                            const float* __restrict__ wl1, const float* __restrict__ wr1,
                            float* __restrict__ el, float* __restrict__ er,
                            int NL, int NPL, int NT) {
    int n    = (blockIdx.x * blockDim.x + threadIdx.x) >> 5;
    int lane = threadIdx.x & 31;
    if (n >= NT) return;
    if (n >= NL && n < NPL) return;
    int br = (n >= NPL);
    const float4* xv = reinterpret_cast<const float4*>(
        br ? xr + (size_t)(n - NPL) * 64 : xl + (size_t)n * 64);
    bool isl = lane < 10;
    bool isr = lane >= 16 && lane < 26;
    if (!(isl || isr)) return;
    int h = isl ? lane : lane - 16;
    const float4* wv = reinterpret_cast<const float4*>(
        (isl ? wl1 : wr1) + br * 640 + h * 64);
    float s = 0.f;
#pragma unroll
    for (int q = 0; q < 16; q++) {
        float4 a = xv[q];
        float4 b = wv[q];
        s += a.x * b.x + a.y * b.y + a.z * b.z + a.w * b.w;
    }
    if (isl) el[(size_t)n * 10 + h] = s;
    else     er[(size_t)n * 10 + h] = s;
}

// ---------------------------------------------------------------------------
// Layer-1 gather on RAW x: 2 warps per node (5 heads each), distance-1
// prefetch (R11-proven version). Emits split bf16.
// ---------------------------------------------------------------------------
__global__ void gather1_kernel(const float* __restrict__ xl, const float* __restrict__ xr,
                               const int* __restrict__ cnt, const int* __restrict__ csrsrc,
                               const float* __restrict__ el, const float* __restrict__ er,
                               __nv_bfloat16* __restrict__ agg_hi,
                               __nv_bfloat16* __restrict__ agg_lo,
                               int NPL, int NW) {
    const int gw   = (blockIdx.x * blockDim.x + threadIdx.x) >> 5;
    const int lane = threadIdx.x & 31;
    if (gw >= NW) return;
    const int n    = gw >> 1;
    const int hg   = (gw & 1) * 5;
    const int half = lane & 16;
    const int hb   = half >> 4;
    const int hl   = lane & 15;
    const int db   = hl * 4;
    const int beg = n * MAXDEG;
    const int deg = min(cnt[n], MAXDEG);
    const int end = beg + deg;
    const float* xb = (n < NPL) ? xl : (xr - (ptrdiff_t)NPL * 64);

    float ern = (hl < 5) ? er[(size_t)n * 10 + hg + hl] : 0.f;

    float4 acc[5];
#pragma unroll
    for (int h = 0; h < 5; h++) acc[h] = make_float4(0.f, 0.f, 0.f, 0.f);
    float den = 0.f;

    if (deg > 0) {
        int my = beg + hb;
        bool nvld = my < end;
        int ns = csrsrc[nvld ? my : end - 1];
        float nel = (hl < 5) ? el[(size_t)ns * 10 + hg + hl] : 0.f;
        float4 nv = *reinterpret_cast<const float4*>(xb + (size_t)ns * 64 + db);

        for (int i = beg; i < end; i += 2) {
            bool vld = nvld;
            float e  = nel;
            float4 v = nv;
            int j = i + 2;
            if (j < end) {
                int m2 = j + hb;
                nvld = m2 < end;
                int ni = nvld ? m2 : end - 1;
                ns  = csrsrc[ni];
                nel = (hl < 5) ? el[(size_t)ns * 10 + hg + hl] : 0.f;
                nv  = *reinterpret_cast<const float4*>(xb + (size_t)ns * 64 + db);
            }
            float w = 0.f;
            if (hl < 5) {
                w = vld ? __expf(fminf(lrelu02(e + ern), 60.f)) : 0.f;
                den += w;
            }
#pragma unroll
            for (int h = 0; h < 5; h++) {
                float wh = __shfl_sync(0xffffffffu, w, h + half);
                acc[h].x += wh * v.x;
                acc[h].y += wh * v.y;
                acc[h].z += wh * v.z;
                acc[h].w += wh * v.w;
            }
        }
    }

    den += __shfl_xor_sync(0xffffffffu, den, 16);
#pragma unroll
    for (int h = 0; h < 5; h++) {
        acc[h].x += __shfl_xor_sync(0xffffffffu, acc[h].x, 16);
        acc[h].y += __shfl_xor_sync(0xffffffffu, acc[h].y, 16);
        acc[h].z += __shfl_xor_sync(0xffffffffu, acc[h].z, 16);
        acc[h].w += __shfl_xor_sync(0xffffffffu, acc[h].w, 16);
    }
    float inv = (deg > 0 && hl < 5) ? (1.f / den) : 0.f;

    if (lane < 16) {
        size_t base = (size_t)n * 640 + (size_t)hg * 64 + db;
#pragma unroll
        for (int h = 0; h < 5; h++) {
            float ih = __shfl_sync(0x0000ffffu, inv, h);
            float ax = acc[h].x * ih, ay = acc[h].y * ih;
            float az = acc[h].z * ih, aw = acc[h].w * ih;
            __nv_bfloat162 h0 = __floats2bfloat162_rn(ax, ay);
            __nv_bfloat162 h1 = __floats2bfloat162_rn(az, aw);
            float2 f0 = __bfloat1622float2(h0);
            float2 f1 = __bfloat1622float2(h1);
            __nv_bfloat162 l0 = __floats2bfloat162_rn(ax - f0.x, ay - f0.y);
            __nv_bfloat162 l1 = __floats2bfloat162_rn(az - f1.x, aw - f1.y);
            uint2 uh, ul;
            uh.x = *reinterpret_cast<unsigned*>(&h0);
            uh.y = *reinterpret_cast<unsigned*>(&h1);
            ul.x = *reinterpret_cast<unsigned*>(&l0);
            ul.y = *reinterpret_cast<unsigned*>(&l1);
            *reinterpret_cast<uint2*>(agg_hi + base + h * 64) = uh;
            *reinterpret_cast<uint2*>(agg_lo + base + h * 64) = ul;
        }
    }
}

// ---------------------------------------------------------------------------
// headgemm via mma.sync (HMMA): 64-row tile, 256 threads (4 M x 2 N warps),
// split-bf16 (hi*hi + hi*lo + lo*hi), fp32 register accum, cp.async double
// buffering, per-head bias+relu+head-sum, fused elr2 epilogue.
// ---------------------------------------------------------------------------
__global__ void __launch_bounds__(256) headgemm_mma(
    const __nv_bfloat16* __restrict__ agg_hi, const __nv_bfloat16* __restrict__ agg_lo,
    const __nv_bfloat16* __restrict__ w1t_hi, const __nv_bfloat16* __restrict__ w1t_lo,
    const float* __restrict__ b1l, const float* __restrict__ b1r,
    const float* __restrict__ wl2, const float* __restrict__ wr2,
    float* __restrict__ hsum, float* __restrict__ el2, float* __restrict__ er2,
    int NPL) {
    extern __shared__ char sm[];
    const int tid  = threadIdx.x;
    const int w    = tid >> 5;
    const int lane = tid & 31;
    const int wm   = w & 3;
    const int wn   = w >> 2;
    const int gid  = lane >> 2, tid4 = lane & 3;
    const int bm = blockIdx.x * 64;
    const int br = (bm >= NPL);
    const float* b1 = br ? b1r : b1l;
    const uint32_t smb = smem_to_u32(sm);
    float* b1s  = reinterpret_cast<float*>(sm + 65536);
    float* wl2s = reinterpret_cast<float*>(sm + 68096);
    float* wr2s = reinterpret_cast<float*>(sm + 68352);
    float* hs   = reinterpret_cast<float*>(sm);

    for (int i = tid; i < 640; i += 256) b1s[i] = b1[i];
    if (tid < 64) { wl2s[tid] = wl2[br * 64 + tid]; wr2s[tid] = wr2[br * 64 + tid]; }

    auto loads = [&](int h) {
        int st = h & 1;
        const char* Ah = (const char*)agg_hi + ((size_t)bm * 640 + h * 64) * 2;
        const char* Al = (const char*)agg_lo + ((size_t)bm * 640 + h * 64) * 2;
        char* Ahd = sm + st * 16384;
        char* Ald = Ahd + 8192;
#pragma unroll
        for (int i = 0; i < 2; i++) {
            int f = tid + i * 256;
            int row = f >> 3, c = f & 7;
            int so = SW128(row * 128 + c * 16);
            size_t go = (size_t)row * 1280 + c * 16;
            cp_async16(Ahd + so, Ah + go);
            cp_async16(Ald + so, Al + go);
        }
        const char* Wh = (const char*)w1t_hi + ((size_t)br * 40960 + h * 4096) * 2;
        const char* Wl = (const char*)w1t_lo + ((size_t)br * 40960 + h * 4096) * 2;
        char* Whd = sm + 32768 + st * 16384;
        char* Wld = Whd + 8192;
#pragma unroll
        for (int i = 0; i < 2; i++) {
            int f = tid + i * 256;
            int row = f >> 3, c = f & 7;
            int so = SW128(row * 128 + c * 16);
            size_t go = (size_t)row * 128 + c * 16;
            cp_async16(Whd + so, Wh + go);
            cp_async16(Wld + so, Wl + go);
        }
        CP_COMMIT();
    };

    loads(0);
    loads(1);

    float out[4][4];
#pragma unroll
    for (int nf = 0; nf < 4; nf++)
#pragma unroll
        for (int j = 0; j < 4; j++) out[nf][j] = 0.f;

    const int arow  = wm * 16 + (lane & 15);
    const int acolb = (lane >> 4) * 16;
    const int brow  = lane & 7;
    const int bcolb = ((lane >> 3) & 1) * 16;

    for (int h = 0; h < 10; h++) {
        if (h < 9) { CP_WAIT1(); } else { CP_WAIT0(); }
        __syncthreads();

        const int st = h & 1;
        const uint32_t Ah = smb + st * 16384;
        const uint32_t Al = Ah + 8192;
        const uint32_t Wh = smb + 32768 + st * 16384;
        const uint32_t Wl = Wh + 8192;

        float d[4][4];
#pragma unroll
        for (int nf = 0; nf < 4; nf++)
#pragma unroll
            for (int j = 0; j < 4; j++) d[nf][j] = 0.f;

#pragma unroll
        for (int kc = 0; kc < 4; kc++) {
            uint32_t aoff = SW128(arow * 128 + kc * 32 + acolb);
            uint32_t ah0, ah1, ah2, ah3, al0, al1, al2, al3;
            LDSM_X4(ah0, ah1, ah2, ah3, Ah + aoff);
            LDSM_X4(al0, al1, al2, al3, Al + aoff);
#pragma unroll
            for (int nf = 0; nf < 4; nf++) {
                uint32_t boff = SW128((wn * 32 + nf * 8 + brow) * 128 + kc * 32 + bcolb);
                uint32_t bh0, bh1, bl0, bl1;
                LDSM_X2(bh0, bh1, Wh + boff);
                LDSM_X2(bl0, bl1, Wl + boff);
                MMA_BF16(d[nf], ah0, ah1, ah2, ah3, bh0, bh1);
                MMA_BF16(d[nf], ah0, ah1, ah2, ah3, bl0, bl1);
                MMA_BF16(d[nf], al0, al1, al2, al3, bh0, bh1);
            }
        }
        __syncthreads();
        if (h + 2 < 10) loads(h + 2);

#pragma unroll
        for (int nf = 0; nf < 4; nf++) {
            int col = wn * 32 + nf * 8 + tid4 * 2;
            float2 bb = *reinterpret_cast<const float2*>(&b1s[h * 64 + col]);
            out[nf][0] += fmaxf(d[nf][0] + bb.x, 0.f);
            out[nf][1] += fmaxf(d[nf][1] + bb.y, 0.f);
            out[nf][2] += fmaxf(d[nf][2] + bb.x, 0.f);
            out[nf][3] += fmaxf(d[nf][3] + bb.y, 0.f);
        }
    }

    __syncthreads();
    const int row0 = wm * 16 + gid;
#pragma unroll
    for (int nf = 0; nf < 4; nf++) {
        int colb = wn * 32 + nf * 8 + tid4 * 2;
        *reinterpret_cast<float2*>(&hs[row0 * 66 + colb])       = make_float2(out[nf][0], out[nf][1]);
        *reinterpret_cast<float2*>(&hs[(row0 + 8) * 66 + colb]) = make_float2(out[nf][2], out[nf][3]);
    }
    __syncthreads();
    if (tid < 64) {
        int row = tid;
        float pl = 0.f, pr = 0.f;
        float4* hp = reinterpret_cast<float4*>(hsum + (size_t)(bm + row) * 64);
#pragma unroll
        for (int c4 = 0; c4 < 16; c4++) {
            float v0 = hs[row * 66 + c4 * 4 + 0];
            float v1 = hs[row * 66 + c4 * 4 + 1];
            float v2 = hs[row * 66 + c4 * 4 + 2];
            float v3 = hs[row * 66 + c4 * 4 + 3];
            pl += v0 * wl2s[c4 * 4] + v1 * wl2s[c4 * 4 + 1] + v2 * wl2s[c4 * 4 + 2] + v3 * wl2s[c4 * 4 + 3];
            pr += v0 * wr2s[c4 * 4] + v1 * wr2s[c4 * 4 + 1] + v2 * wr2s[c4 * 4 + 2] + v3 * wr2s[c4 * 4 + 3];
            hp[c4] = make_float4(v0, v1, v2, v3);
        }
        el2[bm + row] = pl;
        er2[bm + row] = pr;
    }
}

// ---------------------------------------------------------------------------
// Layer-2 gather, two-phase: Phase 1 computes NORMALIZED softmax weights for
// edge slots lane and lane+32 with full-lane MUFU + shfl-tree denominator.
// Phase 2 accumulates hsum rows with src/weight already in registers (2 shfl
// + 1 LDG.64 + 2 FMA per edge, independent loads). Resets cnt[n]=0.
// ---------------------------------------------------------------------------
__global__ void gather2_kernel(const float* __restrict__ hsum, int* __restrict__ cnt,
                               const int* __restrict__ csrsrc, const float* __restrict__ el,
                               const float* __restrict__ er, float* __restrict__ agg2, int NT) {
    int n    = (blockIdx.x * blockDim.x + threadIdx.x) >> 5;
    int lane = threadIdx.x & 31;
    if (n >= NT) return;
    int deg = min(cnt[n], MAXDEG);
    if (lane == 0) cnt[n] = 0;
    float2 acc = make_float2(0.f, 0.f);
    if (deg > 0) {
        const float ern = er[n];
        const int* srcp = csrsrc + n * MAXDEG;
        // ---- phase 1: per-slot weights, full-lane MUFU ----
        bool vA = lane < deg, vB = lane + 32 < deg;
        int sA = srcp[vA ? lane : 0];
        int sB = vB ? srcp[lane + 32] : 0;
        float wA = vA ? __expf(fminf(lrelu02(el[sA] + ern), 60.f)) : 0.f;
        float wB = vB ? __expf(fminf(lrelu02(el[sB] + ern), 60.f)) : 0.f;
        float den = wA + wB;
#pragma unroll
        for (int o = 16; o; o >>= 1) den += __shfl_xor_sync(0xffffffffu, den, o);
        float inv = 1.f / den;
        wA *= inv; wB *= inv;
        // ---- phase 2: accumulate (src/w register-resident, loads independent)
        int d1 = min(deg, 32);
        for (int i = 0; i < d1; i++) {
            int   s = __shfl_sync(0xffffffffu, sA, i);
            float a = __shfl_sync(0xffffffffu, wA, i);
            float2 v = *reinterpret_cast<const float2*>(hsum + (size_t)s * 64 + lane * 2);
            acc.x += a * v.x;
            acc.y += a * v.y;
        }
        for (int i = 32; i < deg; i++) {
            int   s = __shfl_sync(0xffffffffu, sB, i - 32);
            float a = __shfl_sync(0xffffffffu, wB, i - 32);
            float2 v = *reinterpret_cast<const float2*>(hsum + (size_t)s * 64 + lane * 2);
            acc.x += a * v.x;
            acc.y += a * v.y;
        }
    }
    *reinterpret_cast<float2*>(agg2 + (size_t)n * 64 + lane * 2) = acc;
}

// ---------------------------------------------------------------------------
// Fused layer-2 GEMM + bias + relu + graph-max readout (combined rows).
// ---------------------------------------------------------------------------
__global__ void gemm2ro_kernel(const float* __restrict__ X,
                               const float* __restrict__ W2l, const float* __restrict__ b2l,
                               const float* __restrict__ W2r, const float* __restrict__ b2r,
                               const int* __restrict__ gid_l, const int* __restrict__ gid_r,
                               float* __restrict__ read, int NL, int NPL, int NR) {
    __shared__ float XsT[64][68];
    __shared__ float Ws[64][64];
    const int bm  = blockIdx.y * 64;
    const int bn  = blockIdx.x * 64;
    const int br  = (bm >= NPL);
    const float* W  = br ? W2r : W2l;
    const float* b2 = br ? b2r : b2l;
    const int tid = threadIdx.x;

#pragma unroll
    for (int i = 0; i < 16; i++) {
        int e = tid + i * 256;
        int r = e >> 6, k = e & 63;
        XsT[k][r] = X[(size_t)(bm + r) * 64 + k];
    }
#pragma unroll
    for (int i = 0; i < 16; i++) {
        int e = tid + i * 256;
        int k = e >> 6, c = e & 63;
        Ws[k][c] = W[(size_t)k * 128 + bn + c];
    }
    __syncthreads();

    const int tx = tid & 15, ty = tid >> 4;
    const int r0 = ty * 4, c0 = tx * 4;
    float acc[4][4] = {};
#pragma unroll
    for (int k = 0; k < 64; k++) {
        float4 a = *reinterpret_cast<const float4*>(&XsT[k][r0]);
        float4 b = *reinterpret_cast<const float4*>(&Ws[k][c0]);
        acc[0][0] += a.x * b.x; acc[0][1] += a.x * b.y; acc[0][2] += a.x * b.z; acc[0][3] += a.x * b.w;
        acc[1][0] += a.y * b.x; acc[1][1] += a.y * b.y; acc[1][2] += a.y * b.z; acc[1][3] += a.y * b.w;
        acc[2][0] += a.z * b.x; acc[2][1] += a.z * b.y; acc[2][2] += a.z * b.z; acc[2][3] += a.z * b.w;
        acc[3][0] += a.w * b.x; acc[3][1] += a.w * b.y; acc[3][2] += a.w * b.z; acc[3][3] += a.w * b.w;
    }

    float4 bb = *reinterpret_cast<const float4*>(&b2[bn + c0]);
#pragma unroll
    for (int i = 0; i < 4; i++) {
        int r = bm + r0 + i;
        bool vlig = (r < NL);
        bool vrec = (r >= NPL) && (r < NPL + NR);
        if (vlig || vrec) {
            int g   = vlig ? gid_l[r] : gid_r[r - NPL];
            int off = vlig ? 0 : 128;
            int* rp = reinterpret_cast<int*>(read) + (size_t)g * 256 + off + bn + c0;
            atomicMax(rp + 0, __float_as_int(fmaxf(acc[i][0] + bb.x, 0.f)));
            atomicMax(rp + 1, __float_as_int(fmaxf(acc[i][1] + bb.y, 0.f)));
            atomicMax(rp + 2, __float_as_int(fmaxf(acc[i][2] + bb.z, 0.f)));
            atomicMax(rp + 3, __float_as_int(fmaxf(acc[i][3] + bb.w, 0.f)));
        }
    }
}

// ---------------------------------------------------------------------------
// Final MLP head: [32,256] -> relu(@W1+b1) -> relu(@W2+b2) -> [32]
// ---------------------------------------------------------------------------
__global__ void mlp_kernel(const float* __restrict__ read, const float* __restrict__ W1,
                           const float* __restrict__ bb1, const float* __restrict__ W2,
                           const float* __restrict__ bb2, float* __restrict__ out) {
    __shared__ float sin[256];
    __shared__ float red[128];
    int t = threadIdx.x;
    for (int b = 0; b < 32; b++) {
        sin[t]       = read[b * 256 + t];
        sin[t + 128] = read[b * 256 + 128 + t];
        __syncthreads();
        float acc = bb1[t];
#pragma unroll 4
        for (int k = 0; k < 256; k++) acc += sin[k] * W1[(size_t)k * 128 + t];
        acc = fmaxf(acc, 0.f);
        red[t] = acc * W2[t];
        __syncthreads();
        for (int o = 64; o; o >>= 1) {
            if (t < o) red[t] += red[t + o];
            __syncthreads();
        }
        if (t == 0) out[b] = fmaxf(red[0] + bb2[0], 0.f);
        __syncthreads();
    }
}

// ---------------------------------------------------------------------------
// Host-side orchestration
// ---------------------------------------------------------------------------
static inline int div_up(int a, int b) { return (a + b - 1) / b; }

extern "C" void kernel_launch(void* const* d_in, const int* in_sizes, int n_in,
                              void* d_out, int out_size) {
    (void)n_in; (void)out_size;
    const float* x_lig   = (const float*)d_in[0];
    const int*   src_lig = (const int*)  d_in[1];
    const int*   dst_lig = (const int*)  d_in[2];
    const int*   gid_lig = (const int*)  d_in[3];
    const float* x_rec   = (const float*)d_in[4];
    const int*   src_rec = (const int*)  d_in[5];
    const int*   dst_rec = (const int*)  d_in[6];
    const int*   gid_rec = (const int*)  d_in[7];
    const float* W1l  = (const float*)d_in[8];
    const float* al1l = (const float*)d_in[9];
    const float* ar1l = (const float*)d_in[10];
    const float* b1l  = (const float*)d_in[11];
    const float* W2l  = (const float*)d_in[12];
    const float* al2l = (const float*)d_in[13];
    const float* ar2l = (const float*)d_in[14];
    const float* b2l  = (const float*)d_in[15];
    const float* W1r  = (const float*)d_in[16];
    const float* al1r = (const float*)d_in[17];
    const float* ar1r = (const float*)d_in[18];
    const float* b1r  = (const float*)d_in[19];
    const float* W2r  = (const float*)d_in[20];
    const float* al2r = (const float*)d_in[21];
    const float* ar2r = (const float*)d_in[22];
    const float* b2r  = (const float*)d_in[23];
    const float* W_lin1 = (const float*)d_in[24];
    const float* b_lin1 = (const float*)d_in[25];
    const float* W_lin2 = (const float*)d_in[26];
    const float* b_lin2 = (const float*)d_in[27];

    const int NL = in_sizes[0] / 64;
    const int EL = in_sizes[1];
    const int NR = in_sizes[4] / 64;
    const int ER = in_sizes[5];
    const int NPL    = (NL + 127) & ~127;       // rec offset, 128-aligned
    const int NT     = NPL + NR;
    const int NT_pad = (NT + 127) & ~127;
    const int ET     = EL + ER;

    __nv_bfloat16 *agg_hi, *agg_lo, *w1t_hi, *w1t_lo;
    float *hsum, *agg2, *el, *er, *el2, *er2, *read;
    float *wl1, *wr1, *wl2, *wr2;
    int *cnt, *csrsrc;
    cudaGetSymbolAddress((void**)&agg_hi, g_agg_hi);
    cudaGetSymbolAddress((void**)&agg_lo, g_agg_lo);
    cudaGetSymbolAddress((void**)&w1t_hi, g_w1t_hi);
    cudaGetSymbolAddress((void**)&w1t_lo, g_w1t_lo);
    cudaGetSymbolAddress((void**)&hsum,   g_hsum);
    cudaGetSymbolAddress((void**)&agg2,   g_agg2);
    cudaGetSymbolAddress((void**)&el,     g_el);
    cudaGetSymbolAddress((void**)&er,     g_er);
    cudaGetSymbolAddress((void**)&el2,    g_el2);
    cudaGetSymbolAddress((void**)&er2,    g_er2);
    cudaGetSymbolAddress((void**)&cnt,    g_cnt);
    cudaGetSymbolAddress((void**)&csrsrc, g_csrsrc);
    cudaGetSymbolAddress((void**)&wl1,    g_wl1);
    cudaGetSymbolAddress((void**)&wr1,    g_wr1);
    cudaGetSymbolAddress((void**)&wl2,    g_wl2);
    cudaGetSymbolAddress((void**)&wr2,    g_wr2);
    cudaGetSymbolAddress((void**)&read,   g_read);

    cudaFuncSetAttribute(headgemm_mma,
                         cudaFuncAttributeMaxDynamicSharedMemorySize, 68608);

    // ---- one-pass bucket CSR (cnt zero from init / gather2's reset) ----
    scatter_kernel<<<div_up(ET, 256), 256>>>(src_lig, dst_lig, src_rec, dst_rec,
                                             cnt, csrsrc, EL, ET, NPL);

    // ---- weights precompute + layer-1 logits ----
    prep_all<<<440, 256>>>(W1l, al1l, ar1l, W2l, al2l, ar2l,
                           W1r, al1r, ar1r, W2r, al2r, ar2r,
                           wl1, wr1, wl2, wr2, w1t_hi, w1t_lo, read);
    elr1_kernel<<<div_up(NT * 32, 256), 256>>>(x_lig, x_rec, wl1, wr1, el, er, NL, NPL, NT);

    // ---- layer 1: 2-warp-per-node gather (bf16 split), HMMA GEMM ----
    gather1_kernel<<<div_up(NT_pad * 64, 256), 256>>>(x_lig, x_rec, cnt, csrsrc,
                                                      el, er, agg_hi, agg_lo,
                                                      NPL, NT_pad * 2);
    headgemm_mma<<<NT_pad / 64, 256, 68608>>>(agg_hi, agg_lo, w1t_hi, w1t_lo,
                                              b1l, b1r, wl2, wr2,
                                              hsum, el2, er2, NPL);

    // ---- layer 2: two-phase gather (+cnt reset), fused GEMM + readout ----
    gather2_kernel<<<div_up(NT * 32, 256), 256>>>(hsum, cnt, csrsrc, el2, er2, agg2, NT);
    gemm2ro_kernel<<<dim3(2, NT_pad / 64), 256>>>(agg2, W2l, b2l, W2r, b2r,
                                                  gid_lig, gid_rec, read, NL, NPL, NR);

    mlp_kernel<<<1, 128>>>(read, W_lin1, b_lin1, W_lin2, b_lin2, (float*)d_out);
}

// round 15
// speedup vs baseline: 1.1984x; 1.0932x over previous
#include <cuda_runtime.h>
#include <cuda_bf16.h>
#include <cstdint>
#include <cstddef>

// ---------------------------------------------------------------------------
// Combined-graph layout: lig nodes [0, NL), pad [NL, NPL), rec [NPL, NPL+NR),
// tail pad to NT_pad (mult of 128). Fixed 64-slot edge buckets per node.
// ---------------------------------------------------------------------------
#define MAXNP 40192
#define MAXDEG 64

__device__ __align__(256) __nv_bfloat16 g_agg_hi[MAXNP * 640];
__device__ __align__(256) __nv_bfloat16 g_agg_lo[MAXNP * 640];
__device__ float g_hsum[MAXNP * 64];
__device__ float g_agg2[MAXNP * 64];
__device__ float g_el[MAXNP * 10];
__device__ float g_er[MAXNP * 10];
__device__ float g_el2[MAXNP];
__device__ float g_er2[MAXNP];
__device__ int   g_cnt[MAXNP];
__device__ int   g_csrsrc[MAXNP * MAXDEG];
__device__ float g_wl1[2 * 640];
__device__ float g_wr1[2 * 640];
__device__ float g_wl2[2 * 64];
__device__ float g_wr2[2 * 64];
__device__ __align__(256) __nv_bfloat16 g_w1t_hi[2 * 40960];  // [br][h][c][k]
__device__ __align__(256) __nv_bfloat16 g_w1t_lo[2 * 40960];
__device__ float g_read[32 * 256];

__device__ __forceinline__ float lrelu02(float e) { return fmaxf(e, 0.2f * e); }

__device__ __forceinline__ uint32_t smem_to_u32(const void* p) {
    uint32_t a;
    asm("{ .reg .u64 t; cvta.to.shared.u64 t, %1; cvt.u32.u64 %0, t; }" : "=r"(a) : "l"(p));
    return a;
}
__device__ __forceinline__ void cp_async16(void* smem_ptr, const void* gptr) {
    unsigned sa = (unsigned)__cvta_generic_to_shared(smem_ptr);
    asm volatile("cp.async.cg.shared.global [%0], [%1], 16;\n" :: "r"(sa), "l"(gptr));
}
#define CP_COMMIT() asm volatile("cp.async.commit_group;\n" ::: "memory")
#define CP_WAIT1()  asm volatile("cp.async.wait_group 1;\n" ::: "memory")
#define CP_WAIT0()  asm volatile("cp.async.wait_group 0;\n" ::: "memory")

#define SW128(o) ((o) ^ (((o) >> 3) & 0x70))

#define LDSM_X4(r0, r1, r2, r3, a) \
    asm volatile("ldmatrix.sync.aligned.m8n8.x4.shared.b16 {%0,%1,%2,%3}, [%4];" \
                 : "=r"(r0), "=r"(r1), "=r"(r2), "=r"(r3) : "r"(a))
#define LDSM_X2(r0, r1, a) \
    asm volatile("ldmatrix.sync.aligned.m8n8.x2.shared.b16 {%0,%1}, [%2];" \
                 : "=r"(r0), "=r"(r1) : "r"(a))
#define MMA_BF16(d, a0, a1, a2, a3, b0, b1) \
    asm volatile("mma.sync.aligned.m16n8k16.row.col.f32.bf16.bf16.f32 " \
                 "{%0,%1,%2,%3}, {%4,%5,%6,%7}, {%8,%9}, {%0,%1,%2,%3};" \
                 : "+f"((d)[0]), "+f"((d)[1]), "+f"((d)[2]), "+f"((d)[3]) \
                 : "r"(a0), "r"(a1), "r"(a2), "r"(a3), "r"(b0), "r"(b1))

// ---------------------------------------------------------------------------
// FRONT kernel: scatter + weight precompute + read zeroing in one launch.
// Block ranges (all tasks write disjoint buffers, no cross-reads):
//   [0, SB)        : bucket scatter of combined edge list
//   [SB, SB+88)    : al/ar projections (warp per output)
//   [SB+88, SB+408): W1^T split-bf16
//   [SB+408,SB+440): zero g_read
// ---------------------------------------------------------------------------
__global__ void front_kernel(
    const int* __restrict__ src_l, const int* __restrict__ dst_l,
    const int* __restrict__ src_r, const int* __restrict__ dst_r,
    int* __restrict__ cnt, int* __restrict__ csrsrc,
    const float* __restrict__ W1l, const float* __restrict__ al1l,
    const float* __restrict__ ar1l, const float* __restrict__ W2l,
    const float* __restrict__ al2l, const float* __restrict__ ar2l,
    const float* __restrict__ W1r, const float* __restrict__ al1r,
    const float* __restrict__ ar1r, const float* __restrict__ W2r,
    const float* __restrict__ al2r, const float* __restrict__ ar2r,
    float* __restrict__ wl1, float* __restrict__ wr1,
    float* __restrict__ wl2, float* __restrict__ wr2,
    __nv_bfloat16* __restrict__ hi, __nv_bfloat16* __restrict__ lo,
    float* __restrict__ read,
    int EL, int ET, int NPL, int SB) {
    int b = blockIdx.x;
    if (b < SB) {
        int i = b * 256 + threadIdx.x;
        if (i >= ET) return;
        int s, d;
        if (i < EL) { s = src_l[i];            d = dst_l[i]; }
        else        { s = NPL + src_r[i - EL]; d = NPL + dst_r[i - EL]; }
        int p = atomicAdd(&cnt[d], 1);
        if (p < MAXDEG) csrsrc[d * MAXDEG + p] = s;
        return;
    }
    b -= SB;
    if (b < 88) {
        int w    = (b * 256 + threadIdx.x) >> 5;
        int lane = threadIdx.x & 31;
        if (w >= 2816) return;
        int combo = w / 704;
        int r     = w - combo * 704;
        int br = combo >> 1, side = combo & 1;
        const float* W1 = br ? W1r : W1l;
        const float* W2 = br ? W2r : W2l;
        const float* a1 = br ? (side ? ar1r : al1r) : (side ? ar1l : al1l);
        const float* a2 = br ? (side ? ar2r : al2r) : (side ? ar2l : al2l);
        float s;
        if (r < 640) {
            int h = r >> 6, k = r & 63;
            s = W1[(size_t)k * 640 + h * 64 + lane]      * a1[h * 64 + lane]
              + W1[(size_t)k * 640 + h * 64 + lane + 32] * a1[h * 64 + lane + 32];
        } else {
            int k = r - 640;
            s = 0.f;
#pragma unroll
            for (int j = 0; j < 4; j++)
                s += W2[(size_t)k * 128 + lane + 32 * j] * a2[lane + 32 * j];
        }
#pragma unroll
        for (int o = 16; o; o >>= 1) s += __shfl_xor_sync(0xffffffffu, s, o);
        if (lane == 0) {
            if (r < 640) (side ? wr1 : wl1)[br * 640 + r]        = s;
            else         (side ? wr2 : wl2)[br * 64 + (r - 640)] = s;
        }
    } else if (b < 408) {
        int idx = (b - 88) * 256 + threadIdx.x;
        if (idx >= 81920) return;
        int br  = idx / 40960;
        int rem = idx - br * 40960;
        int h = rem >> 12;
        int c = (rem >> 6) & 63;
        int k = rem & 63;
        const float* W1 = br ? W1r : W1l;
        float v = W1[(size_t)k * 640 + h * 64 + c];
        __nv_bfloat16 hb = __float2bfloat16(v);
        hi[idx] = hb;
        lo[idx] = __float2bfloat16(v - __bfloat162float(hb));
    } else {
        int idx = (b - 408) * 256 + threadIdx.x;
        if (idx < 8192) read[idx] = 0.f;
    }
}

// ---------------------------------------------------------------------------
// Layer-1 logits over combined nodes. Warp per node.
// ---------------------------------------------------------------------------
__global__ void elr1_kernel(const float* __restrict__ xl, const float* __restrict__ xr,
                            const float* __restrict__ wl1, const float* __restrict__ wr1,
                            float* __restrict__ el, float* __restrict__ er,
                            int NL, int NPL, int NT) {
    int n    = (blockIdx.x * blockDim.x + threadIdx.x) >> 5;
    int lane = threadIdx.x & 31;
    if (n >= NT) return;
    if (n >= NL && n < NPL) return;
    int br = (n >= NPL);
    const float4* xv = reinterpret_cast<const float4*>(
        br ? xr + (size_t)(n - NPL) * 64 : xl + (size_t)n * 64);
    bool isl = lane < 10;
    bool isr = lane >= 16 && lane < 26;
    if (!(isl || isr)) return;
    int h = isl ? lane : lane - 16;
    const float4* wv = reinterpret_cast<const float4*>(
        (isl ? wl1 : wr1) + br * 640 + h * 64);
    float s = 0.f;
#pragma unroll
    for (int q = 0; q < 16; q++) {
        float4 a = xv[q];
        float4 b = wv[q];
        s += a.x * b.x + a.y * b.y + a.z * b.z + a.w * b.w;
    }
    if (isl) el[(size_t)n * 10 + h] = s;
    else     er[(size_t)n * 10 + h] = s;
}

// ---------------------------------------------------------------------------
// Layer-1 gather on RAW x: 2 warps per node (5 heads each), distance-1
// prefetch (R11-proven). Emits split bf16.
// ---------------------------------------------------------------------------
__global__ void gather1_kernel(const float* __restrict__ xl, const float* __restrict__ xr,
                               const int* __restrict__ cnt, const int* __restrict__ csrsrc,
                               const float* __restrict__ el, const float* __restrict__ er,
                               __nv_bfloat16* __restrict__ agg_hi,
                               __nv_bfloat16* __restrict__ agg_lo,
                               int NPL, int NW) {
    const int gw   = (blockIdx.x * blockDim.x + threadIdx.x) >> 5;
    const int lane = threadIdx.x & 31;
    if (gw >= NW) return;
    const int n    = gw >> 1;
    const int hg   = (gw & 1) * 5;
    const int half = lane & 16;
    const int hb   = half >> 4;
    const int hl   = lane & 15;
    const int db   = hl * 4;
    const int beg = n * MAXDEG;
    const int deg = min(cnt[n], MAXDEG);
    const int end = beg + deg;
    const float* xb = (n < NPL) ? xl : (xr - (ptrdiff_t)NPL * 64);

    float ern = (hl < 5) ? er[(size_t)n * 10 + hg + hl] : 0.f;

    float4 acc[5];
#pragma unroll
    for (int h = 0; h < 5; h++) acc[h] = make_float4(0.f, 0.f, 0.f, 0.f);
    float den = 0.f;

    if (deg > 0) {
        int my = beg + hb;
        bool nvld = my < end;
        int ns = csrsrc[nvld ? my : end - 1];
        float nel = (hl < 5) ? el[(size_t)ns * 10 + hg + hl] : 0.f;
        float4 nv = *reinterpret_cast<const float4*>(xb + (size_t)ns * 64 + db);

        for (int i = beg; i < end; i += 2) {
            bool vld = nvld;
            float e  = nel;
            float4 v = nv;
            int j = i + 2;
            if (j < end) {
                int m2 = j + hb;
                nvld = m2 < end;
                int ni = nvld ? m2 : end - 1;
                ns  = csrsrc[ni];
                nel = (hl < 5) ? el[(size_t)ns * 10 + hg + hl] : 0.f;
                nv  = *reinterpret_cast<const float4*>(xb + (size_t)ns * 64 + db);
            }
            float w = 0.f;
            if (hl < 5) {
                w = vld ? __expf(fminf(lrelu02(e + ern), 60.f)) : 0.f;
                den += w;
            }
#pragma unroll
            for (int h = 0; h < 5; h++) {
                float wh = __shfl_sync(0xffffffffu, w, h + half);
                acc[h].x += wh * v.x;
                acc[h].y += wh * v.y;
                acc[h].z += wh * v.z;
                acc[h].w += wh * v.w;
            }
        }
    }

    den += __shfl_xor_sync(0xffffffffu, den, 16);
#pragma unroll
    for (int h = 0; h < 5; h++) {
        acc[h].x += __shfl_xor_sync(0xffffffffu, acc[h].x, 16);
        acc[h].y += __shfl_xor_sync(0xffffffffu, acc[h].y, 16);
        acc[h].z += __shfl_xor_sync(0xffffffffu, acc[h].z, 16);
        acc[h].w += __shfl_xor_sync(0xffffffffu, acc[h].w, 16);
    }
    float inv = (deg > 0 && hl < 5) ? (1.f / den) : 0.f;

    if (lane < 16) {
        size_t base = (size_t)n * 640 + (size_t)hg * 64 + db;
#pragma unroll
        for (int h = 0; h < 5; h++) {
            float ih = __shfl_sync(0x0000ffffu, inv, h);
            float ax = acc[h].x * ih, ay = acc[h].y * ih;
            float az = acc[h].z * ih, aw = acc[h].w * ih;
            __nv_bfloat162 h0 = __floats2bfloat162_rn(ax, ay);
            __nv_bfloat162 h1 = __floats2bfloat162_rn(az, aw);
            float2 f0 = __bfloat1622float2(h0);
            float2 f1 = __bfloat1622float2(h1);
            __nv_bfloat162 l0 = __floats2bfloat162_rn(ax - f0.x, ay - f0.y);
            __nv_bfloat162 l1 = __floats2bfloat162_rn(az - f1.x, aw - f1.y);
            uint2 uh, ul;
            uh.x = *reinterpret_cast<unsigned*>(&h0);
            uh.y = *reinterpret_cast<unsigned*>(&h1);
            ul.x = *reinterpret_cast<unsigned*>(&l0);
            ul.y = *reinterpret_cast<unsigned*>(&l1);
            *reinterpret_cast<uint2*>(agg_hi + base + h * 64) = uh;
            *reinterpret_cast<uint2*>(agg_lo + base + h * 64) = ul;
        }
    }
}

// ---------------------------------------------------------------------------
// headgemm via mma.sync (HMMA): 64-row tile, 256 threads (4 M x 2 N warps),
// split-bf16 (hi*hi + hi*lo + lo*hi), fp32 register accum, cp.async double
// buffering, per-head bias+relu+head-sum, fused elr2 epilogue.
// ---------------------------------------------------------------------------
__global__ void __launch_bounds__(256) headgemm_mma(
    const __nv_bfloat16* __restrict__ agg_hi, const __nv_bfloat16* __restrict__ agg_lo,
    const __nv_bfloat16* __restrict__ w1t_hi, const __nv_bfloat16* __restrict__ w1t_lo,
    const float* __restrict__ b1l, const float* __restrict__ b1r,
    const float* __restrict__ wl2, const float* __restrict__ wr2,
    float* __restrict__ hsum, float* __restrict__ el2, float* __restrict__ er2,
    int NPL) {
    extern __shared__ char sm[];
    const int tid  = threadIdx.x;
    const int w    = tid >> 5;
    const int lane = tid & 31;
    const int wm   = w & 3;
    const int wn   = w >> 2;
    const int gid  = lane >> 2, tid4 = lane & 3;
    const int bm = blockIdx.x * 64;
    const int br = (bm >= NPL);
    const float* b1 = br ? b1r : b1l;
    const uint32_t smb = smem_to_u32(sm);
    float* b1s  = reinterpret_cast<float*>(sm + 65536);
    float* wl2s = reinterpret_cast<float*>(sm + 68096);
    float* wr2s = reinterpret_cast<float*>(sm + 68352);
    float* hs   = reinterpret_cast<float*>(sm);

    for (int i = tid; i < 640; i += 256) b1s[i] = b1[i];
    if (tid < 64) { wl2s[tid] = wl2[br * 64 + tid]; wr2s[tid] = wr2[br * 64 + tid]; }

    auto loads = [&](int h) {
        int st = h & 1;
        const char* Ah = (const char*)agg_hi + ((size_t)bm * 640 + h * 64) * 2;
        const char* Al = (const char*)agg_lo + ((size_t)bm * 640 + h * 64) * 2;
        char* Ahd = sm + st * 16384;
        char* Ald = Ahd + 8192;
#pragma unroll
        for (int i = 0; i < 2; i++) {
            int f = tid + i * 256;
            int row = f >> 3, c = f & 7;
            int so = SW128(row * 128 + c * 16);
            size_t go = (size_t)row * 1280 + c * 16;
            cp_async16(Ahd + so, Ah + go);
            cp_async16(Ald + so, Al + go);
        }
        const char* Wh = (const char*)w1t_hi + ((size_t)br * 40960 + h * 4096) * 2;
        const char* Wl = (const char*)w1t_lo + ((size_t)br * 40960 + h * 4096) * 2;
        char* Whd = sm + 32768 + st * 16384;
        char* Wld = Whd + 8192;
#pragma unroll
        for (int i = 0; i < 2; i++) {
            int f = tid + i * 256;
            int row = f >> 3, c = f & 7;
            int so = SW128(row * 128 + c * 16);
            size_t go = (size_t)row * 128 + c * 16;
            cp_async16(Whd + so, Wh + go);
            cp_async16(Wld + so, Wl + go);
        }
        CP_COMMIT();
    };

    loads(0);
    loads(1);

    float out[4][4];
#pragma unroll
    for (int nf = 0; nf < 4; nf++)
#pragma unroll
        for (int j = 0; j < 4; j++) out[nf][j] = 0.f;

    const int arow  = wm * 16 + (lane & 15);
    const int acolb = (lane >> 4) * 16;
    const int brow  = lane & 7;
    const int bcolb = ((lane >> 3) & 1) * 16;

    for (int h = 0; h < 10; h++) {
        if (h < 9) { CP_WAIT1(); } else { CP_WAIT0(); }
        __syncthreads();

        const int st = h & 1;
        const uint32_t Ah = smb + st * 16384;
        const uint32_t Al = Ah + 8192;
        const uint32_t Wh = smb + 32768 + st * 16384;
        const uint32_t Wl = Wh + 8192;

        float d[4][4];
#pragma unroll
        for (int nf = 0; nf < 4; nf++)
#pragma unroll
            for (int j = 0; j < 4; j++) d[nf][j] = 0.f;

#pragma unroll
        for (int kc = 0; kc < 4; kc++) {
            uint32_t aoff = SW128(arow * 128 + kc * 32 + acolb);
            uint32_t ah0, ah1, ah2, ah3, al0, al1, al2, al3;
            LDSM_X4(ah0, ah1, ah2, ah3, Ah + aoff);
            LDSM_X4(al0, al1, al2, al3, Al + aoff);
#pragma unroll
            for (int nf = 0; nf < 4; nf++) {
                uint32_t boff = SW128((wn * 32 + nf * 8 + brow) * 128 + kc * 32 + bcolb);
                uint32_t bh0, bh1, bl0, bl1;
                LDSM_X2(bh0, bh1, Wh + boff);
                LDSM_X2(bl0, bl1, Wl + boff);
                MMA_BF16(d[nf], ah0, ah1, ah2, ah3, bh0, bh1);
                MMA_BF16(d[nf], ah0, ah1, ah2, ah3, bl0, bl1);
                MMA_BF16(d[nf], al0, al1, al2, al3, bh0, bh1);
            }
        }
        __syncthreads();
        if (h + 2 < 10) loads(h + 2);

#pragma unroll
        for (int nf = 0; nf < 4; nf++) {
            int col = wn * 32 + nf * 8 + tid4 * 2;
            float2 bb = *reinterpret_cast<const float2*>(&b1s[h * 64 + col]);
            out[nf][0] += fmaxf(d[nf][0] + bb.x, 0.f);
            out[nf][1] += fmaxf(d[nf][1] + bb.y, 0.f);
            out[nf][2] += fmaxf(d[nf][2] + bb.x, 0.f);
            out[nf][3] += fmaxf(d[nf][3] + bb.y, 0.f);
        }
    }

    __syncthreads();
    const int row0 = wm * 16 + gid;
#pragma unroll
    for (int nf = 0; nf < 4; nf++) {
        int colb = wn * 32 + nf * 8 + tid4 * 2;
        *reinterpret_cast<float2*>(&hs[row0 * 66 + colb])       = make_float2(out[nf][0], out[nf][1]);
        *reinterpret_cast<float2*>(&hs[(row0 + 8) * 66 + colb]) = make_float2(out[nf][2], out[nf][3]);
    }
    __syncthreads();
    if (tid < 64) {
        int row = tid;
        float pl = 0.f, pr = 0.f;
        float4* hp = reinterpret_cast<float4*>(hsum + (size_t)(bm + row) * 64);
#pragma unroll
        for (int c4 = 0; c4 < 16; c4++) {
            float v0 = hs[row * 66 + c4 * 4 + 0];
            float v1 = hs[row * 66 + c4 * 4 + 1];
            float v2 = hs[row * 66 + c4 * 4 + 2];
            float v3 = hs[row * 66 + c4 * 4 + 3];
            pl += v0 * wl2s[c4 * 4] + v1 * wl2s[c4 * 4 + 1] + v2 * wl2s[c4 * 4 + 2] + v3 * wl2s[c4 * 4 + 3];
            pr += v0 * wr2s[c4 * 4] + v1 * wr2s[c4 * 4 + 1] + v2 * wr2s[c4 * 4 + 2] + v3 * wr2s[c4 * 4 + 3];
            hp[c4] = make_float4(v0, v1, v2, v3);
        }
        el2[bm + row] = pl;
        er2[bm + row] = pr;
    }
}

// ---------------------------------------------------------------------------
// Layer-2 gather on hsum: warp per dst node, float2 per lane, distance-1
// prefetch (R11-proven version).
// ---------------------------------------------------------------------------
__global__ void gather2_kernel(const float* __restrict__ hsum, const int* __restrict__ cnt,
                               const int* __restrict__ csrsrc, const float* __restrict__ el,
                               const float* __restrict__ er, float* __restrict__ agg2, int NT) {
    int n    = (blockIdx.x * blockDim.x + threadIdx.x) >> 5;
    int lane = threadIdx.x & 31;
    if (n >= NT) return;
    int beg = n * MAXDEG;
    int deg = min(cnt[n], MAXDEG);
    int end = beg + deg;
    float2 acc = make_float2(0.f, 0.f);
    float den = 1.f;
    if (deg > 0) {
        den = 0.f;
        const float ern = er[n];
        int s0 = csrsrc[beg];
        bool has1 = beg + 1 < end;
        int s1 = has1 ? csrsrc[beg + 1] : s0;
        float e0 = el[s0], e1 = el[s1];
        float2 v0 = *reinterpret_cast<const float2*>(hsum + (size_t)s0 * 64 + lane * 2);
        float2 v1 = *reinterpret_cast<const float2*>(hsum + (size_t)s1 * 64 + lane * 2);
        for (int i = beg; i < end; i += 2) {
            float ce0 = e0, ce1 = e1;
            float2 cv0 = v0, cv1 = v1;
            bool chas1 = has1;
            int j = i + 2;
            if (j < end) {
                s0 = csrsrc[j];
                has1 = j + 1 < end;
                s1 = has1 ? csrsrc[j + 1] : s0;
                e0 = el[s0]; e1 = el[s1];
                v0 = *reinterpret_cast<const float2*>(hsum + (size_t)s0 * 64 + lane * 2);
                v1 = *reinterpret_cast<const float2*>(hsum + (size_t)s1 * 64 + lane * 2);
            }
            float w0 = __expf(fminf(lrelu02(ce0 + ern), 60.f));
            float w1 = chas1 ? __expf(fminf(lrelu02(ce1 + ern), 60.f)) : 0.f;
            den += w0 + w1;
            acc.x += w0 * cv0.x + w1 * cv1.x;
            acc.y += w0 * cv0.y + w1 * cv1.y;
        }
    }
    const float inv = 1.f / den;
    *reinterpret_cast<float2*>(agg2 + (size_t)n * 64 + lane * 2) =
        make_float2(acc.x * inv, acc.y * inv);
}

// ---------------------------------------------------------------------------
// Fused layer-2 GEMM + bias + relu + graph-max readout (combined rows).
// ---------------------------------------------------------------------------
__global__ void gemm2ro_kernel(const float* __restrict__ X,
                               const float* __restrict__ W2l, const float* __restrict__ b2l,
                               const float* __restrict__ W2r, const float* __restrict__ b2r,
                               const int* __restrict__ gid_l, const int* __restrict__ gid_r,
                               float* __restrict__ read, int NL, int NPL, int NR) {
    __shared__ float XsT[64][68];
    __shared__ float Ws[64][64];
    const int bm  = blockIdx.y * 64;
    const int bn  = blockIdx.x * 64;
    const int br  = (bm >= NPL);
    const float* W  = br ? W2r : W2l;
    const float* b2 = br ? b2r : b2l;
    const int tid = threadIdx.x;

#pragma unroll
    for (int i = 0; i < 16; i++) {
        int e = tid + i * 256;
        int r = e >> 6, k = e & 63;
        XsT[k][r] = X[(size_t)(bm + r) * 64 + k];
    }
#pragma unroll
    for (int i = 0; i < 16; i++) {
        int e = tid + i * 256;
        int k = e >> 6, c = e & 63;
        Ws[k][c] = W[(size_t)k * 128 + bn + c];
    }
    __syncthreads();

    const int tx = tid & 15, ty = tid >> 4;
    const int r0 = ty * 4, c0 = tx * 4;
    float acc[4][4] = {};
#pragma unroll
    for (int k = 0; k < 64; k++) {
        float4 a = *reinterpret_cast<const float4*>(&XsT[k][r0]);
        float4 b = *reinterpret_cast<const float4*>(&Ws[k][c0]);
        acc[0][0] += a.x * b.x; acc[0][1] += a.x * b.y; acc[0][2] += a.x * b.z; acc[0][3] += a.x * b.w;
        acc[1][0] += a.y * b.x; acc[1][1] += a.y * b.y; acc[1][2] += a.y * b.z; acc[1][3] += a.y * b.w;
        acc[2][0] += a.z * b.x; acc[2][1] += a.z * b.y; acc[2][2] += a.z * b.z; acc[2][3] += a.z * b.w;
        acc[3][0] += a.w * b.x; acc[3][1] += a.w * b.y; acc[3][2] += a.w * b.z; acc[3][3] += a.w * b.w;
    }

    float4 bb = *reinterpret_cast<const float4*>(&b2[bn + c0]);
#pragma unroll
    for (int i = 0; i < 4; i++) {
        int r = bm + r0 + i;
        bool vlig = (r < NL);
        bool vrec = (r >= NPL) && (r < NPL + NR);
        if (vlig || vrec) {
            int g   = vlig ? gid_l[r] : gid_r[r - NPL];
            int off = vlig ? 0 : 128;
            int* rp = reinterpret_cast<int*>(read) + (size_t)g * 256 + off + bn + c0;
            atomicMax(rp + 0, __float_as_int(fmaxf(acc[i][0] + bb.x, 0.f)));
            atomicMax(rp + 1, __float_as_int(fmaxf(acc[i][1] + bb.y, 0.f)));
            atomicMax(rp + 2, __float_as_int(fmaxf(acc[i][2] + bb.z, 0.f)));
            atomicMax(rp + 3, __float_as_int(fmaxf(acc[i][3] + bb.w, 0.f)));
        }
    }
}

// ---------------------------------------------------------------------------
// Final MLP head: [32,256] -> relu(@W1+b1) -> relu(@W2+b2) -> [32]
// ---------------------------------------------------------------------------
__global__ void mlp_kernel(const float* __restrict__ read, const float* __restrict__ W1,
                           const float* __restrict__ bb1, const float* __restrict__ W2,
                           const float* __restrict__ bb2, float* __restrict__ out) {
    __shared__ float sin[256];
    __shared__ float red[128];
    int t = threadIdx.x;
    for (int b = 0; b < 32; b++) {
        sin[t]       = read[b * 256 + t];
        sin[t + 128] = read[b * 256 + 128 + t];
        __syncthreads();
        float acc = bb1[t];
#pragma unroll 4
        for (int k = 0; k < 256; k++) acc += sin[k] * W1[(size_t)k * 128 + t];
        acc = fmaxf(acc, 0.f);
        red[t] = acc * W2[t];
        __syncthreads();
        for (int o = 64; o; o >>= 1) {
            if (t < o) red[t] += red[t + o];
            __syncthreads();
        }
        if (t == 0) out[b] = fmaxf(red[0] + bb2[0], 0.f);
        __syncthreads();
    }
}

// ---------------------------------------------------------------------------
// Host-side orchestration
// ---------------------------------------------------------------------------
static inline int div_up(int a, int b) { return (a + b - 1) / b; }

extern "C" void kernel_launch(void* const* d_in, const int* in_sizes, int n_in,
                              void* d_out, int out_size) {
    (void)n_in; (void)out_size;
    const float* x_lig   = (const float*)d_in[0];
    const int*   src_lig = (const int*)  d_in[1];
    const int*   dst_lig = (const int*)  d_in[2];
    const int*   gid_lig = (const int*)  d_in[3];
    const float* x_rec   = (const float*)d_in[4];
    const int*   src_rec = (const int*)  d_in[5];
    const int*   dst_rec = (const int*)  d_in[6];
    const int*   gid_rec = (const int*)  d_in[7];
    const float* W1l  = (const float*)d_in[8];
    const float* al1l = (const float*)d_in[9];
    const float* ar1l = (const float*)d_in[10];
    const float* b1l  = (const float*)d_in[11];
    const float* W2l  = (const float*)d_in[12];
    const float* al2l = (const float*)d_in[13];
    const float* ar2l = (const float*)d_in[14];
    const float* b2l  = (const float*)d_in[15];
    const float* W1r  = (const float*)d_in[16];
    const float* al1r = (const float*)d_in[17];
    const float* ar1r = (const float*)d_in[18];
    const float* b1r  = (const float*)d_in[19];
    const float* W2r  = (const float*)d_in[20];
    const float* al2r = (const float*)d_in[21];
    const float* ar2r = (const float*)d_in[22];
    const float* b2r  = (const float*)d_in[23];
    const float* W_lin1 = (const float*)d_in[24];
    const float* b_lin1 = (const float*)d_in[25];
    const float* W_lin2 = (const float*)d_in[26];
    const float* b_lin2 = (const float*)d_in[27];

    const int NL = in_sizes[0] / 64;
    const int EL = in_sizes[1];
    const int NR = in_sizes[4] / 64;
    const int ER = in_sizes[5];
    const int NPL    = (NL + 127) & ~127;       // rec offset, 128-aligned
    const int NT     = NPL + NR;
    const int NT_pad = (NT + 127) & ~127;
    const int ET     = EL + ER;
    const int SB     = div_up(ET, 256);

    __nv_bfloat16 *agg_hi, *agg_lo, *w1t_hi, *w1t_lo;
    float *hsum, *agg2, *el, *er, *el2, *er2, *read;
    float *wl1, *wr1, *wl2, *wr2;
    int *cnt, *csrsrc;
    cudaGetSymbolAddress((void**)&agg_hi, g_agg_hi);
    cudaGetSymbolAddress((void**)&agg_lo, g_agg_lo);
    cudaGetSymbolAddress((void**)&w1t_hi, g_w1t_hi);
    cudaGetSymbolAddress((void**)&w1t_lo, g_w1t_lo);
    cudaGetSymbolAddress((void**)&hsum,   g_hsum);
    cudaGetSymbolAddress((void**)&agg2,   g_agg2);
    cudaGetSymbolAddress((void**)&el,     g_el);
    cudaGetSymbolAddress((void**)&er,     g_er);
    cudaGetSymbolAddress((void**)&el2,    g_el2);
    cudaGetSymbolAddress((void**)&er2,    g_er2);
    cudaGetSymbolAddress((void**)&cnt,    g_cnt);
    cudaGetSymbolAddress((void**)&csrsrc, g_csrsrc);
    cudaGetSymbolAddress((void**)&wl1,    g_wl1);
    cudaGetSymbolAddress((void**)&wr1,    g_wr1);
    cudaGetSymbolAddress((void**)&wl2,    g_wl2);
    cudaGetSymbolAddress((void**)&wr2,    g_wr2);
    cudaGetSymbolAddress((void**)&read,   g_read);

    cudaFuncSetAttribute(headgemm_mma,
                         cudaFuncAttributeMaxDynamicSharedMemorySize, 68608);

    // ---- CSR zero + FRONT (scatter + weight precompute + read zeroing) ----
    cudaMemsetAsync(cnt, 0, sizeof(int) * (size_t)NT_pad, 0);
    front_kernel<<<SB + 440, 256>>>(
        src_lig, dst_lig, src_rec, dst_rec, cnt, csrsrc,
        W1l, al1l, ar1l, W2l, al2l, ar2l,
        W1r, al1r, ar1r, W2r, al2r, ar2r,
        wl1, wr1, wl2, wr2, w1t_hi, w1t_lo, read,
        EL, ET, NPL, SB);
    elr1_kernel<<<div_up(NT * 32, 256), 256>>>(x_lig, x_rec, wl1, wr1, el, er, NL, NPL, NT);

    // ---- layer 1: 2-warp-per-node gather (bf16 split), HMMA GEMM ----
    gather1_kernel<<<div_up(NT_pad * 64, 256), 256>>>(x_lig, x_rec, cnt, csrsrc,
                                                      el, er, agg_hi, agg_lo,
                                                      NPL, NT_pad * 2);
    headgemm_mma<<<NT_pad / 64, 256, 68608>>>(agg_hi, agg_lo, w1t_hi, w1t_lo,
                                              b1l, b1r, wl2, wr2,
                                              hsum, el2, er2, NPL);

    // ---- layer 2: prefetched gather, fused GEMM + readout ----
    gather2_kernel<<<div_up(NT * 32, 256), 256>>>(hsum, cnt, csrsrc, el2, er2, agg2, NT);
    gemm2ro_kernel<<<dim3(2, NT_pad / 64), 256>>>(agg2, W2l, b2l, W2r, b2r,
                                                  gid_lig, gid_rec, read, NL, NPL, NR);

    mlp_kernel<<<1, 128>>>(read, W_lin1, b_lin1, W_lin2, b_lin2, (float*)d_out);
}

// round 16
// speedup vs baseline: 1.2207x; 1.0186x over previous
#include <cuda_runtime.h>
#include <cuda_bf16.h>
#include <cstdint>
#include <cstddef>

// ---------------------------------------------------------------------------
// Combined-graph layout: lig nodes [0, NL), pad [NL, NPL), rec [NPL, NPL+NR),
// tail pad to NT_pad (mult of 128). Fixed 64-slot edge buckets per node.
// ---------------------------------------------------------------------------
#define MAXNP 40192
#define MAXDEG 64

__device__ __align__(256) __nv_bfloat16 g_agg_hi[MAXNP * 640];
__device__ __align__(256) __nv_bfloat16 g_agg_lo[MAXNP * 640];
__device__ float g_hsum[MAXNP * 64];
__device__ float g_agg2[MAXNP * 64];
__device__ float g_el[MAXNP * 10];
__device__ float g_er[MAXNP * 10];
__device__ float g_el2[MAXNP];
__device__ float g_er2[MAXNP];
__device__ int   g_cnt[MAXNP];
__device__ int   g_csrsrc[MAXNP * MAXDEG];
__device__ float g_wl1[2 * 640];
__device__ float g_wr1[2 * 640];
__device__ float g_wl2[2 * 64];
__device__ float g_wr2[2 * 64];
__device__ __align__(256) __nv_bfloat16 g_w1t_hi[2 * 40960];  // [br][h][c][k]
__device__ __align__(256) __nv_bfloat16 g_w1t_lo[2 * 40960];
__device__ float g_read[32 * 256];

__device__ __forceinline__ float lrelu02(float e) { return fmaxf(e, 0.2f * e); }

__device__ __forceinline__ uint32_t smem_to_u32(const void* p) {
    uint32_t a;
    asm("{ .reg .u64 t; cvta.to.shared.u64 t, %1; cvt.u32.u64 %0, t; }" : "=r"(a) : "l"(p));
    return a;
}
__device__ __forceinline__ void cp_async16(void* smem_ptr, const void* gptr) {
    unsigned sa = (unsigned)__cvta_generic_to_shared(smem_ptr);
    asm volatile("cp.async.cg.shared.global [%0], [%1], 16;\n" :: "r"(sa), "l"(gptr));
}
#define CP_COMMIT() asm volatile("cp.async.commit_group;\n" ::: "memory")
#define CP_WAIT1()  asm volatile("cp.async.wait_group 1;\n" ::: "memory")
#define CP_WAIT0()  asm volatile("cp.async.wait_group 0;\n" ::: "memory")

#define SW128(o) ((o) ^ (((o) >> 3) & 0x70))

#define LDSM_X4(r0, r1, r2, r3, a) \
    asm volatile("ldmatrix.sync.aligned.m8n8.x4.shared.b16 {%0,%1,%2,%3}, [%4];" \
                 : "=r"(r0), "=r"(r1), "=r"(r2), "=r"(r3) : "r"(a))
#define LDSM_X2(r0, r1, a) \
    asm volatile("ldmatrix.sync.aligned.m8n8.x2.shared.b16 {%0,%1}, [%2];" \
                 : "=r"(r0), "=r"(r1) : "r"(a))
#define MMA_BF16(d, a0, a1, a2, a3, b0, b1) \
    asm volatile("mma.sync.aligned.m16n8k16.row.col.f32.bf16.bf16.f32 " \
                 "{%0,%1,%2,%3}, {%4,%5,%6,%7}, {%8,%9}, {%0,%1,%2,%3};" \
                 : "+f"((d)[0]), "+f"((d)[1]), "+f"((d)[2]), "+f"((d)[3]) \
                 : "r"(a0), "r"(a1), "r"(a2), "r"(a3), "r"(b0), "r"(b1))

// ---------------------------------------------------------------------------
// FRONT kernel: scatter + weight precompute + read zeroing in one launch.
// Block ranges (all tasks write disjoint buffers, no cross-reads):
//   [0, SB)        : bucket scatter of combined edge list
//   [SB, SB+88)    : al/ar projections (warp per output)
//   [SB+88, SB+408): W1^T split-bf16
//   [SB+408,SB+440): zero g_read
// ---------------------------------------------------------------------------
__global__ void front_kernel(
    const int* __restrict__ src_l, const int* __restrict__ dst_l,
    const int* __restrict__ src_r, const int* __restrict__ dst_r,
    int* __restrict__ cnt, int* __restrict__ csrsrc,
    const float* __restrict__ W1l, const float* __restrict__ al1l,
    const float* __restrict__ ar1l, const float* __restrict__ W2l,
    const float* __restrict__ al2l, const float* __restrict__ ar2l,
    const float* __restrict__ W1r, const float* __restrict__ al1r,
    const float* __restrict__ ar1r, const float* __restrict__ W2r,
    const float* __restrict__ al2r, const float* __restrict__ ar2r,
    float* __restrict__ wl1, float* __restrict__ wr1,
    float* __restrict__ wl2, float* __restrict__ wr2,
    __nv_bfloat16* __restrict__ hi, __nv_bfloat16* __restrict__ lo,
    float* __restrict__ read,
    int EL, int ET, int NPL, int SB) {
    int b = blockIdx.x;
    if (b < SB) {
        int i = b * 256 + threadIdx.x;
        if (i >= ET) return;
        int s, d;
        if (i < EL) { s = src_l[i];            d = dst_l[i]; }
        else        { s = NPL + src_r[i - EL]; d = NPL + dst_r[i - EL]; }
        int p = atomicAdd(&cnt[d], 1);
        if (p < MAXDEG) csrsrc[d * MAXDEG + p] = s;
        return;
    }
    b -= SB;
    if (b < 88) {
        int w    = (b * 256 + threadIdx.x) >> 5;
        int lane = threadIdx.x & 31;
        if (w >= 2816) return;
        int combo = w / 704;
        int r     = w - combo * 704;
        int br = combo >> 1, side = combo & 1;
        const float* W1 = br ? W1r : W1l;
        const float* W2 = br ? W2r : W2l;
        const float* a1 = br ? (side ? ar1r : al1r) : (side ? ar1l : al1l);
        const float* a2 = br ? (side ? ar2r : al2r) : (side ? ar2l : al2l);
        float s;
        if (r < 640) {
            int h = r >> 6, k = r & 63;
            s = W1[(size_t)k * 640 + h * 64 + lane]      * a1[h * 64 + lane]
              + W1[(size_t)k * 640 + h * 64 + lane + 32] * a1[h * 64 + lane + 32];
        } else {
            int k = r - 640;
            s = 0.f;
#pragma unroll
            for (int j = 0; j < 4; j++)
                s += W2[(size_t)k * 128 + lane + 32 * j] * a2[lane + 32 * j];
        }
#pragma unroll
        for (int o = 16; o; o >>= 1) s += __shfl_xor_sync(0xffffffffu, s, o);
        if (lane == 0) {
            if (r < 640) (side ? wr1 : wl1)[br * 640 + r]        = s;
            else         (side ? wr2 : wl2)[br * 64 + (r - 640)] = s;
        }
    } else if (b < 408) {
        int idx = (b - 88) * 256 + threadIdx.x;
        if (idx >= 81920) return;
        int br  = idx / 40960;
        int rem = idx - br * 40960;
        int h = rem >> 12;
        int c = (rem >> 6) & 63;
        int k = rem & 63;
        const float* W1 = br ? W1r : W1l;
        float v = W1[(size_t)k * 640 + h * 64 + c];
        __nv_bfloat16 hb = __float2bfloat16(v);
        hi[idx] = hb;
        lo[idx] = __float2bfloat16(v - __bfloat162float(hb));
    } else {
        int idx = (b - 408) * 256 + threadIdx.x;
        if (idx < 8192) read[idx] = 0.f;
    }
}

// ---------------------------------------------------------------------------
// Layer-1 logits over combined nodes. Warp per node.
// ---------------------------------------------------------------------------
__global__ void elr1_kernel(const float* __restrict__ xl, const float* __restrict__ xr,
                            const float* __restrict__ wl1, const float* __restrict__ wr1,
                            float* __restrict__ el, float* __restrict__ er,
                            int NL, int NPL, int NT) {
    int n    = (blockIdx.x * blockDim.x + threadIdx.x) >> 5;
    int lane = threadIdx.x & 31;
    if (n >= NT) return;
    if (n >= NL && n < NPL) return;
    int br = (n >= NPL);
    const float4* xv = reinterpret_cast<const float4*>(
        br ? xr + (size_t)(n - NPL) * 64 : xl + (size_t)n * 64);
    bool isl = lane < 10;
    bool isr = lane >= 16 && lane < 26;
    if (!(isl || isr)) return;
    int h = isl ? lane : lane - 16;
    const float4* wv = reinterpret_cast<const float4*>(
        (isl ? wl1 : wr1) + br * 640 + h * 64);
    float s = 0.f;
#pragma unroll
    for (int q = 0; q < 16; q++) {
        float4 a = xv[q];
        float4 b = wv[q];
        s += a.x * b.x + a.y * b.y + a.z * b.z + a.w * b.w;
    }
    if (isl) el[(size_t)n * 10 + h] = s;
    else     er[(size_t)n * 10 + h] = s;
}

// ---------------------------------------------------------------------------
// Layer-1 gather on RAW x: 2 warps per node (5 heads each), distance-1
// prefetch (R11-proven). Emits split bf16.
// ---------------------------------------------------------------------------
__global__ void gather1_kernel(const float* __restrict__ xl, const float* __restrict__ xr,
                               const int* __restrict__ cnt, const int* __restrict__ csrsrc,
                               const float* __restrict__ el, const float* __restrict__ er,
                               __nv_bfloat16* __restrict__ agg_hi,
                               __nv_bfloat16* __restrict__ agg_lo,
                               int NPL, int NW) {
    const int gw   = (blockIdx.x * blockDim.x + threadIdx.x) >> 5;
    const int lane = threadIdx.x & 31;
    if (gw >= NW) return;
    const int n    = gw >> 1;
    const int hg   = (gw & 1) * 5;
    const int half = lane & 16;
    const int hb   = half >> 4;
    const int hl   = lane & 15;
    const int db   = hl * 4;
    const int beg = n * MAXDEG;
    const int deg = min(cnt[n], MAXDEG);
    const int end = beg + deg;
    const float* xb = (n < NPL) ? xl : (xr - (ptrdiff_t)NPL * 64);

    float ern = (hl < 5) ? er[(size_t)n * 10 + hg + hl] : 0.f;

    float4 acc[5];
#pragma unroll
    for (int h = 0; h < 5; h++) acc[h] = make_float4(0.f, 0.f, 0.f, 0.f);
    float den = 0.f;

    if (deg > 0) {
        int my = beg + hb;
        bool nvld = my < end;
        int ns = csrsrc[nvld ? my : end - 1];
        float nel = (hl < 5) ? el[(size_t)ns * 10 + hg + hl] : 0.f;
        float4 nv = *reinterpret_cast<const float4*>(xb + (size_t)ns * 64 + db);

        for (int i = beg; i < end; i += 2) {
            bool vld = nvld;
            float e  = nel;
            float4 v = nv;
            int j = i + 2;
            if (j < end) {
                int m2 = j + hb;
                nvld = m2 < end;
                int ni = nvld ? m2 : end - 1;
                ns  = csrsrc[ni];
                nel = (hl < 5) ? el[(size_t)ns * 10 + hg + hl] : 0.f;
                nv  = *reinterpret_cast<const float4*>(xb + (size_t)ns * 64 + db);
            }
            float w = 0.f;
            if (hl < 5) {
                w = vld ? __expf(fminf(lrelu02(e + ern), 60.f)) : 0.f;
                den += w;
            }
#pragma unroll
            for (int h = 0; h < 5; h++) {
                float wh = __shfl_sync(0xffffffffu, w, h + half);
                acc[h].x += wh * v.x;
                acc[h].y += wh * v.y;
                acc[h].z += wh * v.z;
                acc[h].w += wh * v.w;
            }
        }
    }

    den += __shfl_xor_sync(0xffffffffu, den, 16);
#pragma unroll
    for (int h = 0; h < 5; h++) {
        acc[h].x += __shfl_xor_sync(0xffffffffu, acc[h].x, 16);
        acc[h].y += __shfl_xor_sync(0xffffffffu, acc[h].y, 16);
        acc[h].z += __shfl_xor_sync(0xffffffffu, acc[h].z, 16);
        acc[h].w += __shfl_xor_sync(0xffffffffu, acc[h].w, 16);
    }
    float inv = (deg > 0 && hl < 5) ? (1.f / den) : 0.f;

    if (lane < 16) {
        size_t base = (size_t)n * 640 + (size_t)hg * 64 + db;
#pragma unroll
        for (int h = 0; h < 5; h++) {
            float ih = __shfl_sync(0x0000ffffu, inv, h);
            float ax = acc[h].x * ih, ay = acc[h].y * ih;
            float az = acc[h].z * ih, aw = acc[h].w * ih;
            __nv_bfloat162 h0 = __floats2bfloat162_rn(ax, ay);
            __nv_bfloat162 h1 = __floats2bfloat162_rn(az, aw);
            float2 f0 = __bfloat1622float2(h0);
            float2 f1 = __bfloat1622float2(h1);
            __nv_bfloat162 l0 = __floats2bfloat162_rn(ax - f0.x, ay - f0.y);
            __nv_bfloat162 l1 = __floats2bfloat162_rn(az - f1.x, aw - f1.y);
            uint2 uh, ul;
            uh.x = *reinterpret_cast<unsigned*>(&h0);
            uh.y = *reinterpret_cast<unsigned*>(&h1);
            ul.x = *reinterpret_cast<unsigned*>(&l0);
            ul.y = *reinterpret_cast<unsigned*>(&l1);
            *reinterpret_cast<uint2*>(agg_hi + base + h * 64) = uh;
            *reinterpret_cast<uint2*>(agg_lo + base + h * 64) = ul;
        }
    }
}

// ---------------------------------------------------------------------------
// headgemm via mma.sync (HMMA): 64-row tile, 256 threads (4 M x 2 N warps),
// split-bf16 (hi*hi + hi*lo + lo*hi), fp32 register accum, cp.async double
// buffering, per-head bias+relu+head-sum, fused elr2 epilogue.
// ---------------------------------------------------------------------------
__global__ void __launch_bounds__(256) headgemm_mma(
    const __nv_bfloat16* __restrict__ agg_hi, const __nv_bfloat16* __restrict__ agg_lo,
    const __nv_bfloat16* __restrict__ w1t_hi, const __nv_bfloat16* __restrict__ w1t_lo,
    const float* __restrict__ b1l, const float* __restrict__ b1r,
    const float* __restrict__ wl2, const float* __restrict__ wr2,
    float* __restrict__ hsum, float* __restrict__ el2, float* __restrict__ er2,
    int NPL) {
    extern __shared__ char sm[];
    const int tid  = threadIdx.x;
    const int w    = tid >> 5;
    const int lane = tid & 31;
    const int wm   = w & 3;
    const int wn   = w >> 2;
    const int gid  = lane >> 2, tid4 = lane & 3;
    const int bm = blockIdx.x * 64;
    const int br = (bm >= NPL);
    const float* b1 = br ? b1r : b1l;
    const uint32_t smb = smem_to_u32(sm);
    float* b1s  = reinterpret_cast<float*>(sm + 65536);
    float* wl2s = reinterpret_cast<float*>(sm + 68096);
    float* wr2s = reinterpret_cast<float*>(sm + 68352);
    float* hs   = reinterpret_cast<float*>(sm);

    for (int i = tid; i < 640; i += 256) b1s[i] = b1[i];
    if (tid < 64) { wl2s[tid] = wl2[br * 64 + tid]; wr2s[tid] = wr2[br * 64 + tid]; }

    auto loads = [&](int h) {
        int st = h & 1;
        const char* Ah = (const char*)agg_hi + ((size_t)bm * 640 + h * 64) * 2;
        const char* Al = (const char*)agg_lo + ((size_t)bm * 640 + h * 64) * 2;
        char* Ahd = sm + st * 16384;
        char* Ald = Ahd + 8192;
#pragma unroll
        for (int i = 0; i < 2; i++) {
            int f = tid + i * 256;
            int row = f >> 3, c = f & 7;
            int so = SW128(row * 128 + c * 16);
            size_t go = (size_t)row * 1280 + c * 16;
            cp_async16(Ahd + so, Ah + go);
            cp_async16(Ald + so, Al + go);
        }
        const char* Wh = (const char*)w1t_hi + ((size_t)br * 40960 + h * 4096) * 2;
        const char* Wl = (const char*)w1t_lo + ((size_t)br * 40960 + h * 4096) * 2;
        char* Whd = sm + 32768 + st * 16384;
        char* Wld = Whd + 8192;
#pragma unroll
        for (int i = 0; i < 2; i++) {
            int f = tid + i * 256;
            int row = f >> 3, c = f & 7;
            int so = SW128(row * 128 + c * 16);
            size_t go = (size_t)row * 128 + c * 16;
            cp_async16(Whd + so, Wh + go);
            cp_async16(Wld + so, Wl + go);
        }
        CP_COMMIT();
    };

    loads(0);
    loads(1);

    float out[4][4];
#pragma unroll
    for (int nf = 0; nf < 4; nf++)
#pragma unroll
        for (int j = 0; j < 4; j++) out[nf][j] = 0.f;

    const int arow  = wm * 16 + (lane & 15);
    const int acolb = (lane >> 4) * 16;
    const int brow  = lane & 7;
    const int bcolb = ((lane >> 3) & 1) * 16;

    for (int h = 0; h < 10; h++) {
        if (h < 9) { CP_WAIT1(); } else { CP_WAIT0(); }
        __syncthreads();

        const int st = h & 1;
        const uint32_t Ah = smb + st * 16384;
        const uint32_t Al = Ah + 8192;
        const uint32_t Wh = smb + 32768 + st * 16384;
        const uint32_t Wl = Wh + 8192;

        float d[4][4];
#pragma unroll
        for (int nf = 0; nf < 4; nf++)
#pragma unroll
            for (int j = 0; j < 4; j++) d[nf][j] = 0.f;

#pragma unroll
        for (int kc = 0; kc < 4; kc++) {
            uint32_t aoff = SW128(arow * 128 + kc * 32 + acolb);
            uint32_t ah0, ah1, ah2, ah3, al0, al1, al2, al3;
            LDSM_X4(ah0, ah1, ah2, ah3, Ah + aoff);
            LDSM_X4(al0, al1, al2, al3, Al + aoff);
#pragma unroll
            for (int nf = 0; nf < 4; nf++) {
                uint32_t boff = SW128((wn * 32 + nf * 8 + brow) * 128 + kc * 32 + bcolb);
                uint32_t bh0, bh1, bl0, bl1;
                LDSM_X2(bh0, bh1, Wh + boff);
                LDSM_X2(bl0, bl1, Wl + boff);
                MMA_BF16(d[nf], ah0, ah1, ah2, ah3, bh0, bh1);
                MMA_BF16(d[nf], ah0, ah1, ah2, ah3, bl0, bl1);
                MMA_BF16(d[nf], al0, al1, al2, al3, bh0, bh1);
            }
        }
        __syncthreads();
        if (h + 2 < 10) loads(h + 2);

#pragma unroll
        for (int nf = 0; nf < 4; nf++) {
            int col = wn * 32 + nf * 8 + tid4 * 2;
            float2 bb = *reinterpret_cast<const float2*>(&b1s[h * 64 + col]);
            out[nf][0] += fmaxf(d[nf][0] + bb.x, 0.f);
            out[nf][1] += fmaxf(d[nf][1] + bb.y, 0.f);
            out[nf][2] += fmaxf(d[nf][2] + bb.x, 0.f);
            out[nf][3] += fmaxf(d[nf][3] + bb.y, 0.f);
        }
    }

    __syncthreads();
    const int row0 = wm * 16 + gid;
#pragma unroll
    for (int nf = 0; nf < 4; nf++) {
        int colb = wn * 32 + nf * 8 + tid4 * 2;
        *reinterpret_cast<float2*>(&hs[row0 * 66 + colb])       = make_float2(out[nf][0], out[nf][1]);
        *reinterpret_cast<float2*>(&hs[(row0 + 8) * 66 + colb]) = make_float2(out[nf][2], out[nf][3]);
    }
    __syncthreads();
    if (tid < 64) {
        int row = tid;
        float pl = 0.f, pr = 0.f;
        float4* hp = reinterpret_cast<float4*>(hsum + (size_t)(bm + row) * 64);
#pragma unroll
        for (int c4 = 0; c4 < 16; c4++) {
            float v0 = hs[row * 66 + c4 * 4 + 0];
            float v1 = hs[row * 66 + c4 * 4 + 1];
            float v2 = hs[row * 66 + c4 * 4 + 2];
            float v3 = hs[row * 66 + c4 * 4 + 3];
            pl += v0 * wl2s[c4 * 4] + v1 * wl2s[c4 * 4 + 1] + v2 * wl2s[c4 * 4 + 2] + v3 * wl2s[c4 * 4 + 3];
            pr += v0 * wr2s[c4 * 4] + v1 * wr2s[c4 * 4 + 1] + v2 * wr2s[c4 * 4 + 2] + v3 * wr2s[c4 * 4 + 3];
            hp[c4] = make_float4(v0, v1, v2, v3);
        }
        el2[bm + row] = pl;
        er2[bm + row] = pr;
    }
}

// ---------------------------------------------------------------------------
// Layer-2 gather, smem-staged: Phase 1 computes NORMALIZED weights with
// full-lane MUFU (slots lane, lane+32) + shfl-tree denominator, stages
// (weight, src) into per-warp smem. Phase 2 accumulates hsum rows with
// addresses/weights read via LDS broadcast -> independent LDGs, unroll 4.
// ---------------------------------------------------------------------------
__global__ void gather2_kernel(const float* __restrict__ hsum, const int* __restrict__ cnt,
                               const int* __restrict__ csrsrc, const float* __restrict__ el,
                               const float* __restrict__ er, float* __restrict__ agg2, int NT) {
    __shared__ float sw[8][64];
    __shared__ int   ss[8][64];
    int wid  = threadIdx.x >> 5;
    int n    = (blockIdx.x * blockDim.x + threadIdx.x) >> 5;
    int lane = threadIdx.x & 31;
    if (n >= NT) return;
    int deg = min(cnt[n], MAXDEG);
    float2 acc = make_float2(0.f, 0.f);
    if (deg > 0) {
        const float ern = er[n];
        const int* srcp = csrsrc + n * MAXDEG;
        // ---- phase 1: full-lane weights, normalize, stage to smem ----
        bool vA = lane < deg, vB = lane + 32 < deg;
        int sA = srcp[vA ? lane : 0];
        int sB = vB ? srcp[lane + 32] : 0;
        float wA = vA ? __expf(fminf(lrelu02(el[sA] + ern), 60.f)) : 0.f;
        float wB = vB ? __expf(fminf(lrelu02(el[sB] + ern), 60.f)) : 0.f;
        float den = wA + wB;
#pragma unroll
        for (int o = 16; o; o >>= 1) den += __shfl_xor_sync(0xffffffffu, den, o);
        float inv = 1.f / den;
        sw[wid][lane]      = wA * inv;
        sw[wid][lane + 32] = wB * inv;
        ss[wid][lane]      = sA;
        ss[wid][lane + 32] = sB;
        __syncwarp();
        // ---- phase 2: accumulate; (s,w) via LDS broadcast, independent LDGs
#pragma unroll 4
        for (int i = 0; i < deg; i++) {
            int   s = ss[wid][i];
            float a = sw[wid][i];
            float2 v = *reinterpret_cast<const float2*>(hsum + (size_t)s * 64 + lane * 2);
            acc.x += a * v.x;
            acc.y += a * v.y;
        }
    }
    *reinterpret_cast<float2*>(agg2 + (size_t)n * 64 + lane * 2) = acc;
}

// ---------------------------------------------------------------------------
// Fused layer-2 GEMM + bias + relu + graph-max readout (combined rows).
// ---------------------------------------------------------------------------
__global__ void gemm2ro_kernel(const float* __restrict__ X,
                               const float* __restrict__ W2l, const float* __restrict__ b2l,
                               const float* __restrict__ W2r, const float* __restrict__ b2r,
                               const int* __restrict__ gid_l, const int* __restrict__ gid_r,
                               float* __restrict__ read, int NL, int NPL, int NR) {
    __shared__ float XsT[64][68];
    __shared__ float Ws[64][64];
    const int bm  = blockIdx.y * 64;
    const int bn  = blockIdx.x * 64;
    const int br  = (bm >= NPL);
    const float* W  = br ? W2r : W2l;
    const float* b2 = br ? b2r : b2l;
    const int tid = threadIdx.x;

#pragma unroll
    for (int i = 0; i < 16; i++) {
        int e = tid + i * 256;
        int r = e >> 6, k = e & 63;
        XsT[k][r] = X[(size_t)(bm + r) * 64 + k];
    }
#pragma unroll
    for (int i = 0; i < 16; i++) {
        int e = tid + i * 256;
        int k = e >> 6, c = e & 63;
        Ws[k][c] = W[(size_t)k * 128 + bn + c];
    }
    __syncthreads();

    const int tx = tid & 15, ty = tid >> 4;
    const int r0 = ty * 4, c0 = tx * 4;
    float acc[4][4] = {};
#pragma unroll
    for (int k = 0; k < 64; k++) {
        float4 a = *reinterpret_cast<const float4*>(&XsT[k][r0]);
        float4 b = *reinterpret_cast<const float4*>(&Ws[k][c0]);
        acc[0][0] += a.x * b.x; acc[0][1] += a.x * b.y; acc[0][2] += a.x * b.z; acc[0][3] += a.x * b.w;
        acc[1][0] += a.y * b.x; acc[1][1] += a.y * b.y; acc[1][2] += a.y * b.z; acc[1][3] += a.y * b.w;
        acc[2][0] += a.z * b.x; acc[2][1] += a.z * b.y; acc[2][2] += a.z * b.z; acc[2][3] += a.z * b.w;
        acc[3][0] += a.w * b.x; acc[3][1] += a.w * b.y; acc[3][2] += a.w * b.z; acc[3][3] += a.w * b.w;
    }

    float4 bb = *reinterpret_cast<const float4*>(&b2[bn + c0]);
#pragma unroll
    for (int i = 0; i < 4; i++) {
        int r = bm + r0 + i;
        bool vlig = (r < NL);
        bool vrec = (r >= NPL) && (r < NPL + NR);
        if (vlig || vrec) {
            int g   = vlig ? gid_l[r] : gid_r[r - NPL];
            int off = vlig ? 0 : 128;
            int* rp = reinterpret_cast<int*>(read) + (size_t)g * 256 + off + bn + c0;
            atomicMax(rp + 0, __float_as_int(fmaxf(acc[i][0] + bb.x, 0.f)));
            atomicMax(rp + 1, __float_as_int(fmaxf(acc[i][1] + bb.y, 0.f)));
            atomicMax(rp + 2, __float_as_int(fmaxf(acc[i][2] + bb.z, 0.f)));
            atomicMax(rp + 3, __float_as_int(fmaxf(acc[i][3] + bb.w, 0.f)));
        }
    }
}

// ---------------------------------------------------------------------------
// Final MLP head: [32,256] -> relu(@W1+b1) -> relu(@W2+b2) -> [32]
// ---------------------------------------------------------------------------
__global__ void mlp_kernel(const float* __restrict__ read, const float* __restrict__ W1,
                           const float* __restrict__ bb1, const float* __restrict__ W2,
                           const float* __restrict__ bb2, float* __restrict__ out) {
    __shared__ float sin[256];
    __shared__ float red[128];
    int t = threadIdx.x;
    for (int b = 0; b < 32; b++) {
        sin[t]       = read[b * 256 + t];
        sin[t + 128] = read[b * 256 + 128 + t];
        __syncthreads();
        float acc = bb1[t];
#pragma unroll 4
        for (int k = 0; k < 256; k++) acc += sin[k] * W1[(size_t)k * 128 + t];
        acc = fmaxf(acc, 0.f);
        red[t] = acc * W2[t];
        __syncthreads();
        for (int o = 64; o; o >>= 1) {
            if (t < o) red[t] += red[t + o];
            __syncthreads();
        }
        if (t == 0) out[b] = fmaxf(red[0] + bb2[0], 0.f);
        __syncthreads();
    }
}

// ---------------------------------------------------------------------------
// Host-side orchestration
// ---------------------------------------------------------------------------
static inline int div_up(int a, int b) { return (a + b - 1) / b; }

extern "C" void kernel_launch(void* const* d_in, const int* in_sizes, int n_in,
                              void* d_out, int out_size) {
    (void)n_in; (void)out_size;
    const float* x_lig   = (const float*)d_in[0];
    const int*   src_lig = (const int*)  d_in[1];
    const int*   dst_lig = (const int*)  d_in[2];
    const int*   gid_lig = (const int*)  d_in[3];
    const float* x_rec   = (const float*)d_in[4];
    const int*   src_rec = (const int*)  d_in[5];
    const int*   dst_rec = (const int*)  d_in[6];
    const int*   gid_rec = (const int*)  d_in[7];
    const float* W1l  = (const float*)d_in[8];
    const float* al1l = (const float*)d_in[9];
    const float* ar1l = (const float*)d_in[10];
    const float* b1l  = (const float*)d_in[11];
    const float* W2l  = (const float*)d_in[12];
    const float* al2l = (const float*)d_in[13];
    const float* ar2l = (const float*)d_in[14];
    const float* b2l  = (const float*)d_in[15];
    const float* W1r  = (const float*)d_in[16];
    const float* al1r = (const float*)d_in[17];
    const float* ar1r = (const float*)d_in[18];
    const float* b1r  = (const float*)d_in[19];
    const float* W2r  = (const float*)d_in[20];
    const float* al2r = (const float*)d_in[21];
    const float* ar2r = (const float*)d_in[22];
    const float* b2r  = (const float*)d_in[23];
    const float* W_lin1 = (const float*)d_in[24];
    const float* b_lin1 = (const float*)d_in[25];
    const float* W_lin2 = (const float*)d_in[26];
    const float* b_lin2 = (const float*)d_in[27];

    const int NL = in_sizes[0] / 64;
    const int EL = in_sizes[1];
    const int NR = in_sizes[4] / 64;
    const int ER = in_sizes[5];
    const int NPL    = (NL + 127) & ~127;       // rec offset, 128-aligned
    const int NT     = NPL + NR;
    const int NT_pad = (NT + 127) & ~127;
    const int ET     = EL + ER;
    const int SB     = div_up(ET, 256);

    __nv_bfloat16 *agg_hi, *agg_lo, *w1t_hi, *w1t_lo;
    float *hsum, *agg2, *el, *er, *el2, *er2, *read;
    float *wl1, *wr1, *wl2, *wr2;
    int *cnt, *csrsrc;
    cudaGetSymbolAddress((void**)&agg_hi, g_agg_hi);
    cudaGetSymbolAddress((void**)&agg_lo, g_agg_lo);
    cudaGetSymbolAddress((void**)&w1t_hi, g_w1t_hi);
    cudaGetSymbolAddress((void**)&w1t_lo, g_w1t_lo);
    cudaGetSymbolAddress((void**)&hsum,   g_hsum);
    cudaGetSymbolAddress((void**)&agg2,   g_agg2);
    cudaGetSymbolAddress((void**)&el,     g_el);
    cudaGetSymbolAddress((void**)&er,     g_er);
    cudaGetSymbolAddress((void**)&el2,    g_el2);
    cudaGetSymbolAddress((void**)&er2,    g_er2);
    cudaGetSymbolAddress((void**)&cnt,    g_cnt);
    cudaGetSymbolAddress((void**)&csrsrc, g_csrsrc);
    cudaGetSymbolAddress((void**)&wl1,    g_wl1);
    cudaGetSymbolAddress((void**)&wr1,    g_wr1);
    cudaGetSymbolAddress((void**)&wl2,    g_wl2);
    cudaGetSymbolAddress((void**)&wr2,    g_wr2);
    cudaGetSymbolAddress((void**)&read,   g_read);

    cudaFuncSetAttribute(headgemm_mma,
                         cudaFuncAttributeMaxDynamicSharedMemorySize, 68608);

    // ---- CSR zero + FRONT (scatter + weight precompute + read zeroing) ----
    cudaMemsetAsync(cnt, 0, sizeof(int) * (size_t)NT_pad, 0);
    front_kernel<<<SB + 440, 256>>>(
        src_lig, dst_lig, src_rec, dst_rec, cnt, csrsrc,
        W1l, al1l, ar1l, W2l, al2l, ar2l,
        W1r, al1r, ar1r, W2r, al2r, ar2r,
        wl1, wr1, wl2, wr2, w1t_hi, w1t_lo, read,
        EL, ET, NPL, SB);
    elr1_kernel<<<div_up(NT * 32, 256), 256>>>(x_lig, x_rec, wl1, wr1, el, er, NL, NPL, NT);

    // ---- layer 1: 2-warp-per-node gather (bf16 split), HMMA GEMM ----
    gather1_kernel<<<div_up(NT_pad * 64, 256), 256>>>(x_lig, x_rec, cnt, csrsrc,
                                                      el, er, agg_hi, agg_lo,
                                                      NPL, NT_pad * 2);
    headgemm_mma<<<NT_pad / 64, 256, 68608>>>(agg_hi, agg_lo, w1t_hi, w1t_lo,
                                              b1l, b1r, wl2, wr2,
                                              hsum, el2, er2, NPL);

    // ---- layer 2: smem-staged gather, fused GEMM + readout ----
    gather2_kernel<<<div_up(NT * 32, 256), 256>>>(hsum, cnt, csrsrc, el2, er2, agg2, NT);
    gemm2ro_kernel<<<dim3(2, NT_pad / 64), 256>>>(agg2, W2l, b2l, W2r, b2r,
                                                  gid_lig, gid_rec, read, NL, NPL, NR);

    mlp_kernel<<<1, 128>>>(read, W_lin1, b_lin1, W_lin2, b_lin2, (float*)d_out);
}

// round 17
// speedup vs baseline: 1.2411x; 1.0167x over previous
#include <cuda_runtime.h>
#include <cuda_bf16.h>
#include <cstdint>
#include <cstddef>

// ---------------------------------------------------------------------------
// Combined-graph layout: lig nodes [0, NL), pad [NL, NPL), rec [NPL, NPL+NR),
// tail pad to NT_pad (mult of 128). Fixed 64-slot edge buckets per node.
// ---------------------------------------------------------------------------
#define MAXNP 40192
#define MAXDEG 64

__device__ __align__(256) __nv_bfloat16 g_agg_hi[MAXNP * 640];
__device__ __align__(256) __nv_bfloat16 g_agg_lo[MAXNP * 640];
__device__ float g_hsum[MAXNP * 64];
__device__ float g_agg2[MAXNP * 64];
__device__ float g_el[MAXNP * 10];
__device__ float g_er[MAXNP * 10];
__device__ float g_el2[MAXNP];
__device__ float g_er2[MAXNP];
__device__ int   g_cnt[MAXNP];
__device__ int   g_csrsrc[MAXNP * MAXDEG];
__device__ float g_wl1[2 * 640];
__device__ float g_wr1[2 * 640];
__device__ float g_wl2[2 * 64];
__device__ float g_wr2[2 * 64];
__device__ __align__(256) __nv_bfloat16 g_w1t_hi[2 * 40960];  // [br][h][c][k]
__device__ __align__(256) __nv_bfloat16 g_w1t_lo[2 * 40960];
__device__ float g_read[32 * 256];

__device__ __forceinline__ float lrelu02(float e) { return fmaxf(e, 0.2f * e); }

__device__ __forceinline__ uint32_t smem_to_u32(const void* p) {
    uint32_t a;
    asm("{ .reg .u64 t; cvta.to.shared.u64 t, %1; cvt.u32.u64 %0, t; }" : "=r"(a) : "l"(p));
    return a;
}
__device__ __forceinline__ void cp_async16(void* smem_ptr, const void* gptr) {
    unsigned sa = (unsigned)__cvta_generic_to_shared(smem_ptr);
    asm volatile("cp.async.cg.shared.global [%0], [%1], 16;\n" :: "r"(sa), "l"(gptr));
}
#define CP_COMMIT() asm volatile("cp.async.commit_group;\n" ::: "memory")
#define CP_WAIT1()  asm volatile("cp.async.wait_group 1;\n" ::: "memory")
#define CP_WAIT0()  asm volatile("cp.async.wait_group 0;\n" ::: "memory")

#define SW128(o) ((o) ^ (((o) >> 3) & 0x70))

#define LDSM_X4(r0, r1, r2, r3, a) \
    asm volatile("ldmatrix.sync.aligned.m8n8.x4.shared.b16 {%0,%1,%2,%3}, [%4];" \
                 : "=r"(r0), "=r"(r1), "=r"(r2), "=r"(r3) : "r"(a))
#define LDSM_X2(r0, r1, a) \
    asm volatile("ldmatrix.sync.aligned.m8n8.x2.shared.b16 {%0,%1}, [%2];" \
                 : "=r"(r0), "=r"(r1) : "r"(a))
#define MMA_BF16(d, a0, a1, a2, a3, b0, b1) \
    asm volatile("mma.sync.aligned.m16n8k16.row.col.f32.bf16.bf16.f32 " \
                 "{%0,%1,%2,%3}, {%4,%5,%6,%7}, {%8,%9}, {%0,%1,%2,%3};" \
                 : "+f"((d)[0]), "+f"((d)[1]), "+f"((d)[2]), "+f"((d)[3]) \
                 : "r"(a0), "r"(a1), "r"(a2), "r"(a3), "r"(b0), "r"(b1))

// ---------------------------------------------------------------------------
// FRONT kernel: scatter + weight precompute + read zeroing in one launch.
//   [0, SB)        : bucket scatter of combined edge list
//   [SB, SB+88)    : al/ar projections (warp per output)
//   [SB+88, SB+408): W1^T split-bf16
//   [SB+408,SB+440): zero g_read
// ---------------------------------------------------------------------------
__global__ void front_kernel(
    const int* __restrict__ src_l, const int* __restrict__ dst_l,
    const int* __restrict__ src_r, const int* __restrict__ dst_r,
    int* __restrict__ cnt, int* __restrict__ csrsrc,
    const float* __restrict__ W1l, const float* __restrict__ al1l,
    const float* __restrict__ ar1l, const float* __restrict__ W2l,
    const float* __restrict__ al2l, const float* __restrict__ ar2l,
    const float* __restrict__ W1r, const float* __restrict__ al1r,
    const float* __restrict__ ar1r, const float* __restrict__ W2r,
    const float* __restrict__ al2r, const float* __restrict__ ar2r,
    float* __restrict__ wl1, float* __restrict__ wr1,
    float* __restrict__ wl2, float* __restrict__ wr2,
    __nv_bfloat16* __restrict__ hi, __nv_bfloat16* __restrict__ lo,
    float* __restrict__ read,
    int EL, int ET, int NPL, int SB) {
    int b = blockIdx.x;
    if (b < SB) {
        int i = b * 256 + threadIdx.x;
        if (i >= ET) return;
        int s, d;
        if (i < EL) { s = src_l[i];            d = dst_l[i]; }
        else        { s = NPL + src_r[i - EL]; d = NPL + dst_r[i - EL]; }
        int p = atomicAdd(&cnt[d], 1);
        if (p < MAXDEG) csrsrc[d * MAXDEG + p] = s;
        return;
    }
    b -= SB;
    if (b < 88) {
        int w    = (b * 256 + threadIdx.x) >> 5;
        int lane = threadIdx.x & 31;
        if (w >= 2816) return;
        int combo = w / 704;
        int r     = w - combo * 704;
        int br = combo >> 1, side = combo & 1;
        const float* W1 = br ? W1r : W1l;
        const float* W2 = br ? W2r : W2l;
        const float* a1 = br ? (side ? ar1r : al1r) : (side ? ar1l : al1l);
        const float* a2 = br ? (side ? ar2r : al2r) : (side ? ar2l : al2l);
        float s;
        if (r < 640) {
            int h = r >> 6, k = r & 63;
            s = W1[(size_t)k * 640 + h * 64 + lane]      * a1[h * 64 + lane]
              + W1[(size_t)k * 640 + h * 64 + lane + 32] * a1[h * 64 + lane + 32];
        } else {
            int k = r - 640;
            s = 0.f;
#pragma unroll
            for (int j = 0; j < 4; j++)
                s += W2[(size_t)k * 128 + lane + 32 * j] * a2[lane + 32 * j];
        }
#pragma unroll
        for (int o = 16; o; o >>= 1) s += __shfl_xor_sync(0xffffffffu, s, o);
        if (lane == 0) {
            if (r < 640) (side ? wr1 : wl1)[br * 640 + r]        = s;
            else         (side ? wr2 : wl2)[br * 64 + (r - 640)] = s;
        }
    } else if (b < 408) {
        int idx = (b - 88) * 256 + threadIdx.x;
        if (idx >= 81920) return;
        int br  = idx / 40960;
        int rem = idx - br * 40960;
        int h = rem >> 12;
        int c = (rem >> 6) & 63;
        int k = rem & 63;
        const float* W1 = br ? W1r : W1l;
        float v = W1[(size_t)k * 640 + h * 64 + c];
        __nv_bfloat16 hb = __float2bfloat16(v);
        hi[idx] = hb;
        lo[idx] = __float2bfloat16(v - __bfloat162float(hb));
    } else {
        int idx = (b - 408) * 256 + threadIdx.x;
        if (idx < 8192) read[idx] = 0.f;
    }
}

// ---------------------------------------------------------------------------
// Layer-1 logits over combined nodes. Warp per node.
// ---------------------------------------------------------------------------
__global__ void elr1_kernel(const float* __restrict__ xl, const float* __restrict__ xr,
                            const float* __restrict__ wl1, const float* __restrict__ wr1,
                            float* __restrict__ el, float* __restrict__ er,
                            int NL, int NPL, int NT) {
    int n    = (blockIdx.x * blockDim.x + threadIdx.x) >> 5;
    int lane = threadIdx.x & 31;
    if (n >= NT) return;
    if (n >= NL && n < NPL) return;
    int br = (n >= NPL);
    const float4* xv = reinterpret_cast<const float4*>(
        br ? xr + (size_t)(n - NPL) * 64 : xl + (size_t)n * 64);
    bool isl = lane < 10;
    bool isr = lane >= 16 && lane < 26;
    if (!(isl || isr)) return;
    int h = isl ? lane : lane - 16;
    const float4* wv = reinterpret_cast<const float4*>(
        (isl ? wl1 : wr1) + br * 640 + h * 64);
    float s = 0.f;
#pragma unroll
    for (int q = 0; q < 16; q++) {
        float4 a = xv[q];
        float4 b = wv[q];
        s += a.x * b.x + a.y * b.y + a.z * b.z + a.w * b.w;
    }
    if (isl) el[(size_t)n * 10 + h] = s;
    else     er[(size_t)n * 10 + h] = s;
}

// ---------------------------------------------------------------------------
// Layer-1 gather, smem-staged (R16 gather2 pattern): 2 warps per node
// (5 heads each). Phase 1: lanes = edge slots, full-lane MUFU weights for 5
// heads, shfl-tree denominators, NORMALIZED (w,src) staged to per-warp smem
// (1.5 KB/warp). Phase 2: clean loop -- per 2 edges: LDS src + 5 LDS w
// (broadcast) + LDG.128 x + 20 FMA; no exp/el/div in the loop.
// ---------------------------------------------------------------------------
__global__ void gather1_kernel(const float* __restrict__ xl, const float* __restrict__ xr,
                               const int* __restrict__ cnt, const int* __restrict__ csrsrc,
                               const float* __restrict__ el, const float* __restrict__ er,
                               __nv_bfloat16* __restrict__ agg_hi,
                               __nv_bfloat16* __restrict__ agg_lo,
                               int NPL, int NW) {
    __shared__ float sw[8][MAXDEG * 5];
    __shared__ int   ss[8][MAXDEG];
    const int wid  = threadIdx.x >> 5;
    const int gw   = (blockIdx.x * blockDim.x + threadIdx.x) >> 5;
    const int lane = threadIdx.x & 31;
    if (gw >= NW) return;
    const int n    = gw >> 1;
    const int hg   = (gw & 1) * 5;
    const int half = lane & 16;
    const int hb   = half >> 4;
    const int hl   = lane & 15;
    const int db   = hl * 4;
    const int deg  = min(cnt[n], MAXDEG);
    const float* xb = (n < NPL) ? xl : (xr - (ptrdiff_t)NPL * 64);

    float4 acc[5];
#pragma unroll
    for (int h = 0; h < 5; h++) acc[h] = make_float4(0.f, 0.f, 0.f, 0.f);

    if (deg > 0) {
        // ---- phase 1: full-lane weights for slots (lane, lane+32), 5 heads
        const int* srcp = csrsrc + n * MAXDEG;
        float ern[5];
#pragma unroll
        for (int h = 0; h < 5; h++) ern[h] = er[(size_t)n * 10 + hg + h];
        bool vA = lane < deg, vB = lane + 32 < deg;
        int sA = srcp[vA ? lane : 0];
        int sB = vB ? srcp[lane + 32] : 0;
        float wA[5], wB[5];
        const float* elA = el + (size_t)sA * 10 + hg;
        const float* elB = el + (size_t)sB * 10 + hg;
#pragma unroll
        for (int h = 0; h < 5; h++) {
            wA[h] = vA ? __expf(fminf(lrelu02(elA[h] + ern[h]), 60.f)) : 0.f;
            wB[h] = vB ? __expf(fminf(lrelu02(elB[h] + ern[h]), 60.f)) : 0.f;
        }
#pragma unroll
        for (int h = 0; h < 5; h++) {
            float d = wA[h] + wB[h];
#pragma unroll
            for (int o = 16; o; o >>= 1) d += __shfl_xor_sync(0xffffffffu, d, o);
            float inv = 1.f / d;
            wA[h] *= inv; wB[h] *= inv;
        }
        if (vA) {
            ss[wid][lane] = sA;
#pragma unroll
            for (int h = 0; h < 5; h++) sw[wid][lane * 5 + h] = wA[h];
        }
        if (vB) {
            ss[wid][lane + 32] = sB;
#pragma unroll
            for (int h = 0; h < 5; h++) sw[wid][(lane + 32) * 5 + h] = wB[h];
        }
        __syncwarp();

        // ---- phase 2: accumulate; per iteration = 2 edges (one per half)
        for (int i = 0; i < deg; i += 2) {
            int e = i + hb;
            bool v = e < deg;
            int ei = v ? e : 0;
            int s  = ss[wid][ei];
            float w0 = sw[wid][ei * 5 + 0];
            float w1 = sw[wid][ei * 5 + 1];
            float w2 = sw[wid][ei * 5 + 2];
            float w3 = sw[wid][ei * 5 + 3];
            float w4 = sw[wid][ei * 5 + 4];
            if (!v) { w0 = w1 = w2 = w3 = w4 = 0.f; }
            float4 x = *reinterpret_cast<const float4*>(xb + (size_t)s * 64 + db);
            acc[0].x += w0 * x.x; acc[0].y += w0 * x.y; acc[0].z += w0 * x.z; acc[0].w += w0 * x.w;
            acc[1].x += w1 * x.x; acc[1].y += w1 * x.y; acc[1].z += w1 * x.z; acc[1].w += w1 * x.w;
            acc[2].x += w2 * x.x; acc[2].y += w2 * x.y; acc[2].z += w2 * x.z; acc[2].w += w2 * x.w;
            acc[3].x += w3 * x.x; acc[3].y += w3 * x.y; acc[3].z += w3 * x.z; acc[3].w += w3 * x.w;
            acc[4].x += w4 * x.x; acc[4].y += w4 * x.y; acc[4].z += w4 * x.z; acc[4].w += w4 * x.w;
        }
    }

#pragma unroll
    for (int h = 0; h < 5; h++) {
        acc[h].x += __shfl_xor_sync(0xffffffffu, acc[h].x, 16);
        acc[h].y += __shfl_xor_sync(0xffffffffu, acc[h].y, 16);
        acc[h].z += __shfl_xor_sync(0xffffffffu, acc[h].z, 16);
        acc[h].w += __shfl_xor_sync(0xffffffffu, acc[h].w, 16);
    }

    if (lane < 16) {
        size_t base = (size_t)n * 640 + (size_t)hg * 64 + db;
#pragma unroll
        for (int h = 0; h < 5; h++) {
            float ax = acc[h].x, ay = acc[h].y, az = acc[h].z, aw = acc[h].w;
            __nv_bfloat162 h0 = __floats2bfloat162_rn(ax, ay);
            __nv_bfloat162 h1 = __floats2bfloat162_rn(az, aw);
            float2 f0 = __bfloat1622float2(h0);
            float2 f1 = __bfloat1622float2(h1);
            __nv_bfloat162 l0 = __floats2bfloat162_rn(ax - f0.x, ay - f0.y);
            __nv_bfloat162 l1 = __floats2bfloat162_rn(az - f1.x, aw - f1.y);
            uint2 uh, ul;
            uh.x = *reinterpret_cast<unsigned*>(&h0);
            uh.y = *reinterpret_cast<unsigned*>(&h1);
            ul.x = *reinterpret_cast<unsigned*>(&l0);
            ul.y = *reinterpret_cast<unsigned*>(&l1);
            *reinterpret_cast<uint2*>(agg_hi + base + h * 64) = uh;
            *reinterpret_cast<uint2*>(agg_lo + base + h * 64) = ul;
        }
    }
}

// ---------------------------------------------------------------------------
// headgemm via mma.sync (HMMA): 64-row tile, 256 threads (4 M x 2 N warps),
// split-bf16 (hi*hi + hi*lo + lo*hi), fp32 register accum, cp.async double
// buffering, per-head bias+relu+head-sum, fused elr2 epilogue.
// ---------------------------------------------------------------------------
__global__ void __launch_bounds__(256) headgemm_mma(
    const __nv_bfloat16* __restrict__ agg_hi, const __nv_bfloat16* __restrict__ agg_lo,
    const __nv_bfloat16* __restrict__ w1t_hi, const __nv_bfloat16* __restrict__ w1t_lo,
    const float* __restrict__ b1l, const float* __restrict__ b1r,
    const float* __restrict__ wl2, const float* __restrict__ wr2,
    float* __restrict__ hsum, float* __restrict__ el2, float* __restrict__ er2,
    int NPL) {
    extern __shared__ char sm[];
    const int tid  = threadIdx.x;
    const int w    = tid >> 5;
    const int lane = tid & 31;
    const int wm   = w & 3;
    const int wn   = w >> 2;
    const int gid  = lane >> 2, tid4 = lane & 3;
    const int bm = blockIdx.x * 64;
    const int br = (bm >= NPL);
    const float* b1 = br ? b1r : b1l;
    const uint32_t smb = smem_to_u32(sm);
    float* b1s  = reinterpret_cast<float*>(sm + 65536);
    float* wl2s = reinterpret_cast<float*>(sm + 68096);
    float* wr2s = reinterpret_cast<float*>(sm + 68352);
    float* hs   = reinterpret_cast<float*>(sm);

    for (int i = tid; i < 640; i += 256) b1s[i] = b1[i];
    if (tid < 64) { wl2s[tid] = wl2[br * 64 + tid]; wr2s[tid] = wr2[br * 64 + tid]; }

    auto loads = [&](int h) {
        int st = h & 1;
        const char* Ah = (const char*)agg_hi + ((size_t)bm * 640 + h * 64) * 2;
        const char* Al = (const char*)agg_lo + ((size_t)bm * 640 + h * 64) * 2;
        char* Ahd = sm + st * 16384;
        char* Ald = Ahd + 8192;
#pragma unroll
        for (int i = 0; i < 2; i++) {
            int f = tid + i * 256;
            int row = f >> 3, c = f & 7;
            int so = SW128(row * 128 + c * 16);
            size_t go = (size_t)row * 1280 + c * 16;
            cp_async16(Ahd + so, Ah + go);
            cp_async16(Ald + so, Al + go);
        }
        const char* Wh = (const char*)w1t_hi + ((size_t)br * 40960 + h * 4096) * 2;
        const char* Wl = (const char*)w1t_lo + ((size_t)br * 40960 + h * 4096) * 2;
        char* Whd = sm + 32768 + st * 16384;
        char* Wld = Whd + 8192;
#pragma unroll
        for (int i = 0; i < 2; i++) {
            int f = tid + i * 256;
            int row = f >> 3, c = f & 7;
            int so = SW128(row * 128 + c * 16);
            size_t go = (size_t)row * 128 + c * 16;
            cp_async16(Whd + so, Wh + go);
            cp_async16(Wld + so, Wl + go);
        }
        CP_COMMIT();
    };

    loads(0);
    loads(1);

    float out[4][4];
#pragma unroll
    for (int nf = 0; nf < 4; nf++)
#pragma unroll
        for (int j = 0; j < 4; j++) out[nf][j] = 0.f;

    const int arow  = wm * 16 + (lane & 15);
    const int acolb = (lane >> 4) * 16;
    const int brow  = lane & 7;
    const int bcolb = ((lane >> 3) & 1) * 16;

    for (int h = 0; h < 10; h++) {
        if (h < 9) { CP_WAIT1(); } else { CP_WAIT0(); }
        __syncthreads();

        const int st = h & 1;
        const uint32_t Ah = smb + st * 16384;
        const uint32_t Al = Ah + 8192;
        const uint32_t Wh = smb + 32768 + st * 16384;
        const uint32_t Wl = Wh + 8192;

        float d[4][4];
#pragma unroll
        for (int nf = 0; nf < 4; nf++)
#pragma unroll
            for (int j = 0; j < 4; j++) d[nf][j] = 0.f;

#pragma unroll
        for (int kc = 0; kc < 4; kc++) {
            uint32_t aoff = SW128(arow * 128 + kc * 32 + acolb);
            uint32_t ah0, ah1, ah2, ah3, al0, al1, al2, al3;
            LDSM_X4(ah0, ah1, ah2, ah3, Ah + aoff);
            LDSM_X4(al0, al1, al2, al3, Al + aoff);
#pragma unroll
            for (int nf = 0; nf < 4; nf++) {
                uint32_t boff = SW128((wn * 32 + nf * 8 + brow) * 128 + kc * 32 + bcolb);
                uint32_t bh0, bh1, bl0, bl1;
                LDSM_X2(bh0, bh1, Wh + boff);
                LDSM_X2(bl0, bl1, Wl + boff);
                MMA_BF16(d[nf], ah0, ah1, ah2, ah3, bh0, bh1);
                MMA_BF16(d[nf], ah0, ah1, ah2, ah3, bl0, bl1);
                MMA_BF16(d[nf], al0, al1, al2, al3, bh0, bh1);
            }
        }
        __syncthreads();
        if (h + 2 < 10) loads(h + 2);

#pragma unroll
        for (int nf = 0; nf < 4; nf++) {
            int col = wn * 32 + nf * 8 + tid4 * 2;
            float2 bb = *reinterpret_cast<const float2*>(&b1s[h * 64 + col]);
            out[nf][0] += fmaxf(d[nf][0] + bb.x, 0.f);
            out[nf][1] += fmaxf(d[nf][1] + bb.y, 0.f);
            out[nf][2] += fmaxf(d[nf][2] + bb.x, 0.f);
            out[nf][3] += fmaxf(d[nf][3] + bb.y, 0.f);
        }
    }

    __syncthreads();
    const int row0 = wm * 16 + gid;
#pragma unroll
    for (int nf = 0; nf < 4; nf++) {
        int colb = wn * 32 + nf * 8 + tid4 * 2;
        *reinterpret_cast<float2*>(&hs[row0 * 66 + colb])       = make_float2(out[nf][0], out[nf][1]);
        *reinterpret_cast<float2*>(&hs[(row0 + 8) * 66 + colb]) = make_float2(out[nf][2], out[nf][3]);
    }
    __syncthreads();
    if (tid < 64) {
        int row = tid;
        float pl = 0.f, pr = 0.f;
        float4* hp = reinterpret_cast<float4*>(hsum + (size_t)(bm + row) * 64);
#pragma unroll
        for (int c4 = 0; c4 < 16; c4++) {
            float v0 = hs[row * 66 + c4 * 4 + 0];
            float v1 = hs[row * 66 + c4 * 4 + 1];
            float v2 = hs[row * 66 + c4 * 4 + 2];
            float v3 = hs[row * 66 + c4 * 4 + 3];
            pl += v0 * wl2s[c4 * 4] + v1 * wl2s[c4 * 4 + 1] + v2 * wl2s[c4 * 4 + 2] + v3 * wl2s[c4 * 4 + 3];
            pr += v0 * wr2s[c4 * 4] + v1 * wr2s[c4 * 4 + 1] + v2 * wr2s[c4 * 4 + 2] + v3 * wr2s[c4 * 4 + 3];
            hp[c4] = make_float4(v0, v1, v2, v3);
        }
        el2[bm + row] = pl;
        er2[bm + row] = pr;
    }
}

// ---------------------------------------------------------------------------
// Layer-2 gather, smem-staged (R16-proven).
// ---------------------------------------------------------------------------
__global__ void gather2_kernel(const float* __restrict__ hsum, const int* __restrict__ cnt,
                               const int* __restrict__ csrsrc, const float* __restrict__ el,
                               const float* __restrict__ er, float* __restrict__ agg2, int NT) {
    __shared__ float sw[8][64];
    __shared__ int   ss[8][64];
    int wid  = threadIdx.x >> 5;
    int n    = (blockIdx.x * blockDim.x + threadIdx.x) >> 5;
    int lane = threadIdx.x & 31;
    if (n >= NT) return;
    int deg = min(cnt[n], MAXDEG);
    float2 acc = make_float2(0.f, 0.f);
    if (deg > 0) {
        const float ern = er[n];
        const int* srcp = csrsrc + n * MAXDEG;
        bool vA = lane < deg, vB = lane + 32 < deg;
        int sA = srcp[vA ? lane : 0];
        int sB = vB ? srcp[lane + 32] : 0;
        float wA = vA ? __expf(fminf(lrelu02(el[sA] + ern), 60.f)) : 0.f;
        float wB = vB ? __expf(fminf(lrelu02(el[sB] + ern), 60.f)) : 0.f;
        float den = wA + wB;
#pragma unroll
        for (int o = 16; o; o >>= 1) den += __shfl_xor_sync(0xffffffffu, den, o);
        float inv = 1.f / den;
        sw[wid][lane]      = wA * inv;
        sw[wid][lane + 32] = wB * inv;
        ss[wid][lane]      = sA;
        ss[wid][lane + 32] = sB;
        __syncwarp();
#pragma unroll 4
        for (int i = 0; i < deg; i++) {
            int   s = ss[wid][i];
            float a = sw[wid][i];
            float2 v = *reinterpret_cast<const float2*>(hsum + (size_t)s * 64 + lane * 2);
            acc.x += a * v.x;
            acc.y += a * v.y;
        }
    }
    *reinterpret_cast<float2*>(agg2 + (size_t)n * 64 + lane * 2) = acc;
}

// ---------------------------------------------------------------------------
// Fused layer-2 GEMM + bias + relu + graph-max readout (combined rows).
// ---------------------------------------------------------------------------
__global__ void gemm2ro_kernel(const float* __restrict__ X,
                               const float* __restrict__ W2l, const float* __restrict__ b2l,
                               const float* __restrict__ W2r, const float* __restrict__ b2r,
                               const int* __restrict__ gid_l, const int* __restrict__ gid_r,
                               float* __restrict__ read, int NL, int NPL, int NR) {
    __shared__ float XsT[64][68];
    __shared__ float Ws[64][64];
    const int bm  = blockIdx.y * 64;
    const int bn  = blockIdx.x * 64;
    const int br  = (bm >= NPL);
    const float* W  = br ? W2r : W2l;
    const float* b2 = br ? b2r : b2l;
    const int tid = threadIdx.x;

#pragma unroll
    for (int i = 0; i < 16; i++) {
        int e = tid + i * 256;
        int r = e >> 6, k = e & 63;
        XsT[k][r] = X[(size_t)(bm + r) * 64 + k];
    }
#pragma unroll
    for (int i = 0; i < 16; i++) {
        int e = tid + i * 256;
        int k = e >> 6, c = e & 63;
        Ws[k][c] = W[(size_t)k * 128 + bn + c];
    }
    __syncthreads();

    const int tx = tid & 15, ty = tid >> 4;
    const int r0 = ty * 4, c0 = tx * 4;
    float acc[4][4] = {};
#pragma unroll
    for (int k = 0; k < 64; k++) {
        float4 a = *reinterpret_cast<const float4*>(&XsT[k][r0]);
        float4 b = *reinterpret_cast<const float4*>(&Ws[k][c0]);
        acc[0][0] += a.x * b.x; acc[0][1] += a.x * b.y; acc[0][2] += a.x * b.z; acc[0][3] += a.x * b.w;
        acc[1][0] += a.y * b.x; acc[1][1] += a.y * b.y; acc[1][2] += a.y * b.z; acc[1][3] += a.y * b.w;
        acc[2][0] += a.z * b.x; acc[2][1] += a.z * b.y; acc[2][2] += a.z * b.z; acc[2][3] += a.z * b.w;
        acc[3][0] += a.w * b.x; acc[3][1] += a.w * b.y; acc[3][2] += a.w * b.z; acc[3][3] += a.w * b.w;
    }

    float4 bb = *reinterpret_cast<const float4*>(&b2[bn + c0]);
#pragma unroll
    for (int i = 0; i < 4; i++) {
        int r = bm + r0 + i;
        bool vlig = (r < NL);
        bool vrec = (r >= NPL) && (r < NPL + NR);
        if (vlig || vrec) {
            int g   = vlig ? gid_l[r] : gid_r[r - NPL];
            int off = vlig ? 0 : 128;
            int* rp = reinterpret_cast<int*>(read) + (size_t)g * 256 + off + bn + c0;
            atomicMax(rp + 0, __float_as_int(fmaxf(acc[i][0] + bb.x, 0.f)));
            atomicMax(rp + 1, __float_as_int(fmaxf(acc[i][1] + bb.y, 0.f)));
            atomicMax(rp + 2, __float_as_int(fmaxf(acc[i][2] + bb.z, 0.f)));
            atomicMax(rp + 3, __float_as_int(fmaxf(acc[i][3] + bb.w, 0.f)));
        }
    }
}

// ---------------------------------------------------------------------------
// Final MLP head: [32,256] -> relu(@W1+b1) -> relu(@W2+b2) -> [32]
// ---------------------------------------------------------------------------
__global__ void mlp_kernel(const float* __restrict__ read, const float* __restrict__ W1,
                           const float* __restrict__ bb1, const float* __restrict__ W2,
                           const float* __restrict__ bb2, float* __restrict__ out) {
    __shared__ float sin[256];
    __shared__ float red[128];
    int t = threadIdx.x;
    for (int b = 0; b < 32; b++) {
        sin[t]       = read[b * 256 + t];
        sin[t + 128] = read[b * 256 + 128 + t];
        __syncthreads();
        float acc = bb1[t];
#pragma unroll 4
        for (int k = 0; k < 256; k++) acc += sin[k] * W1[(size_t)k * 128 + t];
        acc = fmaxf(acc, 0.f);
        red[t] = acc * W2[t];
        __syncthreads();
        for (int o = 64; o; o >>= 1) {
            if (t < o) red[t] += red[t + o];
            __syncthreads();
        }
        if (t == 0) out[b] = fmaxf(red[0] + bb2[0], 0.f);
        __syncthreads();
    }
}

// ---------------------------------------------------------------------------
// Host-side orchestration
// ---------------------------------------------------------------------------
static inline int div_up(int a, int b) { return (a + b - 1) / b; }

extern "C" void kernel_launch(void* const* d_in, const int* in_sizes, int n_in,
                              void* d_out, int out_size) {
    (void)n_in; (void)out_size;
    const float* x_lig   = (const float*)d_in[0];
    const int*   src_lig = (const int*)  d_in[1];
    const int*   dst_lig = (const int*)  d_in[2];
    const int*   gid_lig = (const int*)  d_in[3];
    const float* x_rec   = (const float*)d_in[4];
    const int*   src_rec = (const int*)  d_in[5];
    const int*   dst_rec = (const int*)  d_in[6];
    const int*   gid_rec = (const int*)  d_in[7];
    const float* W1l  = (const float*)d_in[8];
    const float* al1l = (const float*)d_in[9];
    const float* ar1l = (const float*)d_in[10];
    const float* b1l  = (const float*)d_in[11];
    const float* W2l  = (const float*)d_in[12];
    const float* al2l = (const float*)d_in[13];
    const float* ar2l = (const float*)d_in[14];
    const float* b2l  = (const float*)d_in[15];
    const float* W1r  = (const float*)d_in[16];
    const float* al1r = (const float*)d_in[17];
    const float* ar1r = (const float*)d_in[18];
    const float* b1r  = (const float*)d_in[19];
    const float* W2r  = (const float*)d_in[20];
    const float* al2r = (const float*)d_in[21];
    const float* ar2r = (const float*)d_in[22];
    const float* b2r  = (const float*)d_in[23];
    const float* W_lin1 = (const float*)d_in[24];
    const float* b_lin1 = (const float*)d_in[25];
    const float* W_lin2 = (const float*)d_in[26];
    const float* b_lin2 = (const float*)d_in[27];

    const int NL = in_sizes[0] / 64;
    const int EL = in_sizes[1];
    const int NR = in_sizes[4] / 64;
    const int ER = in_sizes[5];
    const int NPL    = (NL + 127) & ~127;       // rec offset, 128-aligned
    const int NT     = NPL + NR;
    const int NT_pad = (NT + 127) & ~127;
    const int ET     = EL + ER;
    const int SB     = div_up(ET, 256);

    __nv_bfloat16 *agg_hi, *agg_lo, *w1t_hi, *w1t_lo;
    float *hsum, *agg2, *el, *er, *el2, *er2, *read;
    float *wl1, *wr1, *wl2, *wr2;
    int *cnt, *csrsrc;
    cudaGetSymbolAddress((void**)&agg_hi, g_agg_hi);
    cudaGetSymbolAddress((void**)&agg_lo, g_agg_lo);
    cudaGetSymbolAddress((void**)&w1t_hi, g_w1t_hi);
    cudaGetSymbolAddress((void**)&w1t_lo, g_w1t_lo);
    cudaGetSymbolAddress((void**)&hsum,   g_hsum);
    cudaGetSymbolAddress((void**)&agg2,   g_agg2);
    cudaGetSymbolAddress((void**)&el,     g_el);
    cudaGetSymbolAddress((void**)&er,     g_er);
    cudaGetSymbolAddress((void**)&el2,    g_el2);
    cudaGetSymbolAddress((void**)&er2,    g_er2);
    cudaGetSymbolAddress((void**)&cnt,    g_cnt);
    cudaGetSymbolAddress((void**)&csrsrc, g_csrsrc);
    cudaGetSymbolAddress((void**)&wl1,    g_wl1);
    cudaGetSymbolAddress((void**)&wr1,    g_wr1);
    cudaGetSymbolAddress((void**)&wl2,    g_wl2);
    cudaGetSymbolAddress((void**)&wr2,    g_wr2);
    cudaGetSymbolAddress((void**)&read,   g_read);

    cudaFuncSetAttribute(headgemm_mma,
                         cudaFuncAttributeMaxDynamicSharedMemorySize, 68608);

    // ---- CSR zero + FRONT (scatter + weight precompute + read zeroing) ----
    cudaMemsetAsync(cnt, 0, sizeof(int) * (size_t)NT_pad, 0);
    front_kernel<<<SB + 440, 256>>>(
        src_lig, dst_lig, src_rec, dst_rec, cnt, csrsrc,
        W1l, al1l, ar1l, W2l, al2l, ar2l,
        W1r, al1r, ar1r, W2r, al2r, ar2r,
        wl1, wr1, wl2, wr2, w1t_hi, w1t_lo, read,
        EL, ET, NPL, SB);
    elr1_kernel<<<div_up(NT * 32, 256), 256>>>(x_lig, x_rec, wl1, wr1, el, er, NL, NPL, NT);

    // ---- layer 1: smem-staged gather (bf16 split), HMMA GEMM ----
    gather1_kernel<<<div_up(NT_pad * 64, 256), 256>>>(x_lig, x_rec, cnt, csrsrc,
                                                      el, er, agg_hi, agg_lo,
                                                      NPL, NT_pad * 2);
    headgemm_mma<<<NT_pad / 64, 256, 68608>>>(agg_hi, agg_lo, w1t_hi, w1t_lo,
                                              b1l, b1r, wl2, wr2,
                                              hsum, el2, er2, NPL);

    // ---- layer 2: smem-staged gather, fused GEMM + readout ----
    gather2_kernel<<<div_up(NT * 32, 256), 256>>>(hsum, cnt, csrsrc, el2, er2, agg2, NT);
    gemm2ro_kernel<<<dim3(2, NT_pad / 64), 256>>>(agg2, W2l, b2l, W2r, b2r,
                                                  gid_lig, gid_rec, read, NL, NPL, NR);

    mlp_kernel<<<1, 128>>>(read, W_lin1, b_lin1, W_lin2, b_lin2, (float*)d_out);
}